// round 1
// baseline (speedup 1.0000x reference)
#include <cuda_runtime.h>
#include <cuda_bf16.h>

// ---------------- problem constants ----------------
#define BATCH 2
#define S_LEN 512
#define HID 2048
#define NHEAD 32
#define HDIM 64
#define SU_LEN 1024          // upsampled seq
#define T_LEN 1536           // S + SU
#define INTER 5632
#define EPS_RMS 1e-6f

// strides
#define S_H   (S_LEN * HID)          // 1048576
#define SU_H  (SU_LEN * HID)         // 2097152
#define T_H   (T_LEN * HID)          // 3145728
#define SU_T  ((long long)SU_LEN * T_LEN)        // 1572864
#define NH_SU_T ((long long)NHEAD * SU_LEN * T_LEN) // 50331648
#define SU_I  ((long long)SU_LEN * INTER)        // 5767168

// ---------------- scratch (device globals; no allocation) ----------------
__device__ float g_up   [BATCH * SU_LEN * HID];
__device__ float g_x1   [BATCH * SU_LEN * HID];
__device__ float g_q    [BATCH * SU_LEN * HID];
__device__ float g_k    [BATCH * T_LEN * HID];
__device__ float g_v    [BATCH * T_LEN * HID];
__device__ float g_sc   [(long long)BATCH * NHEAD * SU_LEN * T_LEN]; // 402 MB
__device__ float g_o    [BATCH * SU_LEN * HID];
__device__ float g_x2   [BATCH * SU_LEN * HID];
__device__ float g_x3   [BATCH * SU_LEN * HID];
__device__ float g_gate [BATCH * SU_LEN * INTER];
__device__ float g_ubuf [BATCH * SU_LEN * INTER];

// ---------------- generic tiled GEMM ----------------
// C[m,n] = alpha * sum_k A[m,k] * (TRANS_B ? B[n,k] : B[k,n])  (+ bias[m]) (+ resid[m,n])
// Batched over grid.z decomposed as z1 = z/batch2, z2 = z%batch2;
// each operand offset = z1*s1 + z2*s2.
#define BM 128
#define BN 128
#define BKK 16
#define TM 8
#define TN 8

template<bool TRANS_B>
__global__ __launch_bounds__(256) void gemm_kernel(
    const float* __restrict__ A, int lda, long long sA1, long long sA2,
    const float* __restrict__ Bm, int ldb, long long sB1, long long sB2,
    float* __restrict__ C, int ldc, long long sC1, long long sC2,
    const float* __restrict__ bias,
    const float* __restrict__ resid, int ldr, long long sR1, long long sR2,
    int M, int N, int K, float alpha, int batch2)
{
    __shared__ float As[BKK][BM + 4];
    __shared__ float Bs[BKK][BN + 4];

    int z = blockIdx.z;
    int z1 = z / batch2, z2 = z - z1 * batch2;
    A  += z1 * sA1 + z2 * sA2;
    Bm += z1 * sB1 + z2 * sB2;
    C  += z1 * sC1 + z2 * sC2;
    if (resid) resid += z1 * sR1 + z2 * sR2;

    const int m0 = blockIdx.y * BM;
    const int n0 = blockIdx.x * BN;
    const int tid = threadIdx.x;

    // A-tile loader mapping (also used for transposed B)
    const int arow = tid >> 2;          // 0..63
    const int acol = (tid & 3) << 2;    // 0,4,8,12
    // NN B-tile loader mapping
    const int bkrow = tid >> 5;         // 0..7
    const int bncol = (tid & 31) << 2;  // 0..124

    const int ty = tid >> 4;            // 0..15 (m)
    const int tx = tid & 15;            // 0..15 (n)

    float acc[TM][TN];
    #pragma unroll
    for (int i = 0; i < TM; i++)
        #pragma unroll
        for (int j = 0; j < TN; j++) acc[i][j] = 0.f;

    for (int k0 = 0; k0 < K; k0 += BKK) {
        // ---- load A tile (transposed into smem) ----
        #pragma unroll
        for (int i = 0; i < 2; i++) {
            int r = arow + 64 * i;
            float4 v = *(const float4*)(A + (long long)(m0 + r) * lda + (k0 + acol));
            As[acol + 0][r] = v.x; As[acol + 1][r] = v.y;
            As[acol + 2][r] = v.z; As[acol + 3][r] = v.w;
        }
        // ---- load B tile ----
        if (TRANS_B) {
            #pragma unroll
            for (int i = 0; i < 2; i++) {
                int r = arow + 64 * i;   // n index within tile
                float4 v = make_float4(0.f, 0.f, 0.f, 0.f);
                if (n0 + r < N)
                    v = *(const float4*)(Bm + (long long)(n0 + r) * ldb + (k0 + acol));
                Bs[acol + 0][r] = v.x; Bs[acol + 1][r] = v.y;
                Bs[acol + 2][r] = v.z; Bs[acol + 3][r] = v.w;
            }
        } else {
            #pragma unroll
            for (int i = 0; i < 2; i++) {
                int kr = bkrow + 8 * i;
                float4 v = make_float4(0.f, 0.f, 0.f, 0.f);
                if (n0 + bncol < N)
                    v = *(const float4*)(Bm + (long long)(k0 + kr) * ldb + (n0 + bncol));
                *(float4*)&Bs[kr][bncol] = v;
            }
        }
        __syncthreads();

        // ---- compute ----
        #pragma unroll
        for (int kk = 0; kk < BKK; kk++) {
            float a[TM], b[TN];
            #pragma unroll
            for (int i = 0; i < TM; i++) a[i] = As[kk][ty * TM + i];
            #pragma unroll
            for (int j = 0; j < TN; j++) b[j] = Bs[kk][tx * TN + j];
            #pragma unroll
            for (int i = 0; i < TM; i++)
                #pragma unroll
                for (int j = 0; j < TN; j++)
                    acc[i][j] = fmaf(a[i], b[j], acc[i][j]);
        }
        __syncthreads();
    }

    // ---- epilogue ----
    #pragma unroll
    for (int i = 0; i < TM; i++) {
        int m = m0 + ty * TM + i;
        float bv = bias ? bias[m] : 0.f;
        #pragma unroll
        for (int j = 0; j < TN; j++) {
            int n = n0 + tx * TN + j;
            if (n < N) {
                float val = acc[i][j] * alpha + bv;
                if (resid) val += resid[(long long)m * ldr + n];
                C[(long long)m * ldc + n] = val;
            }
        }
    }
}

// ---------------- rmsnorm: one block per row of length HID ----------------
__global__ __launch_bounds__(256) void rmsnorm_kernel(
    const float* __restrict__ x, const float* __restrict__ w, float* __restrict__ y)
{
    __shared__ float red[256];
    long long row = blockIdx.x;
    const float* xr = x + row * HID;
    float* yr = y + row * HID;
    int tid = threadIdx.x;

    float4 v0 = *(const float4*)(xr + tid * 4);
    float4 v1 = *(const float4*)(xr + 1024 + tid * 4);
    float s = v0.x * v0.x + v0.y * v0.y + v0.z * v0.z + v0.w * v0.w
            + v1.x * v1.x + v1.y * v1.y + v1.z * v1.z + v1.w * v1.w;
    red[tid] = s;
    __syncthreads();
    for (int st = 128; st > 0; st >>= 1) {
        if (tid < st) red[tid] += red[tid + st];
        __syncthreads();
    }
    float inv = rsqrtf(red[0] * (1.f / HID) + EPS_RMS);

    float4 w0 = *(const float4*)(w + tid * 4);
    float4 w1 = *(const float4*)(w + 1024 + tid * 4);
    float4 o0, o1;
    o0.x = v0.x * inv * w0.x; o0.y = v0.y * inv * w0.y;
    o0.z = v0.z * inv * w0.z; o0.w = v0.w * inv * w0.w;
    o1.x = v1.x * inv * w1.x; o1.y = v1.y * inv * w1.y;
    o1.z = v1.z * inv * w1.z; o1.w = v1.w * inv * w1.w;
    *(float4*)(yr + tid * 4) = o0;
    *(float4*)(yr + 1024 + tid * 4) = o1;
}

// ---------------- softmax over rows of length T_LEN (in place) ----------------
__global__ __launch_bounds__(256) void softmax_kernel(float* __restrict__ s)
{
    __shared__ float red[256];
    long long row = blockIdx.x;
    float* p = s + row * (long long)T_LEN;
    int tid = threadIdx.x;

    float vals[6];
    float m = -1e30f;
    #pragma unroll
    for (int j = 0; j < 6; j++) {
        vals[j] = p[tid + j * 256];
        m = fmaxf(m, vals[j]);
    }
    red[tid] = m;
    __syncthreads();
    for (int st = 128; st > 0; st >>= 1) {
        if (tid < st) red[tid] = fmaxf(red[tid], red[tid + st]);
        __syncthreads();
    }
    m = red[0];
    __syncthreads();

    float sum = 0.f;
    #pragma unroll
    for (int j = 0; j < 6; j++) {
        vals[j] = __expf(vals[j] - m);
        sum += vals[j];
    }
    red[tid] = sum;
    __syncthreads();
    for (int st = 128; st > 0; st >>= 1) {
        if (tid < st) red[tid] += red[tid + st];
        __syncthreads();
    }
    float inv = 1.f / red[0];
    #pragma unroll
    for (int j = 0; j < 6; j++)
        p[tid + j * 256] = vals[j] * inv;
}

// ---------------- silu(gate) * up, vectorized ----------------
__global__ __launch_bounds__(256) void silu_mul_kernel(
    const float* __restrict__ g, float* __restrict__ u)
{
    long long i = (long long)blockIdx.x * 256 + threadIdx.x;
    float4 gv = ((const float4*)g)[i];
    float4 uv = ((float4*)u)[i];
    float4 o;
    o.x = uv.x * gv.x / (1.f + __expf(-gv.x));
    o.y = uv.y * gv.y / (1.f + __expf(-gv.y));
    o.z = uv.z * gv.z / (1.f + __expf(-gv.z));
    o.w = uv.w * gv.w / (1.f + __expf(-gv.w));
    ((float4*)u)[i] = o;
}

// ---------------- launch ----------------
static float* sym(const void* s) {
    void* p = nullptr;
    cudaGetSymbolAddress(&p, s);
    return (float*)p;
}

extern "C" void kernel_launch(void* const* d_in, const int* in_sizes, int n_in,
                              void* d_out, int out_size)
{
    const float* h_in = (const float*)d_in[0];
    const float* Wup  = (const float*)d_in[1];
    const float* bup  = (const float*)d_in[2];
    const float* anw  = (const float*)d_in[3];
    const float* Wq   = (const float*)d_in[4];
    const float* Wk   = (const float*)d_in[5];
    const float* Wv   = (const float*)d_in[6];
    const float* Wo   = (const float*)d_in[7];
    const float* mnw  = (const float*)d_in[8];
    const float* Wg   = (const float*)d_in[9];
    const float* Wu   = (const float*)d_in[10];
    const float* Wd   = (const float*)d_in[11];
    float* out = (float*)d_out;

    float* up_   = sym(g_up);
    float* x1_   = sym(g_x1);
    float* q_    = sym(g_q);
    float* k_    = sym(g_k);
    float* v_    = sym(g_v);
    float* sc_   = sym(g_sc);
    float* o_    = sym(g_o);
    float* x2_   = sym(g_x2);
    float* x3_   = sym(g_x3);
    float* gate_ = sym(g_gate);
    float* ubuf_ = sym(g_ubuf);

    dim3 blk(256);

    // 1) up = W_up @ h  (+ b_up)   [NN]  M=SU, N=H, K=S, batched over B
    gemm_kernel<false><<<dim3(HID/128, SU_LEN/128, BATCH), blk>>>(
        Wup, S_LEN, 0, 0,
        h_in, HID, S_H, 0,
        up_, HID, SU_H, 0,
        bup, nullptr, 0, 0, 0,
        SU_LEN, HID, S_LEN, 1.f, 1);

    // 2) x1 = rmsnorm(up, attn_norm_w)
    rmsnorm_kernel<<<BATCH * SU_LEN, blk>>>(up_, anw, x1_);

    // 3) q = x1 @ Wq^T   [NT]
    gemm_kernel<true><<<dim3(HID/128, SU_LEN/128, BATCH), blk>>>(
        x1_, HID, SU_H, 0,
        Wq, HID, 0, 0,
        q_, HID, SU_H, 0,
        nullptr, nullptr, 0, 0, 0,
        SU_LEN, HID, HID, 1.f, 1);

    // 4) k = [h; up] @ Wk^T   (two NT GEMMs into g_k)
    gemm_kernel<true><<<dim3(HID/128, S_LEN/128, BATCH), blk>>>(
        h_in, HID, S_H, 0,
        Wk, HID, 0, 0,
        k_, HID, T_H, 0,
        nullptr, nullptr, 0, 0, 0,
        S_LEN, HID, HID, 1.f, 1);
    gemm_kernel<true><<<dim3(HID/128, SU_LEN/128, BATCH), blk>>>(
        up_, HID, SU_H, 0,
        Wk, HID, 0, 0,
        k_ + (long long)S_LEN * HID, HID, T_H, 0,
        nullptr, nullptr, 0, 0, 0,
        SU_LEN, HID, HID, 1.f, 1);

    // 5) v likewise
    gemm_kernel<true><<<dim3(HID/128, S_LEN/128, BATCH), blk>>>(
        h_in, HID, S_H, 0,
        Wv, HID, 0, 0,
        v_, HID, T_H, 0,
        nullptr, nullptr, 0, 0, 0,
        S_LEN, HID, HID, 1.f, 1);
    gemm_kernel<true><<<dim3(HID/128, SU_LEN/128, BATCH), blk>>>(
        up_, HID, SU_H, 0,
        Wv, HID, 0, 0,
        v_ + (long long)S_LEN * HID, HID, T_H, 0,
        nullptr, nullptr, 0, 0, 0,
        SU_LEN, HID, HID, 1.f, 1);

    // 6) scores[b,h] = (q_slice @ k_slice^T) / 8   [NT], batch = B*NH
    gemm_kernel<true><<<dim3(T_LEN/128, SU_LEN/128, BATCH * NHEAD), blk>>>(
        q_, HID, SU_H, HDIM,
        k_, HID, T_H, HDIM,
        sc_, T_LEN, NH_SU_T, SU_T,
        nullptr, nullptr, 0, 0, 0,
        SU_LEN, T_LEN, HDIM, 0.125f, NHEAD);

    // 7) softmax over last axis (T_LEN)
    softmax_kernel<<<BATCH * NHEAD * SU_LEN, blk>>>(sc_);

    // 8) o[b,h] = attn @ v_slice   [NN], batch = B*NH, N = 64
    gemm_kernel<false><<<dim3(1, SU_LEN/128, BATCH * NHEAD), blk>>>(
        sc_, T_LEN, NH_SU_T, SU_T,
        v_, HID, T_H, HDIM,
        o_, HID, SU_H, HDIM,
        nullptr, nullptr, 0, 0, 0,
        SU_LEN, HDIM, T_LEN, 1.f, NHEAD);

    // 9) x2 = o @ Wo^T + x1   [NT + residual]
    gemm_kernel<true><<<dim3(HID/128, SU_LEN/128, BATCH), blk>>>(
        o_, HID, SU_H, 0,
        Wo, HID, 0, 0,
        x2_, HID, SU_H, 0,
        nullptr, x1_, HID, SU_H, 0,
        SU_LEN, HID, HID, 1.f, 1);

    // 10) x3 = rmsnorm(x2, mlp_norm_w)
    rmsnorm_kernel<<<BATCH * SU_LEN, blk>>>(x2_, mnw, x3_);

    // 11) gate = x3 @ Wg^T   [NT]
    gemm_kernel<true><<<dim3(INTER/128, SU_LEN/128, BATCH), blk>>>(
        x3_, HID, SU_H, 0,
        Wg, HID, 0, 0,
        gate_, INTER, SU_I, 0,
        nullptr, nullptr, 0, 0, 0,
        SU_LEN, INTER, HID, 1.f, 1);

    // 12) ubuf = x3 @ Wu^T   [NT]
    gemm_kernel<true><<<dim3(INTER/128, SU_LEN/128, BATCH), blk>>>(
        x3_, HID, SU_H, 0,
        Wu, HID, 0, 0,
        ubuf_, INTER, SU_I, 0,
        nullptr, nullptr, 0, 0, 0,
        SU_LEN, INTER, HID, 1.f, 1);

    // 13) ubuf = silu(gate) * ubuf
    {
        long long n4 = (long long)BATCH * SU_LEN * INTER / 4;   // 2883584
        silu_mul_kernel<<<(unsigned)(n4 / 256), blk>>>(gate_, ubuf_);
    }

    // 14) out = ubuf @ Wd^T + x3   [NT + residual]
    gemm_kernel<true><<<dim3(HID/128, SU_LEN/128, BATCH), blk>>>(
        ubuf_, INTER, SU_I, 0,
        Wd, INTER, 0, 0,
        out, HID, SU_H, 0,
        nullptr, x3_, HID, SU_H, 0,
        SU_LEN, HID, INTER, 1.f, 1);
}

// round 3
// speedup vs baseline: 2.0922x; 2.0922x over previous
#include <cuda_runtime.h>
#include <cuda_bf16.h>
#include <cstdint>

// ---------------- problem constants ----------------
#define BATCH 2
#define S_LEN 512
#define HID 2048
#define NHEAD 32
#define HDIM 64
#define SU_LEN 1024
#define T_LEN 1536
#define INTER 5632
#define EPS_RMS 1e-6f

#define S_H   (S_LEN * HID)
#define SU_H  (SU_LEN * HID)
#define T_H   (T_LEN * HID)
#define SU_T  ((long long)SU_LEN * T_LEN)
#define NH_SU_T ((long long)NHEAD * SU_LEN * T_LEN)
#define SU_I  ((long long)SU_LEN * INTER)

#define HB  (BATCH * S_LEN * HID)
#define XB  (BATCH * SU_LEN * HID)
#define KB  (BATCH * T_LEN * HID)
#define ATB ((long long)BATCH * NHEAD * SU_LEN * T_LEN)
#define UBB ((long long)BATCH * SU_LEN * INTER)
#define WUPN (SU_LEN * S_LEN)
#define W1N  (HID * HID)
#define W2N  (INTER * HID)

typedef __nv_bfloat16 bf16;

// ---------------- scratch (device globals; no runtime allocation) ----------------
__device__ float g_up  [XB];
__device__ float g_x1  [XB];
__device__ float g_x2  [XB];
__device__ float g_x3  [XB];
__device__ float g_v   [KB];
__device__ float g_sc  [ATB];
__device__ float g_gate[UBB];
__device__ float g_ubuf[UBB];

__device__ bf16 b_h_hi[HB],  b_h_lo[HB];
__device__ bf16 b_ht_hi[HB], b_ht_lo[HB];
__device__ bf16 b_wup_hi[WUPN], b_wup_lo[WUPN];
__device__ bf16 b_wq_hi[W1N], b_wq_lo[W1N];
__device__ bf16 b_wk_hi[W1N], b_wk_lo[W1N];
__device__ bf16 b_wv_hi[W1N], b_wv_lo[W1N];
__device__ bf16 b_wo_hi[W1N], b_wo_lo[W1N];
__device__ bf16 b_wg_hi[W2N], b_wg_lo[W2N];
__device__ bf16 b_wu_hi[W2N], b_wu_lo[W2N];
__device__ bf16 b_wd_hi[W2N], b_wd_lo[W2N];
__device__ bf16 b_up_hi[XB], b_up_lo[XB];
__device__ bf16 b_x1_hi[XB], b_x1_lo[XB];
__device__ bf16 b_x3_hi[XB], b_x3_lo[XB];
__device__ bf16 b_q_hi[XB],  b_q_lo[XB];
__device__ bf16 b_k_hi[KB],  b_k_lo[KB];
__device__ bf16 b_o_hi[XB],  b_o_lo[XB];
__device__ bf16 b_vt_hi[KB], b_vt_lo[KB];
__device__ bf16 b_at_hi[ATB], b_at_lo[ATB];
__device__ bf16 b_ub_hi[UBB], b_ub_lo[UBB];

// ---------------- PTX helpers ----------------
__device__ __forceinline__ uint32_t smem_u32(const void* p) {
    uint32_t a;
    asm("{ .reg .u64 t; cvta.to.shared.u64 t, %1; cvt.u32.u64 %0, t; }" : "=r"(a) : "l"(p));
    return a;
}
#define SWZ(off) ((off) ^ (((off) >> 3) & 0x70))

#define CP_ASYNC16(dst, src) \
    asm volatile("cp.async.cg.shared.global [%0], [%1], 16;" :: "r"(dst), "l"(src) : "memory")
#define CP_COMMIT() asm volatile("cp.async.commit_group;" ::: "memory")
__device__ __forceinline__ void cp_wait(int allow) {
    if (allow) asm volatile("cp.async.wait_group 1;" ::: "memory");
    else       asm volatile("cp.async.wait_group 0;" ::: "memory");
}

__device__ __forceinline__ void ldmx4(uint32_t* r, uint32_t addr) {
    asm volatile("ldmatrix.sync.aligned.m8n8.x4.shared.b16 {%0,%1,%2,%3}, [%4];"
        : "=r"(r[0]), "=r"(r[1]), "=r"(r[2]), "=r"(r[3]) : "r"(addr));
}

__device__ __forceinline__ void mma_bf16(float* d, const uint32_t* a, uint32_t b0, uint32_t b1) {
    asm volatile("mma.sync.aligned.m16n8k16.row.col.f32.bf16.bf16.f32 "
        "{%0,%1,%2,%3}, {%4,%5,%6,%7}, {%8,%9}, {%0,%1,%2,%3};"
        : "+f"(d[0]), "+f"(d[1]), "+f"(d[2]), "+f"(d[3])
        : "r"(a[0]), "r"(a[1]), "r"(a[2]), "r"(a[3]), "r"(b0), "r"(b1));
}

__device__ __forceinline__ void split_bf16(float v, bf16& hi, bf16& lo) {
    hi = __float2bfloat16(v);
    lo = __float2bfloat16(v - __bfloat162float(hi));
}

// ---------------- mma.sync GEMM ----------------
// C[m,n] = alpha * sum over 3 bf16-split passes of A[m,:]·B[n,:] (+bias[m]) (+resid)
// Tile: 128 x BN, K chunk 64. 3-stage cp.async pipeline, 8 warps (4 m x 2 n).
template<int BN>
__global__ __launch_bounds__(256, 2) void mma_gemm(
    const bf16* __restrict__ Ah, const bf16* __restrict__ Al,
    int lda, long long sA1, long long sA2,
    const bf16* __restrict__ Bh, const bf16* __restrict__ Bl,
    int ldb, long long sB1, long long sB2,
    float* __restrict__ C, bf16* __restrict__ Chi, bf16* __restrict__ Clo,
    int ldc, long long sC1, long long sC2,
    const float* __restrict__ bias,
    const float* __restrict__ resid, int ldr, long long sR1, long long sR2,
    int K, float alpha, int batch2)
{
    extern __shared__ char smem[];
    const uint32_t sbase = smem_u32(smem);
    const uint32_t tiles = (sbase + 1023u) & ~1023u;
    constexpr int ASZ = 128 * 128;          // A stage bytes (128 rows x 128B)
    constexpr int BSZ = BN * 128;
    constexpr int STG = ASZ + BSZ;
    constexpr int NT8 = BN / 16;            // n8 tiles per warp
    constexpr int NG  = BN / 32;            // n16 ldmatrix groups per warp

    const int tid = threadIdx.x, wid = tid >> 5, lane = tid & 31;
    const int z = blockIdx.z, z1 = z / batch2, z2 = z - z1 * batch2;
    const long long aOff = (long long)z1 * sA1 + (long long)z2 * sA2;
    const long long bOff = (long long)z1 * sB1 + (long long)z2 * sB2;
    const long long cOff = (long long)z1 * sC1 + (long long)z2 * sC2;
    Ah += aOff; Al += aOff; Bh += bOff; Bl += bOff;
    const int m0 = blockIdx.y * 128, n0 = blockIdx.x * BN;
    const int m0w = (wid & 3) * 32;          // warp m offset
    const int n0w = (wid >> 2) * (BN / 2);   // warp n offset

    const int kc = K >> 6;       // 64-elem chunks per pass
    const int nc = 3 * kc;       // hi*hi, lo*hi, hi*lo

    auto load_chunk = [&](int c, int s) {
        const int seg = c / kc, kk = c - seg * kc;
        const bf16* A = (seg == 1) ? Al : Ah;
        const bf16* B = (seg == 2) ? Bl : Bh;
        const int k0 = kk << 6;
        const uint32_t aB = tiles + s * STG;
        const uint32_t bB = aB + ASZ;
        const int NU = 1024 + BN * 8;        // 16B units
        for (int u = tid; u < NU; u += 256) {
            if (u < 1024) {
                int r = u >> 3, g = u & 7;
                CP_ASYNC16(aB + SWZ(r * 128 + g * 16),
                           A + (long long)(m0 + r) * lda + k0 + g * 8);
            } else {
                int u2 = u - 1024;
                int r = u2 >> 3, g = u2 & 7;
                CP_ASYNC16(bB + SWZ(r * 128 + g * 16),
                           B + (long long)(n0 + r) * ldb + k0 + g * 8);
            }
        }
        CP_COMMIT();
    };

    float acc[2][NT8][4];
    #pragma unroll
    for (int i = 0; i < 2; i++)
        #pragma unroll
        for (int j = 0; j < NT8; j++)
            #pragma unroll
            for (int q = 0; q < 4; q++) acc[i][j][q] = 0.f;

    // prologue
    load_chunk(0, 0);
    if (nc > 1) load_chunk(1, 1);

    const int lrow = lane & 15;
    const int lcol = (lane >> 4) * 16;

    for (int c = 0; c < nc; c++) {
        const int s = c % 3;
        cp_wait(c + 1 < nc ? 1 : 0);
        __syncthreads();
        if (c + 2 < nc) load_chunk(c + 2, (c + 2) % 3);

        const uint32_t aSt = tiles + s * STG;
        const uint32_t bSt = aSt + ASZ;
        #pragma unroll
        for (int ks = 0; ks < 4; ks++) {
            uint32_t ra[2][4];
            #pragma unroll
            for (int mt = 0; mt < 2; mt++)
                ldmx4(ra[mt], aSt + SWZ((m0w + mt * 16 + lrow) * 128 + ks * 32 + lcol));
            uint32_t rb[NG][4];
            #pragma unroll
            for (int ng = 0; ng < NG; ng++)
                ldmx4(rb[ng], bSt + SWZ((n0w + ng * 16 + lrow) * 128 + ks * 32 + lcol));
            #pragma unroll
            for (int mt = 0; mt < 2; mt++)
                #pragma unroll
                for (int ng = 0; ng < NG; ng++) {
                    mma_bf16(acc[mt][2 * ng],     ra[mt], rb[ng][0], rb[ng][2]);
                    mma_bf16(acc[mt][2 * ng + 1], ra[mt], rb[ng][1], rb[ng][3]);
                }
        }
        __syncthreads();
    }

    // ---- epilogue (from registers) ----
    const int rq = lane >> 2;          // 0..7
    const int cq = (lane & 3) * 2;     // 0,2,4,6
    #pragma unroll
    for (int mt = 0; mt < 2; mt++) {
        #pragma unroll
        for (int half = 0; half < 2; half++) {
            const int m = m0 + m0w + mt * 16 + rq + half * 8;
            const float bv = bias ? bias[m] : 0.f;
            const long long cBase = cOff + (long long)m * ldc + n0 + n0w;
            const long long rBase = resid ? ((long long)z1 * sR1 + (long long)z2 * sR2 +
                                             (long long)m * ldr + n0 + n0w) : 0;
            #pragma unroll
            for (int nt = 0; nt < NT8; nt++) {
                float v0 = acc[mt][nt][half * 2]     * alpha + bv;
                float v1 = acc[mt][nt][half * 2 + 1] * alpha + bv;
                const int cn = nt * 8 + cq;
                if (resid) {
                    v0 += resid[rBase + cn];
                    v1 += resid[rBase + cn + 1];
                }
                if (C)
                    *(float2*)(C + cBase + cn) = make_float2(v0, v1);
                if (Chi) {
                    bf16 h0, l0, h1, l1;
                    split_bf16(v0, h0, l0);
                    split_bf16(v1, h1, l1);
                    __nv_bfloat162 hp, lp;
                    hp.x = h0; hp.y = h1; lp.x = l0; lp.y = l1;
                    *(__nv_bfloat162*)(Chi + cBase + cn) = hp;
                    *(__nv_bfloat162*)(Clo + cBase + cn) = lp;
                }
            }
        }
    }
}

// ---------------- conversion: fp32 -> bf16 hi/lo ----------------
__global__ __launch_bounds__(256) void conv_split(const float* __restrict__ x,
                                                  bf16* __restrict__ hi, bf16* __restrict__ lo,
                                                  long long n4)
{
    long long i = (long long)blockIdx.x * 256 + threadIdx.x;
    if (i >= n4) return;
    float4 v = ((const float4*)x)[i];
    bf16 h0, l0, h1, l1, h2, l2, h3, l3;
    split_bf16(v.x, h0, l0); split_bf16(v.y, h1, l1);
    split_bf16(v.z, h2, l2); split_bf16(v.w, h3, l3);
    __nv_bfloat162 hp0, hp1, lp0, lp1;
    hp0.x = h0; hp0.y = h1; hp1.x = h2; hp1.y = h3;
    lp0.x = l0; lp0.y = l1; lp1.x = l2; lp1.y = l3;
    ((__nv_bfloat162*)hi)[i * 2]     = hp0;
    ((__nv_bfloat162*)hi)[i * 2 + 1] = hp1;
    ((__nv_bfloat162*)lo)[i * 2]     = lp0;
    ((__nv_bfloat162*)lo)[i * 2 + 1] = lp1;
}

// ---------------- transpose + split: out[c,r] = in[r,c] ----------------
__global__ __launch_bounds__(256) void transpose_split(
    const float* __restrict__ in, int ldi, long long sI1, long long sI2,
    bf16* __restrict__ oh, bf16* __restrict__ ol, int ldo, long long sO1, long long sO2,
    int batch2)
{
    __shared__ float t[32][33];
    int z = blockIdx.z, z1 = z / batch2, z2 = z - z1 * batch2;
    in += (long long)z1 * sI1 + (long long)z2 * sI2;
    long long oOff = (long long)z1 * sO1 + (long long)z2 * sO2;
    int r0 = blockIdx.y * 32, c0 = blockIdx.x * 32;
    int tx = threadIdx.x & 31, ty8 = threadIdx.x >> 5;
    #pragma unroll
    for (int i = 0; i < 4; i++) {
        int ty = ty8 + i * 8;
        t[ty][tx] = in[(long long)(r0 + ty) * ldi + c0 + tx];
    }
    __syncthreads();
    #pragma unroll
    for (int i = 0; i < 4; i++) {
        int oy = ty8 + i * 8;
        float v = t[tx][oy];
        bf16 h, l;
        split_bf16(v, h, l);
        long long idx = oOff + (long long)(c0 + oy) * ldo + r0 + tx;
        oh[idx] = h;
        ol[idx] = l;
    }
}

// ---------------- rmsnorm + split ----------------
__global__ __launch_bounds__(256) void rmsnorm_split(
    const float* __restrict__ x, const float* __restrict__ w,
    float* __restrict__ y, bf16* __restrict__ yh, bf16* __restrict__ yl)
{
    __shared__ float red[256];
    long long row = blockIdx.x;
    const float* xr = x + row * HID;
    int tid = threadIdx.x;
    float4 v0 = *(const float4*)(xr + tid * 4);
    float4 v1 = *(const float4*)(xr + 1024 + tid * 4);
    float s = v0.x * v0.x + v0.y * v0.y + v0.z * v0.z + v0.w * v0.w
            + v1.x * v1.x + v1.y * v1.y + v1.z * v1.z + v1.w * v1.w;
    red[tid] = s;
    __syncthreads();
    for (int st = 128; st > 0; st >>= 1) {
        if (tid < st) red[tid] += red[tid + st];
        __syncthreads();
    }
    float inv = rsqrtf(red[0] * (1.f / HID) + EPS_RMS);

    float4 w0 = *(const float4*)(w + tid * 4);
    float4 w1 = *(const float4*)(w + 1024 + tid * 4);
    float o[8];
    o[0] = v0.x * inv * w0.x; o[1] = v0.y * inv * w0.y;
    o[2] = v0.z * inv * w0.z; o[3] = v0.w * inv * w0.w;
    o[4] = v1.x * inv * w1.x; o[5] = v1.y * inv * w1.y;
    o[6] = v1.z * inv * w1.z; o[7] = v1.w * inv * w1.w;
    float* yr = y + row * HID;
    *(float4*)(yr + tid * 4) = make_float4(o[0], o[1], o[2], o[3]);
    *(float4*)(yr + 1024 + tid * 4) = make_float4(o[4], o[5], o[6], o[7]);
    bf16* yhr = yh + row * HID;
    bf16* ylr = yl + row * HID;
    #pragma unroll
    for (int g = 0; g < 2; g++) {
        __nv_bfloat162 hp0, hp1, lp0, lp1;
        bf16 h, l;
        split_bf16(o[g * 4 + 0], h, l); hp0.x = h; lp0.x = l;
        split_bf16(o[g * 4 + 1], h, l); hp0.y = h; lp0.y = l;
        split_bf16(o[g * 4 + 2], h, l); hp1.x = h; lp1.x = l;
        split_bf16(o[g * 4 + 3], h, l); hp1.y = h; lp1.y = l;
        int off = g * 1024 + tid * 4;
        *(__nv_bfloat162*)(yhr + off)     = hp0;
        *(__nv_bfloat162*)(yhr + off + 2) = hp1;
        *(__nv_bfloat162*)(ylr + off)     = lp0;
        *(__nv_bfloat162*)(ylr + off + 2) = lp1;
    }
}

// ---------------- softmax (rows of T_LEN) -> bf16 hi/lo ----------------
__global__ __launch_bounds__(256) void softmax_split(
    const float* __restrict__ s, bf16* __restrict__ oh, bf16* __restrict__ ol)
{
    __shared__ float red[256];
    long long row = blockIdx.x;
    const float* p = s + row * (long long)T_LEN;
    int tid = threadIdx.x;

    float vals[6];
    float m = -1e30f;
    #pragma unroll
    for (int j = 0; j < 6; j++) {
        vals[j] = p[tid + j * 256];
        m = fmaxf(m, vals[j]);
    }
    red[tid] = m;
    __syncthreads();
    for (int st = 128; st > 0; st >>= 1) {
        if (tid < st) red[tid] = fmaxf(red[tid], red[tid + st]);
        __syncthreads();
    }
    m = red[0];
    __syncthreads();

    float sum = 0.f;
    #pragma unroll
    for (int j = 0; j < 6; j++) {
        vals[j] = __expf(vals[j] - m);
        sum += vals[j];
    }
    red[tid] = sum;
    __syncthreads();
    for (int st = 128; st > 0; st >>= 1) {
        if (tid < st) red[tid] += red[tid + st];
        __syncthreads();
    }
    float inv = 1.f / red[0];
    bf16* ohr = oh + row * (long long)T_LEN;
    bf16* olr = ol + row * (long long)T_LEN;
    #pragma unroll
    for (int j = 0; j < 6; j++) {
        float v = vals[j] * inv;
        bf16 h, l;
        split_bf16(v, h, l);
        ohr[tid + j * 256] = h;
        olr[tid + j * 256] = l;
    }
}

// ---------------- silu(g) * u -> bf16 hi/lo ----------------
__global__ __launch_bounds__(256) void silu_split(
    const float* __restrict__ g, const float* __restrict__ u,
    bf16* __restrict__ oh, bf16* __restrict__ ol)
{
    long long i = (long long)blockIdx.x * 256 + threadIdx.x;
    float4 gv = ((const float4*)g)[i];
    float4 uv = ((const float4*)u)[i];
    float o0 = uv.x * gv.x / (1.f + __expf(-gv.x));
    float o1 = uv.y * gv.y / (1.f + __expf(-gv.y));
    float o2 = uv.z * gv.z / (1.f + __expf(-gv.z));
    float o3 = uv.w * gv.w / (1.f + __expf(-gv.w));
    bf16 h0, l0, h1, l1, h2, l2, h3, l3;
    split_bf16(o0, h0, l0); split_bf16(o1, h1, l1);
    split_bf16(o2, h2, l2); split_bf16(o3, h3, l3);
    __nv_bfloat162 hp0, hp1, lp0, lp1;
    hp0.x = h0; hp0.y = h1; hp1.x = h2; hp1.y = h3;
    lp0.x = l0; lp0.y = l1; lp1.x = l2; lp1.y = l3;
    ((__nv_bfloat162*)oh)[i * 2]     = hp0;
    ((__nv_bfloat162*)oh)[i * 2 + 1] = hp1;
    ((__nv_bfloat162*)ol)[i * 2]     = lp0;
    ((__nv_bfloat162*)ol)[i * 2 + 1] = lp1;
}

// ---------------- host ----------------
static void* sym(const void* s) {
    void* p = nullptr;
    cudaGetSymbolAddress(&p, s);
    return p;
}

extern "C" void kernel_launch(void* const* d_in, const int* in_sizes, int n_in,
                              void* d_out, int out_size)
{
    const float* h_in = (const float*)d_in[0];
    const float* Wup  = (const float*)d_in[1];
    const float* bup  = (const float*)d_in[2];
    const float* anw  = (const float*)d_in[3];
    const float* Wq   = (const float*)d_in[4];
    const float* Wk   = (const float*)d_in[5];
    const float* Wv   = (const float*)d_in[6];
    const float* Wo   = (const float*)d_in[7];
    const float* mnw  = (const float*)d_in[8];
    const float* Wg   = (const float*)d_in[9];
    const float* Wu   = (const float*)d_in[10];
    const float* Wd   = (const float*)d_in[11];
    float* out = (float*)d_out;

    float* up_   = (float*)sym(g_up);
    float* x1_   = (float*)sym(g_x1);
    float* x2_   = (float*)sym(g_x2);
    float* x3_   = (float*)sym(g_x3);
    float* v_    = (float*)sym(g_v);
    float* sc_   = (float*)sym(g_sc);
    float* gate_ = (float*)sym(g_gate);
    float* ubuf_ = (float*)sym(g_ubuf);

    bf16 *hh = (bf16*)sym(b_h_hi),  *hl = (bf16*)sym(b_h_lo);
    bf16 *hth = (bf16*)sym(b_ht_hi), *htl = (bf16*)sym(b_ht_lo);
    bf16 *wuph = (bf16*)sym(b_wup_hi), *wupl = (bf16*)sym(b_wup_lo);
    bf16 *wqh = (bf16*)sym(b_wq_hi), *wql = (bf16*)sym(b_wq_lo);
    bf16 *wkh = (bf16*)sym(b_wk_hi), *wkl = (bf16*)sym(b_wk_lo);
    bf16 *wvh = (bf16*)sym(b_wv_hi), *wvl = (bf16*)sym(b_wv_lo);
    bf16 *woh = (bf16*)sym(b_wo_hi), *wol = (bf16*)sym(b_wo_lo);
    bf16 *wgh = (bf16*)sym(b_wg_hi), *wgl = (bf16*)sym(b_wg_lo);
    bf16 *wuh = (bf16*)sym(b_wu_hi), *wul = (bf16*)sym(b_wu_lo);
    bf16 *wdh = (bf16*)sym(b_wd_hi), *wdl = (bf16*)sym(b_wd_lo);
    bf16 *uph = (bf16*)sym(b_up_hi), *upl = (bf16*)sym(b_up_lo);
    bf16 *x1h = (bf16*)sym(b_x1_hi), *x1l = (bf16*)sym(b_x1_lo);
    bf16 *x3h = (bf16*)sym(b_x3_hi), *x3l = (bf16*)sym(b_x3_lo);
    bf16 *qh = (bf16*)sym(b_q_hi),   *ql = (bf16*)sym(b_q_lo);
    bf16 *kh = (bf16*)sym(b_k_hi),   *kl = (bf16*)sym(b_k_lo);
    bf16 *oh = (bf16*)sym(b_o_hi),   *ol = (bf16*)sym(b_o_lo);
    bf16 *vth = (bf16*)sym(b_vt_hi), *vtl = (bf16*)sym(b_vt_lo);
    bf16 *ath = (bf16*)sym(b_at_hi), *atl = (bf16*)sym(b_at_lo);
    bf16 *ubh = (bf16*)sym(b_ub_hi), *ubl = (bf16*)sym(b_ub_lo);

    const int SMEM128 = 1024 + 3 * (128 * 128 + 128 * 128);  // 99328
    const int SMEM64  = 1024 + 3 * (128 * 128 + 64 * 128);   // 74752
    cudaFuncSetAttribute(mma_gemm<128>, cudaFuncAttributeMaxDynamicSharedMemorySize, SMEM128);
    cudaFuncSetAttribute(mma_gemm<64>,  cudaFuncAttributeMaxDynamicSharedMemorySize, SMEM64);

    dim3 blk(256);

    // ---- input conversions ----
    auto conv = [&](const float* x, bf16* hi, bf16* lo, long long n) {
        long long n4 = n / 4;
        conv_split<<<(unsigned)((n4 + 255) / 256), blk>>>(x, hi, lo, n4);
    };
    conv(h_in, hh, hl, HB);
    conv(Wup, wuph, wupl, WUPN);
    conv(Wq, wqh, wql, W1N);
    conv(Wk, wkh, wkl, W1N);
    conv(Wv, wvh, wvl, W1N);
    conv(Wo, woh, wol, W1N);
    conv(Wg, wgh, wgl, W2N);
    conv(Wu, wuh, wul, W2N);
    conv(Wd, wdh, wdl, W2N);

    // h [S,H] -> hT [H,S] per batch
    transpose_split<<<dim3(HID / 32, S_LEN / 32, BATCH), blk>>>(
        h_in, HID, S_H, 0, hth, htl, S_LEN, S_H, 0, 1);

    // 1) up = Wup @ h (NT vs hT), +bias, fp32 + split
    mma_gemm<128><<<dim3(HID / 128, SU_LEN / 128, BATCH), blk, SMEM128>>>(
        wuph, wupl, S_LEN, 0, 0,
        hth, htl, S_LEN, S_H, 0,
        up_, uph, upl, HID, SU_H, 0,
        bup, nullptr, 0, 0, 0,
        S_LEN, 1.f, 1);

    // 2) x1 = rmsnorm(up)
    rmsnorm_split<<<BATCH * SU_LEN, blk>>>(up_, anw, x1_, x1h, x1l);

    // 3) q = x1 @ Wq^T
    mma_gemm<128><<<dim3(HID / 128, SU_LEN / 128, BATCH), blk, SMEM128>>>(
        x1h, x1l, HID, SU_H, 0,
        wqh, wql, HID, 0, 0,
        nullptr, qh, ql, HID, SU_H, 0,
        nullptr, nullptr, 0, 0, 0,
        HID, 1.f, 1);

    // 4) k = [h; up] @ Wk^T
    mma_gemm<128><<<dim3(HID / 128, S_LEN / 128, BATCH), blk, SMEM128>>>(
        hh, hl, HID, S_H, 0,
        wkh, wkl, HID, 0, 0,
        nullptr, kh, kl, HID, T_H, 0,
        nullptr, nullptr, 0, 0, 0,
        HID, 1.f, 1);
    mma_gemm<128><<<dim3(HID / 128, SU_LEN / 128, BATCH), blk, SMEM128>>>(
        uph, upl, HID, SU_H, 0,
        wkh, wkl, HID, 0, 0,
        nullptr, kh + (long long)S_LEN * HID, kl + (long long)S_LEN * HID, HID, T_H, 0,
        nullptr, nullptr, 0, 0, 0,
        HID, 1.f, 1);

    // 5) v = [h; up] @ Wv^T (fp32; transposed+split below)
    mma_gemm<128><<<dim3(HID / 128, S_LEN / 128, BATCH), blk, SMEM128>>>(
        hh, hl, HID, S_H, 0,
        wvh, wvl, HID, 0, 0,
        v_, nullptr, nullptr, HID, T_H, 0,
        nullptr, nullptr, 0, 0, 0,
        HID, 1.f, 1);
    mma_gemm<128><<<dim3(HID / 128, SU_LEN / 128, BATCH), blk, SMEM128>>>(
        uph, upl, HID, SU_H, 0,
        wvh, wvl, HID, 0, 0,
        v_ + (long long)S_LEN * HID, nullptr, nullptr, HID, T_H, 0,
        nullptr, nullptr, 0, 0, 0,
        HID, 1.f, 1);

    // v[b,t,h,d] -> vT[b,h,d,t]
    transpose_split<<<dim3(HDIM / 32, T_LEN / 32, BATCH * NHEAD), blk>>>(
        v_, HID, T_H, HDIM,
        vth, vtl, T_LEN, T_H, (long long)HDIM * T_LEN, NHEAD);

    // 6) scores = q @ k^T / 8
    mma_gemm<128><<<dim3(T_LEN / 128, SU_LEN / 128, BATCH * NHEAD), blk, SMEM128>>>(
        qh, ql, HID, SU_H, HDIM,
        kh, kl, HID, T_H, HDIM,
        sc_, nullptr, nullptr, T_LEN, NH_SU_T, SU_T,
        nullptr, nullptr, 0, 0, 0,
        HDIM, 0.125f, NHEAD);

    // 7) softmax -> bf16 split
    softmax_split<<<BATCH * NHEAD * SU_LEN, blk>>>(sc_, ath, atl);

    // 8) o = attn @ vT^T (N = 64 per head)
    mma_gemm<64><<<dim3(1, SU_LEN / 128, BATCH * NHEAD), blk, SMEM64>>>(
        ath, atl, T_LEN, NH_SU_T, SU_T,
        vth, vtl, T_LEN, T_H, (long long)HDIM * T_LEN,
        nullptr, oh, ol, HID, SU_H, HDIM,
        nullptr, nullptr, 0, 0, 0,
        T_LEN, 1.f, NHEAD);

    // 9) x2 = o @ Wo^T + x1
    mma_gemm<128><<<dim3(HID / 128, SU_LEN / 128, BATCH), blk, SMEM128>>>(
        oh, ol, HID, SU_H, 0,
        woh, wol, HID, 0, 0,
        x2_, nullptr, nullptr, HID, SU_H, 0,
        nullptr, x1_, HID, SU_H, 0,
        HID, 1.f, 1);

    // 10) x3 = rmsnorm(x2)
    rmsnorm_split<<<BATCH * SU_LEN, blk>>>(x2_, mnw, x3_, x3h, x3l);

    // 11/12) gate = x3 @ Wg^T ; ubuf = x3 @ Wu^T
    mma_gemm<128><<<dim3(INTER / 128, SU_LEN / 128, BATCH), blk, SMEM128>>>(
        x3h, x3l, HID, SU_H, 0,
        wgh, wgl, HID, 0, 0,
        gate_, nullptr, nullptr, INTER, SU_I, 0,
        nullptr, nullptr, 0, 0, 0,
        HID, 1.f, 1);
    mma_gemm<128><<<dim3(INTER / 128, SU_LEN / 128, BATCH), blk, SMEM128>>>(
        x3h, x3l, HID, SU_H, 0,
        wuh, wul, HID, 0, 0,
        ubuf_, nullptr, nullptr, INTER, SU_I, 0,
        nullptr, nullptr, 0, 0, 0,
        HID, 1.f, 1);

    // 13) silu(gate)*ubuf -> bf16 split
    silu_split<<<(unsigned)(UBB / 1024), blk>>>(gate_, ubuf_, ubh, ubl);

    // 14) out = ub @ Wd^T + x3
    mma_gemm<128><<<dim3(HID / 128, SU_LEN / 128, BATCH), blk, SMEM128>>>(
        ubh, ubl, INTER, SU_I, 0,
        wdh, wdl, INTER, 0, 0,
        out, nullptr, nullptr, HID, SU_H, 0,
        nullptr, x3_, HID, SU_H, 0,
        INTER, 1.f, 1);
}

// round 4
// speedup vs baseline: 2.1190x; 1.0128x over previous
#include <cuda_runtime.h>
#include <cuda_bf16.h>
#include <cstdint>

// ---------------- problem constants ----------------
#define BATCH 2
#define S_LEN 512
#define HID 2048
#define NHEAD 32
#define HDIM 64
#define SU_LEN 1024
#define T_LEN 1536
#define INTER 5632
#define EPS_RMS 1e-6f

#define S_H   (S_LEN * HID)
#define SU_H  (SU_LEN * HID)
#define T_H   (T_LEN * HID)
#define SU_I  ((long long)SU_LEN * INTER)

#define HB  (BATCH * S_LEN * HID)
#define XB  (BATCH * SU_LEN * HID)
#define KB  (BATCH * T_LEN * HID)
#define UBB ((long long)BATCH * SU_LEN * INTER)
#define WUPN (SU_LEN * S_LEN)
#define W1N  (HID * HID)
#define W2N  (INTER * HID)

typedef __nv_bfloat16 bf16;

// ---------------- scratch (device globals; no runtime allocation) ----------------
__device__ float g_up  [XB];
__device__ float g_x1  [XB];
__device__ float g_x2  [XB];
__device__ float g_x3  [XB];
__device__ float g_v   [KB];
__device__ float g_gate[UBB];

__device__ bf16 b_h_hi[HB],  b_h_lo[HB];
__device__ bf16 b_ht_hi[HB], b_ht_lo[HB];
__device__ bf16 b_wup_hi[WUPN], b_wup_lo[WUPN];
__device__ bf16 b_wq_hi[W1N], b_wq_lo[W1N];
__device__ bf16 b_wk_hi[W1N], b_wk_lo[W1N];
__device__ bf16 b_wv_hi[W1N], b_wv_lo[W1N];
__device__ bf16 b_wo_hi[W1N], b_wo_lo[W1N];
__device__ bf16 b_wg_hi[W2N], b_wg_lo[W2N];
__device__ bf16 b_wu_hi[W2N], b_wu_lo[W2N];
__device__ bf16 b_wd_hi[W2N], b_wd_lo[W2N];
__device__ bf16 b_up_hi[XB], b_up_lo[XB];
__device__ bf16 b_x1_hi[XB], b_x1_lo[XB];
__device__ bf16 b_x3_hi[XB], b_x3_lo[XB];
__device__ bf16 b_q_hi[XB],  b_q_lo[XB];
__device__ bf16 b_k_hi[KB],  b_k_lo[KB];
__device__ bf16 b_o_hi[XB],  b_o_lo[XB];
__device__ bf16 b_vt_hi[KB], b_vt_lo[KB];
__device__ bf16 b_ub_hi[UBB], b_ub_lo[UBB];

// ---------------- PTX helpers ----------------
__device__ __forceinline__ uint32_t smem_u32(const void* p) {
    uint32_t a;
    asm("{ .reg .u64 t; cvta.to.shared.u64 t, %1; cvt.u32.u64 %0, t; }" : "=r"(a) : "l"(p));
    return a;
}
#define SWZ(off) ((off) ^ (((off) >> 3) & 0x70))

#define CP_ASYNC16(dst, src) \
    asm volatile("cp.async.cg.shared.global [%0], [%1], 16;" :: "r"(dst), "l"(src) : "memory")
#define CP_COMMIT() asm volatile("cp.async.commit_group;" ::: "memory")
__device__ __forceinline__ void cp_wait(int allow) {
    if (allow) asm volatile("cp.async.wait_group 1;" ::: "memory");
    else       asm volatile("cp.async.wait_group 0;" ::: "memory");
}

__device__ __forceinline__ void ldmx4(uint32_t* r, uint32_t addr) {
    asm volatile("ldmatrix.sync.aligned.m8n8.x4.shared.b16 {%0,%1,%2,%3}, [%4];"
        : "=r"(r[0]), "=r"(r[1]), "=r"(r[2]), "=r"(r[3]) : "r"(addr));
}

__device__ __forceinline__ void mma_bf16(float* d, const uint32_t* a, uint32_t b0, uint32_t b1) {
    asm volatile("mma.sync.aligned.m16n8k16.row.col.f32.bf16.bf16.f32 "
        "{%0,%1,%2,%3}, {%4,%5,%6,%7}, {%8,%9}, {%0,%1,%2,%3};"
        : "+f"(d[0]), "+f"(d[1]), "+f"(d[2]), "+f"(d[3])
        : "r"(a[0]), "r"(a[1]), "r"(a[2]), "r"(a[3]), "r"(b0), "r"(b1));
}

__device__ __forceinline__ void split_bf16(float v, bf16& hi, bf16& lo) {
    hi = __float2bfloat16(v);
    lo = __float2bfloat16(v - __bfloat162float(hi));
}
__device__ __forceinline__ uint32_t pack_bf16x2(bf16 lo_elem, bf16 hi_elem) {
    __nv_bfloat162 t;
    t.x = lo_elem; t.y = hi_elem;
    return *(uint32_t*)&t;
}

// ---------------- mma.sync GEMM ----------------
template<int BN>
__global__ __launch_bounds__(256, 2) void mma_gemm(
    const bf16* __restrict__ Ah, const bf16* __restrict__ Al,
    int lda, long long sA1, long long sA2,
    const bf16* __restrict__ Bh, const bf16* __restrict__ Bl,
    int ldb, long long sB1, long long sB2,
    float* __restrict__ C, bf16* __restrict__ Chi, bf16* __restrict__ Clo,
    int ldc, long long sC1, long long sC2,
    const float* __restrict__ bias,
    const float* __restrict__ resid, int ldr, long long sR1, long long sR2,
    const float* __restrict__ gate,
    int K, float alpha, int batch2)
{
    extern __shared__ char smem[];
    const uint32_t sbase = smem_u32(smem);
    const uint32_t tiles = (sbase + 1023u) & ~1023u;
    constexpr int ASZ = 128 * 128;
    constexpr int BSZ = BN * 128;
    constexpr int STG = ASZ + BSZ;
    constexpr int NT8 = BN / 16;
    constexpr int NG  = BN / 32;

    const int tid = threadIdx.x, wid = tid >> 5, lane = tid & 31;
    const int z = blockIdx.z, z1 = z / batch2, z2 = z - z1 * batch2;
    const long long aOff = (long long)z1 * sA1 + (long long)z2 * sA2;
    const long long bOff = (long long)z1 * sB1 + (long long)z2 * sB2;
    const long long cOff = (long long)z1 * sC1 + (long long)z2 * sC2;
    Ah += aOff; Al += aOff; Bh += bOff; Bl += bOff;
    const int m0 = blockIdx.y * 128, n0 = blockIdx.x * BN;
    const int m0w = (wid & 3) * 32;
    const int n0w = (wid >> 2) * (BN / 2);

    const int kc = K >> 6;
    const int nc = 3 * kc;

    auto load_chunk = [&](int c, int s) {
        const int seg = c / kc, kk = c - seg * kc;
        const bf16* A = (seg == 1) ? Al : Ah;
        const bf16* B = (seg == 2) ? Bl : Bh;
        const int k0 = kk << 6;
        const uint32_t aB = tiles + s * STG;
        const uint32_t bB = aB + ASZ;
        const int NU = 1024 + BN * 8;
        for (int u = tid; u < NU; u += 256) {
            if (u < 1024) {
                int r = u >> 3, g = u & 7;
                CP_ASYNC16(aB + SWZ(r * 128 + g * 16),
                           A + (long long)(m0 + r) * lda + k0 + g * 8);
            } else {
                int u2 = u - 1024;
                int r = u2 >> 3, g = u2 & 7;
                CP_ASYNC16(bB + SWZ(r * 128 + g * 16),
                           B + (long long)(n0 + r) * ldb + k0 + g * 8);
            }
        }
        CP_COMMIT();
    };

    float acc[2][NT8][4];
    #pragma unroll
    for (int i = 0; i < 2; i++)
        #pragma unroll
        for (int j = 0; j < NT8; j++)
            #pragma unroll
            for (int q = 0; q < 4; q++) acc[i][j][q] = 0.f;

    load_chunk(0, 0);
    if (nc > 1) load_chunk(1, 1);

    const int lrow = lane & 15;
    const int lcol = (lane >> 4) * 16;

    for (int c = 0; c < nc; c++) {
        const int s = c % 3;
        cp_wait(c + 1 < nc ? 1 : 0);
        __syncthreads();
        if (c + 2 < nc) load_chunk(c + 2, (c + 2) % 3);

        const uint32_t aSt = tiles + s * STG;
        const uint32_t bSt = aSt + ASZ;
        #pragma unroll
        for (int ks = 0; ks < 4; ks++) {
            uint32_t ra[2][4];
            #pragma unroll
            for (int mt = 0; mt < 2; mt++)
                ldmx4(ra[mt], aSt + SWZ((m0w + mt * 16 + lrow) * 128 + ks * 32 + lcol));
            uint32_t rb[NG][4];
            #pragma unroll
            for (int ng = 0; ng < NG; ng++)
                ldmx4(rb[ng], bSt + SWZ((n0w + ng * 16 + lrow) * 128 + ks * 32 + lcol));
            #pragma unroll
            for (int mt = 0; mt < 2; mt++)
                #pragma unroll
                for (int ng = 0; ng < NG; ng++) {
                    mma_bf16(acc[mt][2 * ng],     ra[mt], rb[ng][0], rb[ng][2]);
                    mma_bf16(acc[mt][2 * ng + 1], ra[mt], rb[ng][1], rb[ng][3]);
                }
        }
        __syncthreads();
    }

    const int rq = lane >> 2;
    const int cq = (lane & 3) * 2;
    #pragma unroll
    for (int mt = 0; mt < 2; mt++) {
        #pragma unroll
        for (int half = 0; half < 2; half++) {
            const int m = m0 + m0w + mt * 16 + rq + half * 8;
            const float bv = bias ? bias[m] : 0.f;
            const long long cBase = cOff + (long long)m * ldc + n0 + n0w;
            const long long rBase = resid ? ((long long)z1 * sR1 + (long long)z2 * sR2 +
                                             (long long)m * ldr + n0 + n0w) : 0;
            #pragma unroll
            for (int nt = 0; nt < NT8; nt++) {
                float v0 = acc[mt][nt][half * 2]     * alpha + bv;
                float v1 = acc[mt][nt][half * 2 + 1] * alpha + bv;
                const int cn = nt * 8 + cq;
                if (resid) {
                    v0 += resid[rBase + cn];
                    v1 += resid[rBase + cn + 1];
                }
                if (gate) {
                    float g0 = gate[cBase + cn];
                    float g1 = gate[cBase + cn + 1];
                    v0 *= g0 / (1.f + __expf(-g0));
                    v1 *= g1 / (1.f + __expf(-g1));
                }
                if (C)
                    *(float2*)(C + cBase + cn) = make_float2(v0, v1);
                if (Chi) {
                    bf16 h0, l0, h1, l1;
                    split_bf16(v0, h0, l0);
                    split_bf16(v1, h1, l1);
                    *(uint32_t*)(Chi + cBase + cn) = pack_bf16x2(h0, h1);
                    *(uint32_t*)(Clo + cBase + cn) = pack_bf16x2(l0, l1);
                }
            }
        }
    }
}

// ---------------- fused flash attention ----------------
// grid: (SU/128, BATCH*NHEAD). 8 warps, each warp owns 16 q rows.
// Q/K split hi/lo (3-pass QK^T), P split hi/lo in-register (3-pass PV).
#define FA_NI (T_LEN / 128)   // 12

__global__ __launch_bounds__(256, 1) void flash_attn(
    const bf16* __restrict__ gqh, const bf16* __restrict__ gql,
    const bf16* __restrict__ gkh, const bf16* __restrict__ gkl,
    const bf16* __restrict__ gvh, const bf16* __restrict__ gvl,
    bf16* __restrict__ goh, bf16* __restrict__ gol)
{
    extern __shared__ char smem[];
    const uint32_t sb = smem_u32(smem);
    const uint32_t Qh = sb, Ql = sb + 16384;
    const uint32_t ST0 = sb + 32768;
    const uint32_t STSZ = 65536;   // per stage: Kh 16K, Kl 16K, Vh 16K, Vl 16K

    const int tid = threadIdx.x, wid = tid >> 5, lane = tid & 31;
    const int q0 = blockIdx.x * 128;
    const int bh = blockIdx.y;
    const int b = bh >> 5, head = bh & 31;

    const bf16* qhp = gqh + (long long)b * SU_H + head * HDIM;
    const bf16* qlp = gql + (long long)b * SU_H + head * HDIM;
    const bf16* khp = gkh + (long long)b * T_H + head * HDIM;
    const bf16* klp = gkl + (long long)b * T_H + head * HDIM;
    const bf16* vhp = gvh + (long long)b * T_H + (long long)head * HDIM * T_LEN;
    const bf16* vlp = gvl + (long long)b * T_H + (long long)head * HDIM * T_LEN;

    // load Q (once)
    for (int u = tid; u < 2048; u += 256) {
        int comp = u >> 10, r = (u >> 3) & 127, g = u & 7;
        const bf16* src = (comp ? qlp : qhp) + (long long)(q0 + r) * HID + g * 8;
        CP_ASYNC16((comp ? Ql : Qh) + SWZ(r * 128 + g * 16), src);
    }
    CP_COMMIT();

    auto loadkv = [&](int ci, int s) {
        const int t0 = ci * 128;
        const uint32_t stb = ST0 + s * STSZ;
        for (int u = tid; u < 4096; u += 256) {
            if (u < 2048) {
                int comp = u >> 10, r = (u >> 3) & 127, g = u & 7;
                const bf16* src = (comp ? klp : khp) + (long long)(t0 + r) * HID + g * 8;
                CP_ASYNC16(stb + comp * 16384 + SWZ(r * 128 + g * 16), src);
            } else {
                int u2 = u - 2048;
                int comp = u2 >> 10; u2 &= 1023;
                int d = u2 >> 4, gg = u2 & 15;     // 16 col-groups of 8 over 128 t cols
                const bf16* src = (comp ? vlp : vhp) + (long long)d * T_LEN + t0 + gg * 8;
                CP_ASYNC16(stb + 32768 + comp * 16384 + (gg >> 3) * 8192 +
                           SWZ(d * 128 + (gg & 7) * 16), src);
            }
        }
        CP_COMMIT();
    };

    loadkv(0, 0);
    loadkv(1, 1);
    cp_wait(1);              // Q + chunk0 ready
    __syncthreads();

    // Q fragments (held in registers for the whole kernel)
    const int lrow = lane & 15, lcol = (lane >> 4) * 16;
    const int mrow = wid * 16;
    uint32_t qf[2][4][4];
    #pragma unroll
    for (int ks = 0; ks < 4; ks++) {
        ldmx4(qf[0][ks], Qh + SWZ((mrow + lrow) * 128 + ks * 32 + lcol));
        ldmx4(qf[1][ks], Ql + SWZ((mrow + lrow) * 128 + ks * 32 + lcol));
    }

    float oacc[8][4];
    #pragma unroll
    for (int i = 0; i < 8; i++)
        #pragma unroll
        for (int j = 0; j < 4; j++) oacc[i][j] = 0.f;
    float M0 = -1e30f, M1 = -1e30f, L0 = 0.f, L1 = 0.f;

    for (int i = 0; i < FA_NI; i++) {
        const uint32_t stb = ST0 + (i & 1) * STSZ;
        if (i > 0) { cp_wait(i + 1 < FA_NI ? 1 : 0); __syncthreads(); }

        // ---- S = Q K^T (3 passes) ----
        float sacc[16][4];
        #pragma unroll
        for (int t = 0; t < 16; t++)
            #pragma unroll
            for (int j = 0; j < 4; j++) sacc[t][j] = 0.f;

        #pragma unroll
        for (int p = 0; p < 3; p++) {
            const uint32_t kb = stb + (p == 2 ? 16384 : 0);
            const int qi = (p == 1) ? 1 : 0;
            #pragma unroll
            for (int ks = 0; ks < 4; ks++) {
                #pragma unroll
                for (int ng = 0; ng < 8; ng++) {
                    uint32_t rb[4];
                    ldmx4(rb, kb + SWZ((ng * 16 + lrow) * 128 + ks * 32 + lcol));
                    mma_bf16(sacc[2 * ng],     qf[qi][ks], rb[0], rb[2]);
                    mma_bf16(sacc[2 * ng + 1], qf[qi][ks], rb[1], rb[3]);
                }
            }
        }

        // ---- online softmax ----
        float mx0 = -1e30f, mx1 = -1e30f;
        #pragma unroll
        for (int t = 0; t < 16; t++) {
            sacc[t][0] *= 0.125f; sacc[t][1] *= 0.125f;
            sacc[t][2] *= 0.125f; sacc[t][3] *= 0.125f;
            mx0 = fmaxf(mx0, fmaxf(sacc[t][0], sacc[t][1]));
            mx1 = fmaxf(mx1, fmaxf(sacc[t][2], sacc[t][3]));
        }
        mx0 = fmaxf(mx0, __shfl_xor_sync(0xFFFFFFFFu, mx0, 1));
        mx0 = fmaxf(mx0, __shfl_xor_sync(0xFFFFFFFFu, mx0, 2));
        mx1 = fmaxf(mx1, __shfl_xor_sync(0xFFFFFFFFu, mx1, 1));
        mx1 = fmaxf(mx1, __shfl_xor_sync(0xFFFFFFFFu, mx1, 2));
        const float Mn0 = fmaxf(M0, mx0), Mn1 = fmaxf(M1, mx1);
        const float al0 = __expf(M0 - Mn0), al1 = __expf(M1 - Mn1);
        M0 = Mn0; M1 = Mn1;

        float s0 = 0.f, s1 = 0.f;
        #pragma unroll
        for (int t = 0; t < 16; t++) {
            sacc[t][0] = __expf(sacc[t][0] - M0); s0 += sacc[t][0];
            sacc[t][1] = __expf(sacc[t][1] - M0); s0 += sacc[t][1];
            sacc[t][2] = __expf(sacc[t][2] - M1); s1 += sacc[t][2];
            sacc[t][3] = __expf(sacc[t][3] - M1); s1 += sacc[t][3];
        }
        s0 += __shfl_xor_sync(0xFFFFFFFFu, s0, 1);
        s0 += __shfl_xor_sync(0xFFFFFFFFu, s0, 2);
        s1 += __shfl_xor_sync(0xFFFFFFFFu, s1, 1);
        s1 += __shfl_xor_sync(0xFFFFFFFFu, s1, 2);
        L0 = L0 * al0 + s0;
        L1 = L1 * al1 + s1;
        #pragma unroll
        for (int t = 0; t < 8; t++) {
            oacc[t][0] *= al0; oacc[t][1] *= al0;
            oacc[t][2] *= al1; oacc[t][3] *= al1;
        }

        // ---- O += P V (3 passes, P split in-register) ----
        const uint32_t vb = stb + 32768;
        #pragma unroll
        for (int ks = 0; ks < 8; ks++) {
            // A frags for k16 step ks from sacc tiles 2ks, 2ks+1
            float p0 = sacc[2 * ks][0],     p1 = sacc[2 * ks][1];
            float p2 = sacc[2 * ks][2],     p3 = sacc[2 * ks][3];
            float p4 = sacc[2 * ks + 1][0], p5 = sacc[2 * ks + 1][1];
            float p6 = sacc[2 * ks + 1][2], p7 = sacc[2 * ks + 1][3];
            bf16 h0, l0, h1, l1, h2, l2, h3, l3, h4, l4, h5, l5, h6, l6, h7, l7;
            split_bf16(p0, h0, l0); split_bf16(p1, h1, l1);
            split_bf16(p2, h2, l2); split_bf16(p3, h3, l3);
            split_bf16(p4, h4, l4); split_bf16(p5, h5, l5);
            split_bf16(p6, h6, l6); split_bf16(p7, h7, l7);
            uint32_t ah[4], alr[4];
            ah[0] = pack_bf16x2(h0, h1);  ah[1] = pack_bf16x2(h2, h3);
            ah[2] = pack_bf16x2(h4, h5);  ah[3] = pack_bf16x2(h6, h7);
            alr[0] = pack_bf16x2(l0, l1); alr[1] = pack_bf16x2(l2, l3);
            alr[2] = pack_bf16x2(l4, l5); alr[3] = pack_bf16x2(l6, l7);

            const uint32_t vhb = vb + (ks >> 2) * 8192;
            const int ksl = ks & 3;
            #pragma unroll
            for (int ng = 0; ng < 4; ng++) {
                uint32_t rb[4];
                ldmx4(rb, vhb + SWZ((ng * 16 + lrow) * 128 + ksl * 32 + lcol));
                mma_bf16(oacc[2 * ng],     ah,  rb[0], rb[2]);
                mma_bf16(oacc[2 * ng + 1], ah,  rb[1], rb[3]);
                mma_bf16(oacc[2 * ng],     alr, rb[0], rb[2]);
                mma_bf16(oacc[2 * ng + 1], alr, rb[1], rb[3]);
            }
            const uint32_t vlb = vhb + 16384;
            #pragma unroll
            for (int ng = 0; ng < 4; ng++) {
                uint32_t rb[4];
                ldmx4(rb, vlb + SWZ((ng * 16 + lrow) * 128 + ksl * 32 + lcol));
                mma_bf16(oacc[2 * ng],     ah, rb[0], rb[2]);
                mma_bf16(oacc[2 * ng + 1], ah, rb[1], rb[3]);
            }
        }

        __syncthreads();
        if (i + 2 < FA_NI) loadkv(i + 2, i & 1);
    }

    // ---- epilogue: O /= L, write hi/lo bf16 ----
    const float inv0 = 1.f / L0, inv1 = 1.f / L1;
    const int rq = lane >> 2, cq = (lane & 3) * 2;
    const long long base0 = (long long)b * SU_H + (long long)(q0 + mrow + rq) * HID + head * HDIM;
    const long long base1 = base0 + 8LL * HID;
    #pragma unroll
    for (int nt = 0; nt < 8; nt++) {
        const int cn = nt * 8 + cq;
        float v0 = oacc[nt][0] * inv0, v1 = oacc[nt][1] * inv0;
        float v2 = oacc[nt][2] * inv1, v3 = oacc[nt][3] * inv1;
        bf16 h0, l0, h1, l1, h2, l2, h3, l3;
        split_bf16(v0, h0, l0); split_bf16(v1, h1, l1);
        split_bf16(v2, h2, l2); split_bf16(v3, h3, l3);
        *(uint32_t*)(goh + base0 + cn) = pack_bf16x2(h0, h1);
        *(uint32_t*)(gol + base0 + cn) = pack_bf16x2(l0, l1);
        *(uint32_t*)(goh + base1 + cn) = pack_bf16x2(h2, h3);
        *(uint32_t*)(gol + base1 + cn) = pack_bf16x2(l2, l3);
    }
}

// ---------------- conversion: fp32 -> bf16 hi/lo ----------------
__global__ __launch_bounds__(256) void conv_split(const float* __restrict__ x,
                                                  bf16* __restrict__ hi, bf16* __restrict__ lo,
                                                  long long n4)
{
    long long i = (long long)blockIdx.x * 256 + threadIdx.x;
    if (i >= n4) return;
    float4 v = ((const float4*)x)[i];
    bf16 h0, l0, h1, l1, h2, l2, h3, l3;
    split_bf16(v.x, h0, l0); split_bf16(v.y, h1, l1);
    split_bf16(v.z, h2, l2); split_bf16(v.w, h3, l3);
    ((uint32_t*)hi)[i * 2]     = pack_bf16x2(h0, h1);
    ((uint32_t*)hi)[i * 2 + 1] = pack_bf16x2(h2, h3);
    ((uint32_t*)lo)[i * 2]     = pack_bf16x2(l0, l1);
    ((uint32_t*)lo)[i * 2 + 1] = pack_bf16x2(l2, l3);
}

// ---------------- transpose + split: out[c,r] = in[r,c] ----------------
__global__ __launch_bounds__(256) void transpose_split(
    const float* __restrict__ in, int ldi, long long sI1, long long sI2,
    bf16* __restrict__ oh, bf16* __restrict__ ol, int ldo, long long sO1, long long sO2,
    int batch2)
{
    __shared__ float t[32][33];
    int z = blockIdx.z, z1 = z / batch2, z2 = z - z1 * batch2;
    in += (long long)z1 * sI1 + (long long)z2 * sI2;
    long long oOff = (long long)z1 * sO1 + (long long)z2 * sO2;
    int r0 = blockIdx.y * 32, c0 = blockIdx.x * 32;
    int tx = threadIdx.x & 31, ty8 = threadIdx.x >> 5;
    #pragma unroll
    for (int i = 0; i < 4; i++) {
        int ty = ty8 + i * 8;
        t[ty][tx] = in[(long long)(r0 + ty) * ldi + c0 + tx];
    }
    __syncthreads();
    #pragma unroll
    for (int i = 0; i < 4; i++) {
        int oy = ty8 + i * 8;
        float v = t[tx][oy];
        bf16 h, l;
        split_bf16(v, h, l);
        long long idx = oOff + (long long)(c0 + oy) * ldo + r0 + tx;
        oh[idx] = h;
        ol[idx] = l;
    }
}

// ---------------- rmsnorm + split ----------------
__global__ __launch_bounds__(256) void rmsnorm_split(
    const float* __restrict__ x, const float* __restrict__ w,
    float* __restrict__ y, bf16* __restrict__ yh, bf16* __restrict__ yl)
{
    __shared__ float red[256];
    long long row = blockIdx.x;
    const float* xr = x + row * HID;
    int tid = threadIdx.x;
    float4 v0 = *(const float4*)(xr + tid * 4);
    float4 v1 = *(const float4*)(xr + 1024 + tid * 4);
    float s = v0.x * v0.x + v0.y * v0.y + v0.z * v0.z + v0.w * v0.w
            + v1.x * v1.x + v1.y * v1.y + v1.z * v1.z + v1.w * v1.w;
    red[tid] = s;
    __syncthreads();
    for (int st = 128; st > 0; st >>= 1) {
        if (tid < st) red[tid] += red[tid + st];
        __syncthreads();
    }
    float inv = rsqrtf(red[0] * (1.f / HID) + EPS_RMS);

    float4 w0 = *(const float4*)(w + tid * 4);
    float4 w1 = *(const float4*)(w + 1024 + tid * 4);
    float o[8];
    o[0] = v0.x * inv * w0.x; o[1] = v0.y * inv * w0.y;
    o[2] = v0.z * inv * w0.z; o[3] = v0.w * inv * w0.w;
    o[4] = v1.x * inv * w1.x; o[5] = v1.y * inv * w1.y;
    o[6] = v1.z * inv * w1.z; o[7] = v1.w * inv * w1.w;
    float* yr = y + row * HID;
    *(float4*)(yr + tid * 4) = make_float4(o[0], o[1], o[2], o[3]);
    *(float4*)(yr + 1024 + tid * 4) = make_float4(o[4], o[5], o[6], o[7]);
    bf16* yhr = yh + row * HID;
    bf16* ylr = yl + row * HID;
    #pragma unroll
    for (int g = 0; g < 2; g++) {
        bf16 h0, l0, h1, l1, h2, l2, h3, l3;
        split_bf16(o[g * 4 + 0], h0, l0);
        split_bf16(o[g * 4 + 1], h1, l1);
        split_bf16(o[g * 4 + 2], h2, l2);
        split_bf16(o[g * 4 + 3], h3, l3);
        int off = g * 1024 + tid * 4;
        *(uint32_t*)(yhr + off)     = pack_bf16x2(h0, h1);
        *(uint32_t*)(yhr + off + 2) = pack_bf16x2(h2, h3);
        *(uint32_t*)(ylr + off)     = pack_bf16x2(l0, l1);
        *(uint32_t*)(ylr + off + 2) = pack_bf16x2(l2, l3);
    }
}

// ---------------- host ----------------
static void* sym(const void* s) {
    void* p = nullptr;
    cudaGetSymbolAddress(&p, s);
    return p;
}

extern "C" void kernel_launch(void* const* d_in, const int* in_sizes, int n_in,
                              void* d_out, int out_size)
{
    const float* h_in = (const float*)d_in[0];
    const float* Wup  = (const float*)d_in[1];
    const float* bup  = (const float*)d_in[2];
    const float* anw  = (const float*)d_in[3];
    const float* Wq   = (const float*)d_in[4];
    const float* Wk   = (const float*)d_in[5];
    const float* Wv   = (const float*)d_in[6];
    const float* Wo   = (const float*)d_in[7];
    const float* mnw  = (const float*)d_in[8];
    const float* Wg   = (const float*)d_in[9];
    const float* Wu   = (const float*)d_in[10];
    const float* Wd   = (const float*)d_in[11];
    float* out = (float*)d_out;

    float* up_   = (float*)sym(g_up);
    float* x1_   = (float*)sym(g_x1);
    float* x2_   = (float*)sym(g_x2);
    float* x3_   = (float*)sym(g_x3);
    float* v_    = (float*)sym(g_v);
    float* gate_ = (float*)sym(g_gate);

    bf16 *hh = (bf16*)sym(b_h_hi),  *hl = (bf16*)sym(b_h_lo);
    bf16 *hth = (bf16*)sym(b_ht_hi), *htl = (bf16*)sym(b_ht_lo);
    bf16 *wuph = (bf16*)sym(b_wup_hi), *wupl = (bf16*)sym(b_wup_lo);
    bf16 *wqh = (bf16*)sym(b_wq_hi), *wql = (bf16*)sym(b_wq_lo);
    bf16 *wkh = (bf16*)sym(b_wk_hi), *wkl = (bf16*)sym(b_wk_lo);
    bf16 *wvh = (bf16*)sym(b_wv_hi), *wvl = (bf16*)sym(b_wv_lo);
    bf16 *woh = (bf16*)sym(b_wo_hi), *wol = (bf16*)sym(b_wo_lo);
    bf16 *wgh = (bf16*)sym(b_wg_hi), *wgl = (bf16*)sym(b_wg_lo);
    bf16 *wuh = (bf16*)sym(b_wu_hi), *wul = (bf16*)sym(b_wu_lo);
    bf16 *wdh = (bf16*)sym(b_wd_hi), *wdl = (bf16*)sym(b_wd_lo);
    bf16 *uph = (bf16*)sym(b_up_hi), *upl = (bf16*)sym(b_up_lo);
    bf16 *x1h = (bf16*)sym(b_x1_hi), *x1l = (bf16*)sym(b_x1_lo);
    bf16 *x3h = (bf16*)sym(b_x3_hi), *x3l = (bf16*)sym(b_x3_lo);
    bf16 *qh = (bf16*)sym(b_q_hi),   *ql = (bf16*)sym(b_q_lo);
    bf16 *kh = (bf16*)sym(b_k_hi),   *kl = (bf16*)sym(b_k_lo);
    bf16 *oh = (bf16*)sym(b_o_hi),   *ol = (bf16*)sym(b_o_lo);
    bf16 *vth = (bf16*)sym(b_vt_hi), *vtl = (bf16*)sym(b_vt_lo);
    bf16 *ubh = (bf16*)sym(b_ub_hi), *ubl = (bf16*)sym(b_ub_lo);

    const int SMEM128 = 1024 + 3 * (128 * 128 + 128 * 128);  // 99328
    const int SMEMFA  = 32768 + 2 * 65536;                    // 163840
    cudaFuncSetAttribute(mma_gemm<128>, cudaFuncAttributeMaxDynamicSharedMemorySize, SMEM128);
    cudaFuncSetAttribute(flash_attn, cudaFuncAttributeMaxDynamicSharedMemorySize, SMEMFA);

    dim3 blk(256);

    auto conv = [&](const float* x, bf16* hi, bf16* lo, long long n) {
        long long n4 = n / 4;
        conv_split<<<(unsigned)((n4 + 255) / 256), blk>>>(x, hi, lo, n4);
    };
    conv(h_in, hh, hl, HB);
    conv(Wup, wuph, wupl, WUPN);
    conv(Wq, wqh, wql, W1N);
    conv(Wk, wkh, wkl, W1N);
    conv(Wv, wvh, wvl, W1N);
    conv(Wo, woh, wol, W1N);
    conv(Wg, wgh, wgl, W2N);
    conv(Wu, wuh, wul, W2N);
    conv(Wd, wdh, wdl, W2N);

    // h [S,H] -> hT [H,S] per batch
    transpose_split<<<dim3(HID / 32, S_LEN / 32, BATCH), blk>>>(
        h_in, HID, S_H, 0, hth, htl, S_LEN, S_H, 0, 1);

    // 1) up = Wup @ h (+bias)
    mma_gemm<128><<<dim3(HID / 128, SU_LEN / 128, BATCH), blk, SMEM128>>>(
        wuph, wupl, S_LEN, 0, 0,
        hth, htl, S_LEN, S_H, 0,
        up_, uph, upl, HID, SU_H, 0,
        bup, nullptr, 0, 0, 0, nullptr,
        S_LEN, 1.f, 1);

    // 2) x1 = rmsnorm(up)
    rmsnorm_split<<<BATCH * SU_LEN, blk>>>(up_, anw, x1_, x1h, x1l);

    // 3) q = x1 @ Wq^T
    mma_gemm<128><<<dim3(HID / 128, SU_LEN / 128, BATCH), blk, SMEM128>>>(
        x1h, x1l, HID, SU_H, 0,
        wqh, wql, HID, 0, 0,
        nullptr, qh, ql, HID, SU_H, 0,
        nullptr, nullptr, 0, 0, 0, nullptr,
        HID, 1.f, 1);

    // 4) k = [h; up] @ Wk^T
    mma_gemm<128><<<dim3(HID / 128, S_LEN / 128, BATCH), blk, SMEM128>>>(
        hh, hl, HID, S_H, 0,
        wkh, wkl, HID, 0, 0,
        nullptr, kh, kl, HID, T_H, 0,
        nullptr, nullptr, 0, 0, 0, nullptr,
        HID, 1.f, 1);
    mma_gemm<128><<<dim3(HID / 128, SU_LEN / 128, BATCH), blk, SMEM128>>>(
        uph, upl, HID, SU_H, 0,
        wkh, wkl, HID, 0, 0,
        nullptr, kh + (long long)S_LEN * HID, kl + (long long)S_LEN * HID, HID, T_H, 0,
        nullptr, nullptr, 0, 0, 0, nullptr,
        HID, 1.f, 1);

    // 5) v = [h; up] @ Wv^T (fp32) then transpose+split to [b,h,d,t]
    mma_gemm<128><<<dim3(HID / 128, S_LEN / 128, BATCH), blk, SMEM128>>>(
        hh, hl, HID, S_H, 0,
        wvh, wvl, HID, 0, 0,
        v_, nullptr, nullptr, HID, T_H, 0,
        nullptr, nullptr, 0, 0, 0, nullptr,
        HID, 1.f, 1);
    mma_gemm<128><<<dim3(HID / 128, SU_LEN / 128, BATCH), blk, SMEM128>>>(
        uph, upl, HID, SU_H, 0,
        wvh, wvl, HID, 0, 0,
        v_ + (long long)S_LEN * HID, nullptr, nullptr, HID, T_H, 0,
        nullptr, nullptr, 0, 0, 0, nullptr,
        HID, 1.f, 1);
    transpose_split<<<dim3(HDIM / 32, T_LEN / 32, BATCH * NHEAD), blk>>>(
        v_, HID, T_H, HDIM,
        vth, vtl, T_LEN, T_H, (long long)HDIM * T_LEN, NHEAD);

    // 6-8) fused flash attention -> o hi/lo
    flash_attn<<<dim3(SU_LEN / 128, BATCH * NHEAD), blk, SMEMFA>>>(
        qh, ql, kh, kl, vth, vtl, oh, ol);

    // 9) x2 = o @ Wo^T + x1
    mma_gemm<128><<<dim3(HID / 128, SU_LEN / 128, BATCH), blk, SMEM128>>>(
        oh, ol, HID, SU_H, 0,
        woh, wol, HID, 0, 0,
        x2_, nullptr, nullptr, HID, SU_H, 0,
        nullptr, x1_, HID, SU_H, 0, nullptr,
        HID, 1.f, 1);

    // 10) x3 = rmsnorm(x2)
    rmsnorm_split<<<BATCH * SU_LEN, blk>>>(x2_, mnw, x3_, x3h, x3l);

    // 11) gate = x3 @ Wg^T (fp32)
    mma_gemm<128><<<dim3(INTER / 128, SU_LEN / 128, BATCH), blk, SMEM128>>>(
        x3h, x3l, HID, SU_H, 0,
        wgh, wgl, HID, 0, 0,
        gate_, nullptr, nullptr, INTER, SU_I, 0,
        nullptr, nullptr, 0, 0, 0, nullptr,
        HID, 1.f, 1);

    // 12) ub = silu(gate) * (x3 @ Wu^T) -> bf16 hi/lo (fused epilogue)
    mma_gemm<128><<<dim3(INTER / 128, SU_LEN / 128, BATCH), blk, SMEM128>>>(
        x3h, x3l, HID, SU_H, 0,
        wuh, wul, HID, 0, 0,
        nullptr, ubh, ubl, INTER, SU_I, 0,
        nullptr, nullptr, 0, 0, 0, gate_,
        HID, 1.f, 1);

    // 13) out = ub @ Wd^T + x3
    mma_gemm<128><<<dim3(HID / 128, SU_LEN / 128, BATCH), blk, SMEM128>>>(
        ubh, ubl, INTER, SU_I, 0,
        wdh, wdl, INTER, 0, 0,
        out, nullptr, nullptr, HID, SU_H, 0,
        nullptr, x3_, HID, SU_H, 0, nullptr,
        INTER, 1.f, 1);
}

// round 5
// speedup vs baseline: 3.0127x; 1.4217x over previous
#include <cuda_runtime.h>
#include <cuda_fp16.h>
#include <cstdint>

// ---------------- problem constants ----------------
#define BATCH 2
#define S_LEN 512
#define HID 2048
#define NHEAD 32
#define HDIM 64
#define SU_LEN 1024
#define T_LEN 1536
#define INTER 5632
#define EPS_RMS 1e-6f

#define S_H   (S_LEN * HID)
#define SU_H  (SU_LEN * HID)
#define T_H   (T_LEN * HID)
#define SU_I  ((long long)SU_LEN * INTER)

#define HB  (BATCH * S_LEN * HID)
#define XB  (BATCH * SU_LEN * HID)
#define KBN (BATCH * T_LEN * HID)
#define UBB ((long long)BATCH * SU_LEN * INTER)
#define WUPN (SU_LEN * S_LEN)
#define W1N  (HID * HID)
#define W2N  (INTER * HID)

typedef __half hf;

// ---------------- scratch (device globals; no runtime allocation) ----------------
__device__ float g_up  [XB];
__device__ float g_x1  [XB];
__device__ float g_x2  [XB];
__device__ float g_x3  [XB];
__device__ float g_v   [KBN];
__device__ float g_gate[UBB];

__device__ hf f_h_hi[HB],  f_h_lo[HB];
__device__ hf f_ht_hi[HB], f_ht_lo[HB];
__device__ hf f_wup[WUPN];
__device__ hf f_wq[W1N];
__device__ hf f_wk[W1N];
__device__ hf f_wv[W1N];
__device__ hf f_wo[W1N];
__device__ hf f_wg[W2N];
__device__ hf f_wu[W2N];
__device__ hf f_wd[W2N];
__device__ hf f_up_hi[XB], f_up_lo[XB];
__device__ hf f_x1_hi[XB], f_x1_lo[XB];
__device__ hf f_x3_hi[XB], f_x3_lo[XB];
__device__ hf f_q_hi[XB],  f_q_lo[XB];
__device__ hf f_k_hi[KBN];
__device__ hf f_o_hi[XB],  f_o_lo[XB];
__device__ hf f_vt_hi[KBN];
__device__ hf f_ub_hi[UBB], f_ub_lo[UBB];

// ---------------- PTX helpers ----------------
__device__ __forceinline__ uint32_t smem_u32(const void* p) {
    uint32_t a;
    asm("{ .reg .u64 t; cvta.to.shared.u64 t, %1; cvt.u32.u64 %0, t; }" : "=r"(a) : "l"(p));
    return a;
}
#define SWZ(off) ((off) ^ (((off) >> 3) & 0x70))

#define CP_ASYNC16(dst, src) \
    asm volatile("cp.async.cg.shared.global [%0], [%1], 16;" :: "r"(dst), "l"(src) : "memory")
#define CP_COMMIT() asm volatile("cp.async.commit_group;" ::: "memory")
__device__ __forceinline__ void cp_wait(int allow) {
    if (allow) asm volatile("cp.async.wait_group 1;" ::: "memory");
    else       asm volatile("cp.async.wait_group 0;" ::: "memory");
}

__device__ __forceinline__ void ldmx4(uint32_t* r, uint32_t addr) {
    asm volatile("ldmatrix.sync.aligned.m8n8.x4.shared.b16 {%0,%1,%2,%3}, [%4];"
        : "=r"(r[0]), "=r"(r[1]), "=r"(r[2]), "=r"(r[3]) : "r"(addr));
}

__device__ __forceinline__ void mma_f16(float* d, const uint32_t* a, uint32_t b0, uint32_t b1) {
    asm volatile("mma.sync.aligned.m16n8k16.row.col.f32.f16.f16.f32 "
        "{%0,%1,%2,%3}, {%4,%5,%6,%7}, {%8,%9}, {%0,%1,%2,%3};"
        : "+f"(d[0]), "+f"(d[1]), "+f"(d[2]), "+f"(d[3])
        : "r"(a[0]), "r"(a[1]), "r"(a[2]), "r"(a[3]), "r"(b0), "r"(b1));
}

__device__ __forceinline__ void split_f16(float v, hf& hi, hf& lo) {
    hi = __float2half(v);
    lo = __float2half(v - __half2float(hi));
}
__device__ __forceinline__ uint32_t pack_f16x2(hf a, hf b) {
    __half2 t;
    t.x = a; t.y = b;
    return *(uint32_t*)&t;
}

// ---------------- mma.sync GEMM (fp16, 2-pass one-sided compensation) ----------------
// C[m,n] = alpha * (Ah·Bh + (Al?Al:Ah)·(Al?Bh:Bl))  (+bias) (+resid) (silu-gate)
// Exactly one of Al / Bl is non-null.
template<int BN>
__global__ __launch_bounds__(256, 2) void mma_gemm(
    const hf* __restrict__ Ah, const hf* __restrict__ Al,
    int lda, long long sA1, long long sA2,
    const hf* __restrict__ Bh, const hf* __restrict__ Bl,
    int ldb, long long sB1, long long sB2,
    float* __restrict__ C, hf* __restrict__ Chi, hf* __restrict__ Clo,
    int ldc, long long sC1, long long sC2,
    const float* __restrict__ bias,
    const float* __restrict__ resid, int ldr, long long sR1, long long sR2,
    const float* __restrict__ gate,
    int K, float alpha, int batch2)
{
    extern __shared__ char smem[];
    const uint32_t sbase = smem_u32(smem);
    const uint32_t tiles = (sbase + 1023u) & ~1023u;
    constexpr int ASZ = 128 * 128;
    constexpr int BSZ = BN * 128;
    constexpr int STG = ASZ + BSZ;
    constexpr int NT8 = BN / 16;
    constexpr int NG  = BN / 32;

    const int tid = threadIdx.x, wid = tid >> 5, lane = tid & 31;
    const int z = blockIdx.z, z1 = z / batch2, z2 = z - z1 * batch2;
    const long long aOff = (long long)z1 * sA1 + (long long)z2 * sA2;
    const long long bOff = (long long)z1 * sB1 + (long long)z2 * sB2;
    const long long cOff = (long long)z1 * sC1 + (long long)z2 * sC2;
    Ah += aOff; Bh += bOff;
    if (Al) Al += aOff;
    if (Bl) Bl += bOff;
    const int m0 = blockIdx.y * 128, n0 = blockIdx.x * BN;
    const int m0w = (wid & 3) * 32;
    const int n0w = (wid >> 2) * (BN / 2);

    const int kc = K >> 6;
    const int nc = 2 * kc;

    auto load_chunk = [&](int c, int s) {
        const int seg = c / kc, kk = c - seg * kc;
        const hf* A = (seg == 1 && Al) ? Al : Ah;
        const hf* B = (seg == 1 && Bl) ? Bl : Bh;
        const int k0 = kk << 6;
        const uint32_t aB = tiles + s * STG;
        const uint32_t bB = aB + ASZ;
        const int NU = 1024 + BN * 8;
        for (int u = tid; u < NU; u += 256) {
            if (u < 1024) {
                int r = u >> 3, g = u & 7;
                CP_ASYNC16(aB + SWZ(r * 128 + g * 16),
                           A + (long long)(m0 + r) * lda + k0 + g * 8);
            } else {
                int u2 = u - 1024;
                int r = u2 >> 3, g = u2 & 7;
                CP_ASYNC16(bB + SWZ(r * 128 + g * 16),
                           B + (long long)(n0 + r) * ldb + k0 + g * 8);
            }
        }
        CP_COMMIT();
    };

    float acc[2][NT8][4];
    #pragma unroll
    for (int i = 0; i < 2; i++)
        #pragma unroll
        for (int j = 0; j < NT8; j++)
            #pragma unroll
            for (int q = 0; q < 4; q++) acc[i][j][q] = 0.f;

    load_chunk(0, 0);
    if (nc > 1) load_chunk(1, 1);

    const int lrow = lane & 15;
    const int lcol = (lane >> 4) * 16;

    for (int c = 0; c < nc; c++) {
        const int s = c % 3;
        cp_wait(c + 1 < nc ? 1 : 0);
        __syncthreads();
        if (c + 2 < nc) load_chunk(c + 2, (c + 2) % 3);

        const uint32_t aSt = tiles + s * STG;
        const uint32_t bSt = aSt + ASZ;
        #pragma unroll
        for (int ks = 0; ks < 4; ks++) {
            uint32_t ra[2][4];
            #pragma unroll
            for (int mt = 0; mt < 2; mt++)
                ldmx4(ra[mt], aSt + SWZ((m0w + mt * 16 + lrow) * 128 + ks * 32 + lcol));
            uint32_t rb[NG][4];
            #pragma unroll
            for (int ng = 0; ng < NG; ng++)
                ldmx4(rb[ng], bSt + SWZ((n0w + ng * 16 + lrow) * 128 + ks * 32 + lcol));
            #pragma unroll
            for (int mt = 0; mt < 2; mt++)
                #pragma unroll
                for (int ng = 0; ng < NG; ng++) {
                    mma_f16(acc[mt][2 * ng],     ra[mt], rb[ng][0], rb[ng][2]);
                    mma_f16(acc[mt][2 * ng + 1], ra[mt], rb[ng][1], rb[ng][3]);
                }
        }
        __syncthreads();
    }

    const int rq = lane >> 2;
    const int cq = (lane & 3) * 2;
    #pragma unroll
    for (int mt = 0; mt < 2; mt++) {
        #pragma unroll
        for (int half = 0; half < 2; half++) {
            const int m = m0 + m0w + mt * 16 + rq + half * 8;
            const float bv = bias ? bias[m] : 0.f;
            const long long cBase = cOff + (long long)m * ldc + n0 + n0w;
            const long long rBase = resid ? ((long long)z1 * sR1 + (long long)z2 * sR2 +
                                             (long long)m * ldr + n0 + n0w) : 0;
            #pragma unroll
            for (int nt = 0; nt < NT8; nt++) {
                float v0 = acc[mt][nt][half * 2]     * alpha + bv;
                float v1 = acc[mt][nt][half * 2 + 1] * alpha + bv;
                const int cn = nt * 8 + cq;
                if (resid) {
                    v0 += resid[rBase + cn];
                    v1 += resid[rBase + cn + 1];
                }
                if (gate) {
                    float g0 = gate[cBase + cn];
                    float g1 = gate[cBase + cn + 1];
                    v0 *= g0 / (1.f + __expf(-g0));
                    v1 *= g1 / (1.f + __expf(-g1));
                }
                if (C)
                    *(float2*)(C + cBase + cn) = make_float2(v0, v1);
                if (Chi) {
                    hf h0, l0, h1, l1;
                    split_f16(v0, h0, l0);
                    split_f16(v1, h1, l1);
                    *(uint32_t*)(Chi + cBase + cn) = pack_f16x2(h0, h1);
                    if (Clo)
                        *(uint32_t*)(Clo + cBase + cn) = pack_f16x2(l0, l1);
                }
            }
        }
    }
}

// ---------------- fused flash attention (fp16, 2-pass) ----------------
// grid: (SU/128, BATCH*NHEAD). 8 warps, each warp owns 16 q rows.
#define FA_NI (T_LEN / 128)   // 12

__global__ __launch_bounds__(256, 1) void flash_attn(
    const hf* __restrict__ gqh, const hf* __restrict__ gql,
    const hf* __restrict__ gkh,
    const hf* __restrict__ gvh,
    hf* __restrict__ goh, hf* __restrict__ gol)
{
    extern __shared__ char smem[];
    const uint32_t sb0 = smem_u32(smem);
    const uint32_t sb = (sb0 + 1023u) & ~1023u;
    const uint32_t Qh = sb, Ql = sb + 16384;
    const uint32_t ST0 = sb + 32768;
    const uint32_t STSZ = 32768;   // per stage: Kh 16K, Vh 16K

    const int tid = threadIdx.x, wid = tid >> 5, lane = tid & 31;
    const int q0 = blockIdx.x * 128;
    const int bh = blockIdx.y;
    const int b = bh >> 5, head = bh & 31;

    const hf* qhp = gqh + (long long)b * SU_H + head * HDIM;
    const hf* qlp = gql + (long long)b * SU_H + head * HDIM;
    const hf* khp = gkh + (long long)b * T_H + head * HDIM;
    const hf* vhp = gvh + (long long)b * T_H + (long long)head * HDIM * T_LEN;

    // load Q (once)
    for (int u = tid; u < 2048; u += 256) {
        int comp = u >> 10, r = (u >> 3) & 127, g = u & 7;
        const hf* src = (comp ? qlp : qhp) + (long long)(q0 + r) * HID + g * 8;
        CP_ASYNC16((comp ? Ql : Qh) + SWZ(r * 128 + g * 16), src);
    }
    CP_COMMIT();

    auto loadkv = [&](int ci, int s) {
        const int t0 = ci * 128;
        const uint32_t stb = ST0 + s * STSZ;
        for (int u = tid; u < 2048; u += 256) {
            if (u < 1024) {
                int r = u >> 3, g = u & 7;
                CP_ASYNC16(stb + SWZ(r * 128 + g * 16),
                           khp + (long long)(t0 + r) * HID + g * 8);
            } else {
                int u2 = u - 1024;
                int d = u2 >> 4, gg = u2 & 15;     // 16 groups of 8 over 128 t cols
                CP_ASYNC16(stb + 16384 + (gg >> 3) * 8192 + SWZ(d * 128 + (gg & 7) * 16),
                           vhp + (long long)d * T_LEN + t0 + gg * 8);
            }
        }
        CP_COMMIT();
    };

    loadkv(0, 0);
    loadkv(1, 1);
    cp_wait(1);              // Q + chunk0 ready
    __syncthreads();

    const int lrow = lane & 15, lcol = (lane >> 4) * 16;
    const int mrow = wid * 16;
    uint32_t qf[2][4][4];
    #pragma unroll
    for (int ks = 0; ks < 4; ks++) {
        ldmx4(qf[0][ks], Qh + SWZ((mrow + lrow) * 128 + ks * 32 + lcol));
        ldmx4(qf[1][ks], Ql + SWZ((mrow + lrow) * 128 + ks * 32 + lcol));
    }

    float oacc[8][4];
    #pragma unroll
    for (int i = 0; i < 8; i++)
        #pragma unroll
        for (int j = 0; j < 4; j++) oacc[i][j] = 0.f;
    float M0 = -1e30f, M1 = -1e30f, L0 = 0.f, L1 = 0.f;

    for (int i = 0; i < FA_NI; i++) {
        const uint32_t stb = ST0 + (i & 1) * STSZ;
        if (i > 0) { cp_wait(i + 1 < FA_NI ? 1 : 0); __syncthreads(); }

        // ---- S = Qh K^T + Ql K^T ----
        float sacc[16][4];
        #pragma unroll
        for (int t = 0; t < 16; t++)
            #pragma unroll
            for (int j = 0; j < 4; j++) sacc[t][j] = 0.f;

        #pragma unroll
        for (int p = 0; p < 2; p++) {
            #pragma unroll
            for (int ks = 0; ks < 4; ks++) {
                #pragma unroll
                for (int ng = 0; ng < 8; ng++) {
                    uint32_t rb[4];
                    ldmx4(rb, stb + SWZ((ng * 16 + lrow) * 128 + ks * 32 + lcol));
                    mma_f16(sacc[2 * ng],     qf[p][ks], rb[0], rb[2]);
                    mma_f16(sacc[2 * ng + 1], qf[p][ks], rb[1], rb[3]);
                }
            }
        }

        // ---- online softmax ----
        float mx0 = -1e30f, mx1 = -1e30f;
        #pragma unroll
        for (int t = 0; t < 16; t++) {
            sacc[t][0] *= 0.125f; sacc[t][1] *= 0.125f;
            sacc[t][2] *= 0.125f; sacc[t][3] *= 0.125f;
            mx0 = fmaxf(mx0, fmaxf(sacc[t][0], sacc[t][1]));
            mx1 = fmaxf(mx1, fmaxf(sacc[t][2], sacc[t][3]));
        }
        mx0 = fmaxf(mx0, __shfl_xor_sync(0xFFFFFFFFu, mx0, 1));
        mx0 = fmaxf(mx0, __shfl_xor_sync(0xFFFFFFFFu, mx0, 2));
        mx1 = fmaxf(mx1, __shfl_xor_sync(0xFFFFFFFFu, mx1, 1));
        mx1 = fmaxf(mx1, __shfl_xor_sync(0xFFFFFFFFu, mx1, 2));
        const float Mn0 = fmaxf(M0, mx0), Mn1 = fmaxf(M1, mx1);
        const float al0 = __expf(M0 - Mn0), al1 = __expf(M1 - Mn1);
        M0 = Mn0; M1 = Mn1;

        float s0 = 0.f, s1 = 0.f;
        #pragma unroll
        for (int t = 0; t < 16; t++) {
            sacc[t][0] = __expf(sacc[t][0] - M0); s0 += sacc[t][0];
            sacc[t][1] = __expf(sacc[t][1] - M0); s0 += sacc[t][1];
            sacc[t][2] = __expf(sacc[t][2] - M1); s1 += sacc[t][2];
            sacc[t][3] = __expf(sacc[t][3] - M1); s1 += sacc[t][3];
        }
        s0 += __shfl_xor_sync(0xFFFFFFFFu, s0, 1);
        s0 += __shfl_xor_sync(0xFFFFFFFFu, s0, 2);
        s1 += __shfl_xor_sync(0xFFFFFFFFu, s1, 1);
        s1 += __shfl_xor_sync(0xFFFFFFFFu, s1, 2);
        L0 = L0 * al0 + s0;
        L1 = L1 * al1 + s1;
        #pragma unroll
        for (int t = 0; t < 8; t++) {
            oacc[t][0] *= al0; oacc[t][1] *= al0;
            oacc[t][2] *= al1; oacc[t][3] *= al1;
        }

        // ---- O += Ph V + Pl V ----
        const uint32_t vb = stb + 16384;
        #pragma unroll
        for (int ks = 0; ks < 8; ks++) {
            float p0 = sacc[2 * ks][0],     p1 = sacc[2 * ks][1];
            float p2 = sacc[2 * ks][2],     p3 = sacc[2 * ks][3];
            float p4 = sacc[2 * ks + 1][0], p5 = sacc[2 * ks + 1][1];
            float p6 = sacc[2 * ks + 1][2], p7 = sacc[2 * ks + 1][3];
            hf h0, l0, h1, l1, h2, l2, h3, l3, h4, l4, h5, l5, h6, l6, h7, l7;
            split_f16(p0, h0, l0); split_f16(p1, h1, l1);
            split_f16(p2, h2, l2); split_f16(p3, h3, l3);
            split_f16(p4, h4, l4); split_f16(p5, h5, l5);
            split_f16(p6, h6, l6); split_f16(p7, h7, l7);
            uint32_t ah[4], alr[4];
            ah[0] = pack_f16x2(h0, h1);  ah[1] = pack_f16x2(h2, h3);
            ah[2] = pack_f16x2(h4, h5);  ah[3] = pack_f16x2(h6, h7);
            alr[0] = pack_f16x2(l0, l1); alr[1] = pack_f16x2(l2, l3);
            alr[2] = pack_f16x2(l4, l5); alr[3] = pack_f16x2(l6, l7);

            const uint32_t vhb = vb + (ks >> 2) * 8192;
            const int ksl = ks & 3;
            #pragma unroll
            for (int ng = 0; ng < 4; ng++) {
                uint32_t rb[4];
                ldmx4(rb, vhb + SWZ((ng * 16 + lrow) * 128 + ksl * 32 + lcol));
                mma_f16(oacc[2 * ng],     ah,  rb[0], rb[2]);
                mma_f16(oacc[2 * ng + 1], ah,  rb[1], rb[3]);
                mma_f16(oacc[2 * ng],     alr, rb[0], rb[2]);
                mma_f16(oacc[2 * ng + 1], alr, rb[1], rb[3]);
            }
        }

        __syncthreads();
        if (i + 2 < FA_NI) loadkv(i + 2, i & 1);
    }

    // ---- epilogue ----
    const float inv0 = 1.f / L0, inv1 = 1.f / L1;
    const int rq = lane >> 2, cq = (lane & 3) * 2;
    const long long base0 = (long long)b * SU_H + (long long)(q0 + mrow + rq) * HID + head * HDIM;
    const long long base1 = base0 + 8LL * HID;
    #pragma unroll
    for (int nt = 0; nt < 8; nt++) {
        const int cn = nt * 8 + cq;
        float v0 = oacc[nt][0] * inv0, v1 = oacc[nt][1] * inv0;
        float v2 = oacc[nt][2] * inv1, v3 = oacc[nt][3] * inv1;
        hf h0, l0, h1, l1, h2, l2, h3, l3;
        split_f16(v0, h0, l0); split_f16(v1, h1, l1);
        split_f16(v2, h2, l2); split_f16(v3, h3, l3);
        *(uint32_t*)(goh + base0 + cn) = pack_f16x2(h0, h1);
        *(uint32_t*)(gol + base0 + cn) = pack_f16x2(l0, l1);
        *(uint32_t*)(goh + base1 + cn) = pack_f16x2(h2, h3);
        *(uint32_t*)(gol + base1 + cn) = pack_f16x2(l2, l3);
    }
}

// ---------------- conversions ----------------
__global__ __launch_bounds__(256) void conv_split2(const float* __restrict__ x,
                                                   hf* __restrict__ hi, hf* __restrict__ lo,
                                                   long long n4)
{
    long long i = (long long)blockIdx.x * 256 + threadIdx.x;
    if (i >= n4) return;
    float4 v = ((const float4*)x)[i];
    hf h0, l0, h1, l1, h2, l2, h3, l3;
    split_f16(v.x, h0, l0); split_f16(v.y, h1, l1);
    split_f16(v.z, h2, l2); split_f16(v.w, h3, l3);
    ((uint32_t*)hi)[i * 2]     = pack_f16x2(h0, h1);
    ((uint32_t*)hi)[i * 2 + 1] = pack_f16x2(h2, h3);
    ((uint32_t*)lo)[i * 2]     = pack_f16x2(l0, l1);
    ((uint32_t*)lo)[i * 2 + 1] = pack_f16x2(l2, l3);
}

__global__ __launch_bounds__(256) void conv_hi(const float* __restrict__ x,
                                               hf* __restrict__ hi, long long n4)
{
    long long i = (long long)blockIdx.x * 256 + threadIdx.x;
    if (i >= n4) return;
    float4 v = ((const float4*)x)[i];
    ((uint32_t*)hi)[i * 2]     = pack_f16x2(__float2half(v.x), __float2half(v.y));
    ((uint32_t*)hi)[i * 2 + 1] = pack_f16x2(__float2half(v.z), __float2half(v.w));
}

// ---------------- transpose variants ----------------
__global__ __launch_bounds__(256) void transpose_split2(
    const float* __restrict__ in, int ldi, long long sI1, long long sI2,
    hf* __restrict__ oh, hf* __restrict__ ol, int ldo, long long sO1, long long sO2,
    int batch2)
{
    __shared__ float t[32][33];
    int z = blockIdx.z, z1 = z / batch2, z2 = z - z1 * batch2;
    in += (long long)z1 * sI1 + (long long)z2 * sI2;
    long long oOff = (long long)z1 * sO1 + (long long)z2 * sO2;
    int r0 = blockIdx.y * 32, c0 = blockIdx.x * 32;
    int tx = threadIdx.x & 31, ty8 = threadIdx.x >> 5;
    #pragma unroll
    for (int i = 0; i < 4; i++) {
        int ty = ty8 + i * 8;
        t[ty][tx] = in[(long long)(r0 + ty) * ldi + c0 + tx];
    }
    __syncthreads();
    #pragma unroll
    for (int i = 0; i < 4; i++) {
        int oy = ty8 + i * 8;
        float v = t[tx][oy];
        hf h, l;
        split_f16(v, h, l);
        long long idx = oOff + (long long)(c0 + oy) * ldo + r0 + tx;
        oh[idx] = h;
        if (ol) ol[idx] = l;
    }
}

// ---------------- rmsnorm + split ----------------
__global__ __launch_bounds__(256) void rmsnorm_split(
    const float* __restrict__ x, const float* __restrict__ w,
    float* __restrict__ y, hf* __restrict__ yh, hf* __restrict__ yl)
{
    __shared__ float red[256];
    long long row = blockIdx.x;
    const float* xr = x + row * HID;
    int tid = threadIdx.x;
    float4 v0 = *(const float4*)(xr + tid * 4);
    float4 v1 = *(const float4*)(xr + 1024 + tid * 4);
    float s = v0.x * v0.x + v0.y * v0.y + v0.z * v0.z + v0.w * v0.w
            + v1.x * v1.x + v1.y * v1.y + v1.z * v1.z + v1.w * v1.w;
    red[tid] = s;
    __syncthreads();
    for (int st = 128; st > 0; st >>= 1) {
        if (tid < st) red[tid] += red[tid + st];
        __syncthreads();
    }
    float inv = rsqrtf(red[0] * (1.f / HID) + EPS_RMS);

    float4 w0 = *(const float4*)(w + tid * 4);
    float4 w1 = *(const float4*)(w + 1024 + tid * 4);
    float o[8];
    o[0] = v0.x * inv * w0.x; o[1] = v0.y * inv * w0.y;
    o[2] = v0.z * inv * w0.z; o[3] = v0.w * inv * w0.w;
    o[4] = v1.x * inv * w1.x; o[5] = v1.y * inv * w1.y;
    o[6] = v1.z * inv * w1.z; o[7] = v1.w * inv * w1.w;
    float* yr = y + row * HID;
    *(float4*)(yr + tid * 4) = make_float4(o[0], o[1], o[2], o[3]);
    *(float4*)(yr + 1024 + tid * 4) = make_float4(o[4], o[5], o[6], o[7]);
    hf* yhr = yh + row * HID;
    hf* ylr = yl + row * HID;
    #pragma unroll
    for (int g = 0; g < 2; g++) {
        hf h0, l0, h1, l1, h2, l2, h3, l3;
        split_f16(o[g * 4 + 0], h0, l0);
        split_f16(o[g * 4 + 1], h1, l1);
        split_f16(o[g * 4 + 2], h2, l2);
        split_f16(o[g * 4 + 3], h3, l3);
        int off = g * 1024 + tid * 4;
        *(uint32_t*)(yhr + off)     = pack_f16x2(h0, h1);
        *(uint32_t*)(yhr + off + 2) = pack_f16x2(h2, h3);
        *(uint32_t*)(ylr + off)     = pack_f16x2(l0, l1);
        *(uint32_t*)(ylr + off + 2) = pack_f16x2(l2, l3);
    }
}

// ---------------- host ----------------
static void* sym(const void* s) {
    void* p = nullptr;
    cudaGetSymbolAddress(&p, s);
    return p;
}

extern "C" void kernel_launch(void* const* d_in, const int* in_sizes, int n_in,
                              void* d_out, int out_size)
{
    const float* h_in = (const float*)d_in[0];
    const float* Wup  = (const float*)d_in[1];
    const float* bup  = (const float*)d_in[2];
    const float* anw  = (const float*)d_in[3];
    const float* Wq   = (const float*)d_in[4];
    const float* Wk   = (const float*)d_in[5];
    const float* Wv   = (const float*)d_in[6];
    const float* Wo   = (const float*)d_in[7];
    const float* mnw  = (const float*)d_in[8];
    const float* Wg   = (const float*)d_in[9];
    const float* Wu   = (const float*)d_in[10];
    const float* Wd   = (const float*)d_in[11];
    float* out = (float*)d_out;

    float* up_   = (float*)sym(g_up);
    float* x1_   = (float*)sym(g_x1);
    float* x2_   = (float*)sym(g_x2);
    float* x3_   = (float*)sym(g_x3);
    float* v_    = (float*)sym(g_v);
    float* gate_ = (float*)sym(g_gate);

    hf *hh = (hf*)sym(f_h_hi),  *hl = (hf*)sym(f_h_lo);
    hf *hth = (hf*)sym(f_ht_hi), *htl = (hf*)sym(f_ht_lo);
    hf *wup = (hf*)sym(f_wup);
    hf *wq = (hf*)sym(f_wq);
    hf *wk = (hf*)sym(f_wk);
    hf *wv = (hf*)sym(f_wv);
    hf *wo = (hf*)sym(f_wo);
    hf *wg = (hf*)sym(f_wg);
    hf *wu = (hf*)sym(f_wu);
    hf *wd = (hf*)sym(f_wd);
    hf *uph = (hf*)sym(f_up_hi), *upl = (hf*)sym(f_up_lo);
    hf *x1h = (hf*)sym(f_x1_hi), *x1l = (hf*)sym(f_x1_lo);
    hf *x3h = (hf*)sym(f_x3_hi), *x3l = (hf*)sym(f_x3_lo);
    hf *qh = (hf*)sym(f_q_hi),   *ql = (hf*)sym(f_q_lo);
    hf *kh = (hf*)sym(f_k_hi);
    hf *oh = (hf*)sym(f_o_hi),   *ol = (hf*)sym(f_o_lo);
    hf *vth = (hf*)sym(f_vt_hi);
    hf *ubh = (hf*)sym(f_ub_hi), *ubl = (hf*)sym(f_ub_lo);

    const int SMEM128 = 1024 + 3 * (128 * 128 + 128 * 128);  // 99328
    const int SMEMFA  = 1024 + 32768 + 2 * 32768;            // 99328
    cudaFuncSetAttribute(mma_gemm<128>, cudaFuncAttributeMaxDynamicSharedMemorySize, SMEM128);
    cudaFuncSetAttribute(flash_attn, cudaFuncAttributeMaxDynamicSharedMemorySize, SMEMFA);

    dim3 blk(256);

    auto convW = [&](const float* x, hf* hi, long long n) {
        conv_hi<<<(unsigned)((n / 4 + 255) / 256), blk>>>(x, hi, n / 4);
    };

    // ---- first 5 launches (so ncu -s 5 captures the `up` GEMM) ----
    conv_split2<<<(unsigned)(HB / 1024), blk>>>(h_in, hh, hl, HB / 4);       // 1
    convW(Wup, wup, WUPN);                                                   // 2
    transpose_split2<<<dim3(HID / 32, S_LEN / 32, BATCH), blk>>>(            // 3
        h_in, HID, S_H, 0, hth, htl, S_LEN, S_H, 0, 1);
    convW(Wq, wq, W1N);                                                      // 4
    convW(Wk, wk, W1N);                                                      // 5

    // 6) up = Wup @ h (+bias)  [A=Wup hi-only, B=hT hi/lo]  <-- ncu target
    mma_gemm<128><<<dim3(HID / 128, SU_LEN / 128, BATCH), blk, SMEM128>>>(
        wup, nullptr, S_LEN, 0, 0,
        hth, htl, S_LEN, S_H, 0,
        up_, uph, upl, HID, SU_H, 0,
        bup, nullptr, 0, 0, 0, nullptr,
        S_LEN, 1.f, 1);

    convW(Wv, wv, W1N);
    convW(Wo, wo, W1N);
    convW(Wg, wg, W2N);
    convW(Wu, wu, W2N);
    convW(Wd, wd, W2N);

    // x1 = rmsnorm(up)
    rmsnorm_split<<<BATCH * SU_LEN, blk>>>(up_, anw, x1_, x1h, x1l);

    // q = x1 @ Wq^T  -> hi/lo
    mma_gemm<128><<<dim3(HID / 128, SU_LEN / 128, BATCH), blk, SMEM128>>>(
        x1h, x1l, HID, SU_H, 0,
        wq, nullptr, HID, 0, 0,
        nullptr, qh, ql, HID, SU_H, 0,
        nullptr, nullptr, 0, 0, 0, nullptr,
        HID, 1.f, 1);

    // k = [h; up] @ Wk^T  -> hi only
    mma_gemm<128><<<dim3(HID / 128, S_LEN / 128, BATCH), blk, SMEM128>>>(
        hh, hl, HID, S_H, 0,
        wk, nullptr, HID, 0, 0,
        nullptr, kh, nullptr, HID, T_H, 0,
        nullptr, nullptr, 0, 0, 0, nullptr,
        HID, 1.f, 1);
    mma_gemm<128><<<dim3(HID / 128, SU_LEN / 128, BATCH), blk, SMEM128>>>(
        uph, upl, HID, SU_H, 0,
        wk, nullptr, HID, 0, 0,
        nullptr, kh + (long long)S_LEN * HID, nullptr, HID, T_H, 0,
        nullptr, nullptr, 0, 0, 0, nullptr,
        HID, 1.f, 1);

    // v = [h; up] @ Wv^T (fp32), then transpose -> vT hi only
    mma_gemm<128><<<dim3(HID / 128, S_LEN / 128, BATCH), blk, SMEM128>>>(
        hh, hl, HID, S_H, 0,
        wv, nullptr, HID, 0, 0,
        v_, nullptr, nullptr, HID, T_H, 0,
        nullptr, nullptr, 0, 0, 0, nullptr,
        HID, 1.f, 1);
    mma_gemm<128><<<dim3(HID / 128, SU_LEN / 128, BATCH), blk, SMEM128>>>(
        uph, upl, HID, SU_H, 0,
        wv, nullptr, HID, 0, 0,
        v_ + (long long)S_LEN * HID, nullptr, nullptr, HID, T_H, 0,
        nullptr, nullptr, 0, 0, 0, nullptr,
        HID, 1.f, 1);
    transpose_split2<<<dim3(HDIM / 32, T_LEN / 32, BATCH * NHEAD), blk>>>(
        v_, HID, T_H, HDIM,
        vth, nullptr, T_LEN, T_H, (long long)HDIM * T_LEN, NHEAD);

    // fused flash attention -> o hi/lo
    flash_attn<<<dim3(SU_LEN / 128, BATCH * NHEAD), blk, SMEMFA>>>(
        qh, ql, kh, vth, oh, ol);

    // x2 = o @ Wo^T + x1
    mma_gemm<128><<<dim3(HID / 128, SU_LEN / 128, BATCH), blk, SMEM128>>>(
        oh, ol, HID, SU_H, 0,
        wo, nullptr, HID, 0, 0,
        x2_, nullptr, nullptr, HID, SU_H, 0,
        nullptr, x1_, HID, SU_H, 0, nullptr,
        HID, 1.f, 1);

    // x3 = rmsnorm(x2)
    rmsnorm_split<<<BATCH * SU_LEN, blk>>>(x2_, mnw, x3_, x3h, x3l);

    // gate = x3 @ Wg^T (fp32)
    mma_gemm<128><<<dim3(INTER / 128, SU_LEN / 128, BATCH), blk, SMEM128>>>(
        x3h, x3l, HID, SU_H, 0,
        wg, nullptr, HID, 0, 0,
        gate_, nullptr, nullptr, INTER, SU_I, 0,
        nullptr, nullptr, 0, 0, 0, nullptr,
        HID, 1.f, 1);

    // ub = silu(gate) * (x3 @ Wu^T) -> hi/lo (fused epilogue)
    mma_gemm<128><<<dim3(INTER / 128, SU_LEN / 128, BATCH), blk, SMEM128>>>(
        x3h, x3l, HID, SU_H, 0,
        wu, nullptr, HID, 0, 0,
        nullptr, ubh, ubl, INTER, SU_I, 0,
        nullptr, nullptr, 0, 0, 0, gate_,
        HID, 1.f, 1);

    // out = ub @ Wd^T + x3
    mma_gemm<128><<<dim3(HID / 128, SU_LEN / 128, BATCH), blk, SMEM128>>>(
        ubh, ubl, INTER, SU_I, 0,
        wd, nullptr, INTER, 0, 0,
        out, nullptr, nullptr, HID, SU_H, 0,
        nullptr, x3_, HID, SU_H, 0, nullptr,
        INTER, 1.f, 1);
}

// round 6
// speedup vs baseline: 3.0203x; 1.0025x over previous
#include <cuda_runtime.h>
#include <cuda_fp16.h>
#include <cstdint>

// ---------------- problem constants ----------------
#define BATCH 2
#define S_LEN 512
#define HID 2048
#define NHEAD 32
#define HDIM 64
#define SU_LEN 1024
#define T_LEN 1536
#define INTER 5632
#define EPS_RMS 1e-6f

#define S_H   (S_LEN * HID)
#define SU_H  (SU_LEN * HID)
#define T_H   (T_LEN * HID)
#define SU_I  ((long long)SU_LEN * INTER)

#define HB  (BATCH * S_LEN * HID)
#define XB  (BATCH * SU_LEN * HID)
#define KBN (BATCH * T_LEN * HID)
#define UBB ((long long)BATCH * SU_LEN * INTER)
#define WUPN (SU_LEN * S_LEN)
#define W1N  (HID * HID)
#define W2N  (INTER * HID)

typedef __half hf;

// ---------------- scratch (device globals; no runtime allocation) ----------------
__device__ float g_up  [XB];
__device__ float g_x1  [XB];
__device__ float g_x2  [XB];
__device__ float g_x3  [XB];
__device__ float g_v   [KBN];
__device__ float g_gate[UBB];

__device__ hf f_h_hi[HB],  f_h_lo[HB];
__device__ hf f_ht_hi[HB], f_ht_lo[HB];
__device__ hf f_wup[WUPN];
__device__ hf f_wq[W1N];
__device__ hf f_wk[W1N];
__device__ hf f_wv[W1N];
__device__ hf f_wo[W1N];
__device__ hf f_wg[W2N];
__device__ hf f_wu[W2N];
__device__ hf f_wd[W2N];
__device__ hf f_up_hi[XB], f_up_lo[XB];
__device__ hf f_x1_hi[XB], f_x1_lo[XB];
__device__ hf f_x3_hi[XB], f_x3_lo[XB];
__device__ hf f_q_hi[XB],  f_q_lo[XB];
__device__ hf f_k_hi[KBN];
__device__ hf f_o_hi[XB],  f_o_lo[XB];
__device__ hf f_vt_hi[KBN];
__device__ hf f_ub_hi[UBB], f_ub_lo[UBB];

// ---------------- PTX helpers ----------------
__device__ __forceinline__ uint32_t smem_u32(const void* p) {
    uint32_t a;
    asm("{ .reg .u64 t; cvta.to.shared.u64 t, %1; cvt.u32.u64 %0, t; }" : "=r"(a) : "l"(p));
    return a;
}
#define SWZ(off) ((off) ^ (((off) >> 3) & 0x70))

#define CP_ASYNC16(dst, src) \
    asm volatile("cp.async.cg.shared.global [%0], [%1], 16;" :: "r"(dst), "l"(src) : "memory")
#define CP_COMMIT() asm volatile("cp.async.commit_group;" ::: "memory")
__device__ __forceinline__ void cp_wait(int allow) {
    if (allow) asm volatile("cp.async.wait_group 1;" ::: "memory");
    else       asm volatile("cp.async.wait_group 0;" ::: "memory");
}

__device__ __forceinline__ void ldmx4(uint32_t* r, uint32_t addr) {
    asm volatile("ldmatrix.sync.aligned.m8n8.x4.shared.b16 {%0,%1,%2,%3}, [%4];"
        : "=r"(r[0]), "=r"(r[1]), "=r"(r[2]), "=r"(r[3]) : "r"(addr));
}

__device__ __forceinline__ void mma_f16(float* d, const uint32_t* a, uint32_t b0, uint32_t b1) {
    asm volatile("mma.sync.aligned.m16n8k16.row.col.f32.f16.f16.f32 "
        "{%0,%1,%2,%3}, {%4,%5,%6,%7}, {%8,%9}, {%0,%1,%2,%3};"
        : "+f"(d[0]), "+f"(d[1]), "+f"(d[2]), "+f"(d[3])
        : "r"(a[0]), "r"(a[1]), "r"(a[2]), "r"(a[3]), "r"(b0), "r"(b1));
}

__device__ __forceinline__ void split_f16(float v, hf& hi, hf& lo) {
    hi = __float2half(v);
    lo = __float2half(v - __half2float(hi));
}
__device__ __forceinline__ uint32_t pack_f16x2(hf a, hf b) {
    __half2 t;
    t.x = a; t.y = b;
    return *(uint32_t*)&t;
}

// ---------------- mma.sync GEMM (fp16, 2-pass one-sided compensation) ----------------
// C[m,n] = alpha * (Ah·Bh + (Al?Al:Ah)·(Al?Bh:Bl))  (+bias) (+resid) (silu-gate)
// Exactly one of Al / Bl is non-null.
template<int BN>
__global__ __launch_bounds__(256, 2) void mma_gemm(
    const hf* __restrict__ Ah, const hf* __restrict__ Al,
    int lda, long long sA1, long long sA2,
    const hf* __restrict__ Bh, const hf* __restrict__ Bl,
    int ldb, long long sB1, long long sB2,
    float* __restrict__ C, hf* __restrict__ Chi, hf* __restrict__ Clo,
    int ldc, long long sC1, long long sC2,
    const float* __restrict__ bias,
    const float* __restrict__ resid, int ldr, long long sR1, long long sR2,
    const float* __restrict__ gate,
    int K, float alpha, int batch2)
{
    extern __shared__ char smem[];
    const uint32_t sbase = smem_u32(smem);
    const uint32_t tiles = (sbase + 1023u) & ~1023u;
    constexpr int ASZ = 128 * 128;
    constexpr int BSZ = BN * 128;
    constexpr int STG = ASZ + BSZ;
    constexpr int NT8 = BN / 16;
    constexpr int NG  = BN / 32;

    const int tid = threadIdx.x, wid = tid >> 5, lane = tid & 31;
    const int z = blockIdx.z, z1 = z / batch2, z2 = z - z1 * batch2;
    const long long aOff = (long long)z1 * sA1 + (long long)z2 * sA2;
    const long long bOff = (long long)z1 * sB1 + (long long)z2 * sB2;
    const long long cOff = (long long)z1 * sC1 + (long long)z2 * sC2;
    Ah += aOff; Bh += bOff;
    if (Al) Al += aOff;
    if (Bl) Bl += bOff;
    const int m0 = blockIdx.y * 128, n0 = blockIdx.x * BN;
    const int m0w = (wid & 3) * 32;
    const int n0w = (wid >> 2) * (BN / 2);

    const int kc = K >> 6;
    const int nc = 2 * kc;

    auto load_chunk = [&](int c, int s) {
        const int seg = c / kc, kk = c - seg * kc;
        const hf* A = (seg == 1 && Al) ? Al : Ah;
        const hf* B = (seg == 1 && Bl) ? Bl : Bh;
        const int k0 = kk << 6;
        const uint32_t aB = tiles + s * STG;
        const uint32_t bB = aB + ASZ;
        const int NU = 1024 + BN * 8;
        for (int u = tid; u < NU; u += 256) {
            if (u < 1024) {
                int r = u >> 3, g = u & 7;
                CP_ASYNC16(aB + SWZ(r * 128 + g * 16),
                           A + (long long)(m0 + r) * lda + k0 + g * 8);
            } else {
                int u2 = u - 1024;
                int r = u2 >> 3, g = u2 & 7;
                CP_ASYNC16(bB + SWZ(r * 128 + g * 16),
                           B + (long long)(n0 + r) * ldb + k0 + g * 8);
            }
        }
        CP_COMMIT();
    };

    float acc[2][NT8][4];
    #pragma unroll
    for (int i = 0; i < 2; i++)
        #pragma unroll
        for (int j = 0; j < NT8; j++)
            #pragma unroll
            for (int q = 0; q < 4; q++) acc[i][j][q] = 0.f;

    load_chunk(0, 0);
    if (nc > 1) load_chunk(1, 1);

    const int lrow = lane & 15;
    const int lcol = (lane >> 4) * 16;

    for (int c = 0; c < nc; c++) {
        const int s = c % 3;
        cp_wait(c + 1 < nc ? 1 : 0);
        __syncthreads();
        if (c + 2 < nc) load_chunk(c + 2, (c + 2) % 3);

        const uint32_t aSt = tiles + s * STG;
        const uint32_t bSt = aSt + ASZ;
        #pragma unroll
        for (int ks = 0; ks < 4; ks++) {
            uint32_t ra[2][4];
            #pragma unroll
            for (int mt = 0; mt < 2; mt++)
                ldmx4(ra[mt], aSt + SWZ((m0w + mt * 16 + lrow) * 128 + ks * 32 + lcol));
            uint32_t rb[NG][4];
            #pragma unroll
            for (int ng = 0; ng < NG; ng++)
                ldmx4(rb[ng], bSt + SWZ((n0w + ng * 16 + lrow) * 128 + ks * 32 + lcol));
            #pragma unroll
            for (int mt = 0; mt < 2; mt++)
                #pragma unroll
                for (int ng = 0; ng < NG; ng++) {
                    mma_f16(acc[mt][2 * ng],     ra[mt], rb[ng][0], rb[ng][2]);
                    mma_f16(acc[mt][2 * ng + 1], ra[mt], rb[ng][1], rb[ng][3]);
                }
        }
        __syncthreads();
    }

    const int rq = lane >> 2;
    const int cq = (lane & 3) * 2;
    #pragma unroll
    for (int mt = 0; mt < 2; mt++) {
        #pragma unroll
        for (int half = 0; half < 2; half++) {
            const int m = m0 + m0w + mt * 16 + rq + half * 8;
            const float bv = bias ? bias[m] : 0.f;
            const long long cBase = cOff + (long long)m * ldc + n0 + n0w;
            const long long rBase = resid ? ((long long)z1 * sR1 + (long long)z2 * sR2 +
                                             (long long)m * ldr + n0 + n0w) : 0;
            #pragma unroll
            for (int nt = 0; nt < NT8; nt++) {
                float v0 = acc[mt][nt][half * 2]     * alpha + bv;
                float v1 = acc[mt][nt][half * 2 + 1] * alpha + bv;
                const int cn = nt * 8 + cq;
                if (resid) {
                    v0 += resid[rBase + cn];
                    v1 += resid[rBase + cn + 1];
                }
                if (gate) {
                    float g0 = gate[cBase + cn];
                    float g1 = gate[cBase + cn + 1];
                    v0 *= g0 / (1.f + __expf(-g0));
                    v1 *= g1 / (1.f + __expf(-g1));
                }
                if (C)
                    *(float2*)(C + cBase + cn) = make_float2(v0, v1);
                if (Chi) {
                    hf h0, l0, h1, l1;
                    split_f16(v0, h0, l0);
                    split_f16(v1, h1, l1);
                    *(uint32_t*)(Chi + cBase + cn) = pack_f16x2(h0, h1);
                    if (Clo)
                        *(uint32_t*)(Clo + cBase + cn) = pack_f16x2(l0, l1);
                }
            }
        }
    }
}

// ---------------- fused flash attention (fp16, 2-pass) ----------------
// grid: (SU/128, BATCH*NHEAD). 8 warps, each warp owns 16 q rows.
#define FA_NI (T_LEN / 128)   // 12

__global__ __launch_bounds__(256, 1) void flash_attn(
    const hf* __restrict__ gqh, const hf* __restrict__ gql,
    const hf* __restrict__ gkh,
    const hf* __restrict__ gvh,
    hf* __restrict__ goh, hf* __restrict__ gol)
{
    extern __shared__ char smem[];
    const uint32_t sb0 = smem_u32(smem);
    const uint32_t sb = (sb0 + 1023u) & ~1023u;
    const uint32_t Qh = sb, Ql = sb + 16384;
    const uint32_t ST0 = sb + 32768;
    const uint32_t STSZ = 32768;   // per stage: Kh 16K, Vh 16K

    const int tid = threadIdx.x, wid = tid >> 5, lane = tid & 31;
    const int q0 = blockIdx.x * 128;
    const int bh = blockIdx.y;
    const int b = bh >> 5, head = bh & 31;

    const hf* qhp = gqh + (long long)b * SU_H + head * HDIM;
    const hf* qlp = gql + (long long)b * SU_H + head * HDIM;
    const hf* khp = gkh + (long long)b * T_H + head * HDIM;
    const hf* vhp = gvh + (long long)b * T_H + (long long)head * HDIM * T_LEN;

    // load Q (once)
    for (int u = tid; u < 2048; u += 256) {
        int comp = u >> 10, r = (u >> 3) & 127, g = u & 7;
        const hf* src = (comp ? qlp : qhp) + (long long)(q0 + r) * HID + g * 8;
        CP_ASYNC16((comp ? Ql : Qh) + SWZ(r * 128 + g * 16), src);
    }
    CP_COMMIT();

    auto loadkv = [&](int ci, int s) {
        const int t0 = ci * 128;
        const uint32_t stb = ST0 + s * STSZ;
        for (int u = tid; u < 2048; u += 256) {
            if (u < 1024) {
                int r = u >> 3, g = u & 7;
                CP_ASYNC16(stb + SWZ(r * 128 + g * 16),
                           khp + (long long)(t0 + r) * HID + g * 8);
            } else {
                int u2 = u - 1024;
                int d = u2 >> 4, gg = u2 & 15;     // 16 groups of 8 over 128 t cols
                CP_ASYNC16(stb + 16384 + (gg >> 3) * 8192 + SWZ(d * 128 + (gg & 7) * 16),
                           vhp + (long long)d * T_LEN + t0 + gg * 8);
            }
        }
        CP_COMMIT();
    };

    loadkv(0, 0);
    loadkv(1, 1);
    cp_wait(1);              // Q + chunk0 ready
    __syncthreads();

    const int lrow = lane & 15, lcol = (lane >> 4) * 16;
    const int mrow = wid * 16;
    uint32_t qf[2][4][4];
    #pragma unroll
    for (int ks = 0; ks < 4; ks++) {
        ldmx4(qf[0][ks], Qh + SWZ((mrow + lrow) * 128 + ks * 32 + lcol));
        ldmx4(qf[1][ks], Ql + SWZ((mrow + lrow) * 128 + ks * 32 + lcol));
    }

    float oacc[8][4];
    #pragma unroll
    for (int i = 0; i < 8; i++)
        #pragma unroll
        for (int j = 0; j < 4; j++) oacc[i][j] = 0.f;
    float M0 = -1e30f, M1 = -1e30f, L0 = 0.f, L1 = 0.f;

    for (int i = 0; i < FA_NI; i++) {
        const uint32_t stb = ST0 + (i & 1) * STSZ;
        if (i > 0) { cp_wait(i + 1 < FA_NI ? 1 : 0); __syncthreads(); }

        // ---- S = Qh K^T + Ql K^T ----
        float sacc[16][4];
        #pragma unroll
        for (int t = 0; t < 16; t++)
            #pragma unroll
            for (int j = 0; j < 4; j++) sacc[t][j] = 0.f;

        #pragma unroll
        for (int p = 0; p < 2; p++) {
            #pragma unroll
            for (int ks = 0; ks < 4; ks++) {
                #pragma unroll
                for (int ng = 0; ng < 8; ng++) {
                    uint32_t rb[4];
                    ldmx4(rb, stb + SWZ((ng * 16 + lrow) * 128 + ks * 32 + lcol));
                    mma_f16(sacc[2 * ng],     qf[p][ks], rb[0], rb[2]);
                    mma_f16(sacc[2 * ng + 1], qf[p][ks], rb[1], rb[3]);
                }
            }
        }

        // ---- online softmax ----
        float mx0 = -1e30f, mx1 = -1e30f;
        #pragma unroll
        for (int t = 0; t < 16; t++) {
            sacc[t][0] *= 0.125f; sacc[t][1] *= 0.125f;
            sacc[t][2] *= 0.125f; sacc[t][3] *= 0.125f;
            mx0 = fmaxf(mx0, fmaxf(sacc[t][0], sacc[t][1]));
            mx1 = fmaxf(mx1, fmaxf(sacc[t][2], sacc[t][3]));
        }
        mx0 = fmaxf(mx0, __shfl_xor_sync(0xFFFFFFFFu, mx0, 1));
        mx0 = fmaxf(mx0, __shfl_xor_sync(0xFFFFFFFFu, mx0, 2));
        mx1 = fmaxf(mx1, __shfl_xor_sync(0xFFFFFFFFu, mx1, 1));
        mx1 = fmaxf(mx1, __shfl_xor_sync(0xFFFFFFFFu, mx1, 2));
        const float Mn0 = fmaxf(M0, mx0), Mn1 = fmaxf(M1, mx1);
        const float al0 = __expf(M0 - Mn0), al1 = __expf(M1 - Mn1);
        M0 = Mn0; M1 = Mn1;

        float s0 = 0.f, s1 = 0.f;
        #pragma unroll
        for (int t = 0; t < 16; t++) {
            sacc[t][0] = __expf(sacc[t][0] - M0); s0 += sacc[t][0];
            sacc[t][1] = __expf(sacc[t][1] - M0); s0 += sacc[t][1];
            sacc[t][2] = __expf(sacc[t][2] - M1); s1 += sacc[t][2];
            sacc[t][3] = __expf(sacc[t][3] - M1); s1 += sacc[t][3];
        }
        s0 += __shfl_xor_sync(0xFFFFFFFFu, s0, 1);
        s0 += __shfl_xor_sync(0xFFFFFFFFu, s0, 2);
        s1 += __shfl_xor_sync(0xFFFFFFFFu, s1, 1);
        s1 += __shfl_xor_sync(0xFFFFFFFFu, s1, 2);
        L0 = L0 * al0 + s0;
        L1 = L1 * al1 + s1;
        #pragma unroll
        for (int t = 0; t < 8; t++) {
            oacc[t][0] *= al0; oacc[t][1] *= al0;
            oacc[t][2] *= al1; oacc[t][3] *= al1;
        }

        // ---- O += Ph V + Pl V ----
        const uint32_t vb = stb + 16384;
        #pragma unroll
        for (int ks = 0; ks < 8; ks++) {
            float p0 = sacc[2 * ks][0],     p1 = sacc[2 * ks][1];
            float p2 = sacc[2 * ks][2],     p3 = sacc[2 * ks][3];
            float p4 = sacc[2 * ks + 1][0], p5 = sacc[2 * ks + 1][1];
            float p6 = sacc[2 * ks + 1][2], p7 = sacc[2 * ks + 1][3];
            hf h0, l0, h1, l1, h2, l2, h3, l3, h4, l4, h5, l5, h6, l6, h7, l7;
            split_f16(p0, h0, l0); split_f16(p1, h1, l1);
            split_f16(p2, h2, l2); split_f16(p3, h3, l3);
            split_f16(p4, h4, l4); split_f16(p5, h5, l5);
            split_f16(p6, h6, l6); split_f16(p7, h7, l7);
            uint32_t ah[4], alr[4];
            ah[0] = pack_f16x2(h0, h1);  ah[1] = pack_f16x2(h2, h3);
            ah[2] = pack_f16x2(h4, h5);  ah[3] = pack_f16x2(h6, h7);
            alr[0] = pack_f16x2(l0, l1); alr[1] = pack_f16x2(l2, l3);
            alr[2] = pack_f16x2(l4, l5); alr[3] = pack_f16x2(l6, l7);

            const uint32_t vhb = vb + (ks >> 2) * 8192;
            const int ksl = ks & 3;
            #pragma unroll
            for (int ng = 0; ng < 4; ng++) {
                uint32_t rb[4];
                ldmx4(rb, vhb + SWZ((ng * 16 + lrow) * 128 + ksl * 32 + lcol));
                mma_f16(oacc[2 * ng],     ah,  rb[0], rb[2]);
                mma_f16(oacc[2 * ng + 1], ah,  rb[1], rb[3]);
                mma_f16(oacc[2 * ng],     alr, rb[0], rb[2]);
                mma_f16(oacc[2 * ng + 1], alr, rb[1], rb[3]);
            }
        }

        __syncthreads();
        if (i + 2 < FA_NI) loadkv(i + 2, i & 1);
    }

    // ---- epilogue ----
    const float inv0 = 1.f / L0, inv1 = 1.f / L1;
    const int rq = lane >> 2, cq = (lane & 3) * 2;
    const long long base0 = (long long)b * SU_H + (long long)(q0 + mrow + rq) * HID + head * HDIM;
    const long long base1 = base0 + 8LL * HID;
    #pragma unroll
    for (int nt = 0; nt < 8; nt++) {
        const int cn = nt * 8 + cq;
        float v0 = oacc[nt][0] * inv0, v1 = oacc[nt][1] * inv0;
        float v2 = oacc[nt][2] * inv1, v3 = oacc[nt][3] * inv1;
        hf h0, l0, h1, l1, h2, l2, h3, l3;
        split_f16(v0, h0, l0); split_f16(v1, h1, l1);
        split_f16(v2, h2, l2); split_f16(v3, h3, l3);
        *(uint32_t*)(goh + base0 + cn) = pack_f16x2(h0, h1);
        *(uint32_t*)(gol + base0 + cn) = pack_f16x2(l0, l1);
        *(uint32_t*)(goh + base1 + cn) = pack_f16x2(h2, h3);
        *(uint32_t*)(gol + base1 + cn) = pack_f16x2(l2, l3);
    }
}

// ---------------- conversions ----------------
__global__ __launch_bounds__(256) void conv_split2(const float* __restrict__ x,
                                                   hf* __restrict__ hi, hf* __restrict__ lo,
                                                   long long n4)
{
    long long i = (long long)blockIdx.x * 256 + threadIdx.x;
    if (i >= n4) return;
    float4 v = ((const float4*)x)[i];
    hf h0, l0, h1, l1, h2, l2, h3, l3;
    split_f16(v.x, h0, l0); split_f16(v.y, h1, l1);
    split_f16(v.z, h2, l2); split_f16(v.w, h3, l3);
    ((uint32_t*)hi)[i * 2]     = pack_f16x2(h0, h1);
    ((uint32_t*)hi)[i * 2 + 1] = pack_f16x2(h2, h3);
    ((uint32_t*)lo)[i * 2]     = pack_f16x2(l0, l1);
    ((uint32_t*)lo)[i * 2 + 1] = pack_f16x2(l2, l3);
}

__global__ __launch_bounds__(256) void conv_hi(const float* __restrict__ x,
                                               hf* __restrict__ hi, long long n4)
{
    long long i = (long long)blockIdx.x * 256 + threadIdx.x;
    if (i >= n4) return;
    float4 v = ((const float4*)x)[i];
    ((uint32_t*)hi)[i * 2]     = pack_f16x2(__float2half(v.x), __float2half(v.y));
    ((uint32_t*)hi)[i * 2 + 1] = pack_f16x2(__float2half(v.z), __float2half(v.w));
}

// ---------------- transpose variants ----------------
__global__ __launch_bounds__(256) void transpose_split2(
    const float* __restrict__ in, int ldi, long long sI1, long long sI2,
    hf* __restrict__ oh, hf* __restrict__ ol, int ldo, long long sO1, long long sO2,
    int batch2)
{
    __shared__ float t[32][33];
    int z = blockIdx.z, z1 = z / batch2, z2 = z - z1 * batch2;
    in += (long long)z1 * sI1 + (long long)z2 * sI2;
    long long oOff = (long long)z1 * sO1 + (long long)z2 * sO2;
    int r0 = blockIdx.y * 32, c0 = blockIdx.x * 32;
    int tx = threadIdx.x & 31, ty8 = threadIdx.x >> 5;
    #pragma unroll
    for (int i = 0; i < 4; i++) {
        int ty = ty8 + i * 8;
        t[ty][tx] = in[(long long)(r0 + ty) * ldi + c0 + tx];
    }
    __syncthreads();
    #pragma unroll
    for (int i = 0; i < 4; i++) {
        int oy = ty8 + i * 8;
        float v = t[tx][oy];
        hf h, l;
        split_f16(v, h, l);
        long long idx = oOff + (long long)(c0 + oy) * ldo + r0 + tx;
        oh[idx] = h;
        if (ol) ol[idx] = l;
    }
}

// ---------------- rmsnorm + split ----------------
__global__ __launch_bounds__(256) void rmsnorm_split(
    const float* __restrict__ x, const float* __restrict__ w,
    float* __restrict__ y, hf* __restrict__ yh, hf* __restrict__ yl)
{
    __shared__ float red[256];
    long long row = blockIdx.x;
    const float* xr = x + row * HID;
    int tid = threadIdx.x;
    float4 v0 = *(const float4*)(xr + tid * 4);
    float4 v1 = *(const float4*)(xr + 1024 + tid * 4);
    float s = v0.x * v0.x + v0.y * v0.y + v0.z * v0.z + v0.w * v0.w
            + v1.x * v1.x + v1.y * v1.y + v1.z * v1.z + v1.w * v1.w;
    red[tid] = s;
    __syncthreads();
    for (int st = 128; st > 0; st >>= 1) {
        if (tid < st) red[tid] += red[tid + st];
        __syncthreads();
    }
    float inv = rsqrtf(red[0] * (1.f / HID) + EPS_RMS);

    float4 w0 = *(const float4*)(w + tid * 4);
    float4 w1 = *(const float4*)(w + 1024 + tid * 4);
    float o[8];
    o[0] = v0.x * inv * w0.x; o[1] = v0.y * inv * w0.y;
    o[2] = v0.z * inv * w0.z; o[3] = v0.w * inv * w0.w;
    o[4] = v1.x * inv * w1.x; o[5] = v1.y * inv * w1.y;
    o[6] = v1.z * inv * w1.z; o[7] = v1.w * inv * w1.w;
    float* yr = y + row * HID;
    *(float4*)(yr + tid * 4) = make_float4(o[0], o[1], o[2], o[3]);
    *(float4*)(yr + 1024 + tid * 4) = make_float4(o[4], o[5], o[6], o[7]);
    hf* yhr = yh + row * HID;
    hf* ylr = yl + row * HID;
    #pragma unroll
    for (int g = 0; g < 2; g++) {
        hf h0, l0, h1, l1, h2, l2, h3, l3;
        split_f16(o[g * 4 + 0], h0, l0);
        split_f16(o[g * 4 + 1], h1, l1);
        split_f16(o[g * 4 + 2], h2, l2);
        split_f16(o[g * 4 + 3], h3, l3);
        int off = g * 1024 + tid * 4;
        *(uint32_t*)(yhr + off)     = pack_f16x2(h0, h1);
        *(uint32_t*)(yhr + off + 2) = pack_f16x2(h2, h3);
        *(uint32_t*)(ylr + off)     = pack_f16x2(l0, l1);
        *(uint32_t*)(ylr + off + 2) = pack_f16x2(l2, l3);
    }
}

// ---------------- host ----------------
static void* sym(const void* s) {
    void* p = nullptr;
    cudaGetSymbolAddress(&p, s);
    return p;
}

extern "C" void kernel_launch(void* const* d_in, const int* in_sizes, int n_in,
                              void* d_out, int out_size)
{
    const float* h_in = (const float*)d_in[0];
    const float* Wup  = (const float*)d_in[1];
    const float* bup  = (const float*)d_in[2];
    const float* anw  = (const float*)d_in[3];
    const float* Wq   = (const float*)d_in[4];
    const float* Wk   = (const float*)d_in[5];
    const float* Wv   = (const float*)d_in[6];
    const float* Wo   = (const float*)d_in[7];
    const float* mnw  = (const float*)d_in[8];
    const float* Wg   = (const float*)d_in[9];
    const float* Wu   = (const float*)d_in[10];
    const float* Wd   = (const float*)d_in[11];
    float* out = (float*)d_out;

    float* up_   = (float*)sym(g_up);
    float* x1_   = (float*)sym(g_x1);
    float* x2_   = (float*)sym(g_x2);
    float* x3_   = (float*)sym(g_x3);
    float* v_    = (float*)sym(g_v);
    float* gate_ = (float*)sym(g_gate);

    hf *hh = (hf*)sym(f_h_hi),  *hl = (hf*)sym(f_h_lo);
    hf *hth = (hf*)sym(f_ht_hi), *htl = (hf*)sym(f_ht_lo);
    hf *wup = (hf*)sym(f_wup);
    hf *wq = (hf*)sym(f_wq);
    hf *wk = (hf*)sym(f_wk);
    hf *wv = (hf*)sym(f_wv);
    hf *wo = (hf*)sym(f_wo);
    hf *wg = (hf*)sym(f_wg);
    hf *wu = (hf*)sym(f_wu);
    hf *wd = (hf*)sym(f_wd);
    hf *uph = (hf*)sym(f_up_hi), *upl = (hf*)sym(f_up_lo);
    hf *x1h = (hf*)sym(f_x1_hi), *x1l = (hf*)sym(f_x1_lo);
    hf *x3h = (hf*)sym(f_x3_hi), *x3l = (hf*)sym(f_x3_lo);
    hf *qh = (hf*)sym(f_q_hi),   *ql = (hf*)sym(f_q_lo);
    hf *kh = (hf*)sym(f_k_hi);
    hf *oh = (hf*)sym(f_o_hi),   *ol = (hf*)sym(f_o_lo);
    hf *vth = (hf*)sym(f_vt_hi);
    hf *ubh = (hf*)sym(f_ub_hi), *ubl = (hf*)sym(f_ub_lo);

    const int SMEM128 = 1024 + 3 * (128 * 128 + 128 * 128);  // 99328
    const int SMEMFA  = 1024 + 32768 + 2 * 32768;            // 99328
    cudaFuncSetAttribute(mma_gemm<128>, cudaFuncAttributeMaxDynamicSharedMemorySize, SMEM128);
    cudaFuncSetAttribute(flash_attn, cudaFuncAttributeMaxDynamicSharedMemorySize, SMEMFA);

    dim3 blk(256);

    auto convW = [&](const float* x, hf* hi, long long n) {
        conv_hi<<<(unsigned)((n / 4 + 255) / 256), blk>>>(x, hi, n / 4);
    };

    // ---- first 5 launches (so ncu -s 5 captures the `up` GEMM) ----
    conv_split2<<<(unsigned)(HB / 1024), blk>>>(h_in, hh, hl, HB / 4);       // 1
    convW(Wup, wup, WUPN);                                                   // 2
    transpose_split2<<<dim3(HID / 32, S_LEN / 32, BATCH), blk>>>(            // 3
        h_in, HID, S_H, 0, hth, htl, S_LEN, S_H, 0, 1);
    convW(Wq, wq, W1N);                                                      // 4
    convW(Wk, wk, W1N);                                                      // 5

    // 6) up = Wup @ h (+bias)  [A=Wup hi-only, B=hT hi/lo]  <-- ncu target
    mma_gemm<128><<<dim3(HID / 128, SU_LEN / 128, BATCH), blk, SMEM128>>>(
        wup, nullptr, S_LEN, 0, 0,
        hth, htl, S_LEN, S_H, 0,
        up_, uph, upl, HID, SU_H, 0,
        bup, nullptr, 0, 0, 0, nullptr,
        S_LEN, 1.f, 1);

    convW(Wv, wv, W1N);
    convW(Wo, wo, W1N);
    convW(Wg, wg, W2N);
    convW(Wu, wu, W2N);
    convW(Wd, wd, W2N);

    // x1 = rmsnorm(up)
    rmsnorm_split<<<BATCH * SU_LEN, blk>>>(up_, anw, x1_, x1h, x1l);

    // q = x1 @ Wq^T  -> hi/lo
    mma_gemm<128><<<dim3(HID / 128, SU_LEN / 128, BATCH), blk, SMEM128>>>(
        x1h, x1l, HID, SU_H, 0,
        wq, nullptr, HID, 0, 0,
        nullptr, qh, ql, HID, SU_H, 0,
        nullptr, nullptr, 0, 0, 0, nullptr,
        HID, 1.f, 1);

    // k = [h; up] @ Wk^T  -> hi only
    mma_gemm<128><<<dim3(HID / 128, S_LEN / 128, BATCH), blk, SMEM128>>>(
        hh, hl, HID, S_H, 0,
        wk, nullptr, HID, 0, 0,
        nullptr, kh, nullptr, HID, T_H, 0,
        nullptr, nullptr, 0, 0, 0, nullptr,
        HID, 1.f, 1);
    mma_gemm<128><<<dim3(HID / 128, SU_LEN / 128, BATCH), blk, SMEM128>>>(
        uph, upl, HID, SU_H, 0,
        wk, nullptr, HID, 0, 0,
        nullptr, kh + (long long)S_LEN * HID, nullptr, HID, T_H, 0,
        nullptr, nullptr, 0, 0, 0, nullptr,
        HID, 1.f, 1);

    // v = [h; up] @ Wv^T (fp32), then transpose -> vT hi only
    mma_gemm<128><<<dim3(HID / 128, S_LEN / 128, BATCH), blk, SMEM128>>>(
        hh, hl, HID, S_H, 0,
        wv, nullptr, HID, 0, 0,
        v_, nullptr, nullptr, HID, T_H, 0,
        nullptr, nullptr, 0, 0, 0, nullptr,
        HID, 1.f, 1);
    mma_gemm<128><<<dim3(HID / 128, SU_LEN / 128, BATCH), blk, SMEM128>>>(
        uph, upl, HID, SU_H, 0,
        wv, nullptr, HID, 0, 0,
        v_ + (long long)S_LEN * HID, nullptr, nullptr, HID, T_H, 0,
        nullptr, nullptr, 0, 0, 0, nullptr,
        HID, 1.f, 1);
    transpose_split2<<<dim3(HDIM / 32, T_LEN / 32, BATCH * NHEAD), blk>>>(
        v_, HID, T_H, HDIM,
        vth, nullptr, T_LEN, T_H, (long long)HDIM * T_LEN, NHEAD);

    // fused flash attention -> o hi/lo
    flash_attn<<<dim3(SU_LEN / 128, BATCH * NHEAD), blk, SMEMFA>>>(
        qh, ql, kh, vth, oh, ol);

    // x2 = o @ Wo^T + x1
    mma_gemm<128><<<dim3(HID / 128, SU_LEN / 128, BATCH), blk, SMEM128>>>(
        oh, ol, HID, SU_H, 0,
        wo, nullptr, HID, 0, 0,
        x2_, nullptr, nullptr, HID, SU_H, 0,
        nullptr, x1_, HID, SU_H, 0, nullptr,
        HID, 1.f, 1);

    // x3 = rmsnorm(x2)
    rmsnorm_split<<<BATCH * SU_LEN, blk>>>(x2_, mnw, x3_, x3h, x3l);

    // gate = x3 @ Wg^T (fp32)
    mma_gemm<128><<<dim3(INTER / 128, SU_LEN / 128, BATCH), blk, SMEM128>>>(
        x3h, x3l, HID, SU_H, 0,
        wg, nullptr, HID, 0, 0,
        gate_, nullptr, nullptr, INTER, SU_I, 0,
        nullptr, nullptr, 0, 0, 0, nullptr,
        HID, 1.f, 1);

    // ub = silu(gate) * (x3 @ Wu^T) -> hi/lo (fused epilogue)
    mma_gemm<128><<<dim3(INTER / 128, SU_LEN / 128, BATCH), blk, SMEM128>>>(
        x3h, x3l, HID, SU_H, 0,
        wu, nullptr, HID, 0, 0,
        nullptr, ubh, ubl, INTER, SU_I, 0,
        nullptr, nullptr, 0, 0, 0, gate_,
        HID, 1.f, 1);

    // out = ub @ Wd^T + x3
    mma_gemm<128><<<dim3(HID / 128, SU_LEN / 128, BATCH), blk, SMEM128>>>(
        ubh, ubl, INTER, SU_I, 0,
        wd, nullptr, INTER, 0, 0,
        out, nullptr, nullptr, HID, SU_H, 0,
        nullptr, x3_, HID, SU_H, 0, nullptr,
        INTER, 1.f, 1);
}

// round 7
// speedup vs baseline: 3.7917x; 1.2554x over previous
#include <cuda_runtime.h>
#include <cuda_fp16.h>
#include <cstdint>

// ---------------- problem constants ----------------
#define BATCH 2
#define S_LEN 512
#define HID 2048
#define NHEAD 32
#define HDIM 64
#define SU_LEN 1024
#define T_LEN 1536
#define INTER 5632
#define EPS_RMS 1e-6f

#define S_H   (S_LEN * HID)
#define SU_H  (SU_LEN * HID)
#define T_H   (T_LEN * HID)
#define SU_I  ((long long)SU_LEN * INTER)

#define HB  (BATCH * S_LEN * HID)
#define XB  (BATCH * SU_LEN * HID)
#define KBN (BATCH * T_LEN * HID)
#define UBB ((long long)BATCH * SU_LEN * INTER)
#define WUPN (SU_LEN * S_LEN)
#define W1N  (HID * HID)
#define W2N  (INTER * HID)

typedef __half hf;

// ---------------- scratch (device globals; no runtime allocation) ----------------
__device__ float g_up  [XB];
__device__ float g_x1  [XB];
__device__ float g_x2  [XB];
__device__ float g_x3  [XB];
__device__ float g_v   [KBN];
__device__ float g_gate[UBB];

__device__ hf f_h_hi[HB],  f_h_lo[HB];
__device__ hf f_ht_hi[HB], f_ht_lo[HB];
__device__ hf f_wup[WUPN];
__device__ hf f_wq[W1N];
__device__ hf f_wk[W1N];
__device__ hf f_wv[W1N];
__device__ hf f_wo[W1N];
__device__ hf f_wg[W2N];
__device__ hf f_wu[W2N];
__device__ hf f_wd[W2N];
__device__ hf f_up_hi[XB], f_up_lo[XB];
__device__ hf f_x1_hi[XB], f_x1_lo[XB];
__device__ hf f_x3_hi[XB], f_x3_lo[XB];
__device__ hf f_q_hi[XB],  f_q_lo[XB];
__device__ hf f_k_hi[KBN];
__device__ hf f_o_hi[XB],  f_o_lo[XB];
__device__ hf f_vt_hi[KBN];
__device__ hf f_ub_hi[UBB], f_ub_lo[UBB];

// ---------------- PTX helpers ----------------
__device__ __forceinline__ uint32_t smem_u32(const void* p) {
    uint32_t a;
    asm("{ .reg .u64 t; cvta.to.shared.u64 t, %1; cvt.u32.u64 %0, t; }" : "=r"(a) : "l"(p));
    return a;
}
#define SWZ(off) ((off) ^ (((off) >> 3) & 0x70))

#define CP_ASYNC16(dst, src) \
    asm volatile("cp.async.cg.shared.global [%0], [%1], 16;" :: "r"(dst), "l"(src) : "memory")
#define CP_COMMIT() asm volatile("cp.async.commit_group;" ::: "memory")
__device__ __forceinline__ void cp_wait(int allow) {
    if (allow) asm volatile("cp.async.wait_group 1;" ::: "memory");
    else       asm volatile("cp.async.wait_group 0;" ::: "memory");
}

__device__ __forceinline__ void ldmx4(uint32_t* r, uint32_t addr) {
    asm volatile("ldmatrix.sync.aligned.m8n8.x4.shared.b16 {%0,%1,%2,%3}, [%4];"
        : "=r"(r[0]), "=r"(r[1]), "=r"(r[2]), "=r"(r[3]) : "r"(addr));
}

__device__ __forceinline__ void mma_f16(float* d, const uint32_t* a, uint32_t b0, uint32_t b1) {
    asm volatile("mma.sync.aligned.m16n8k16.row.col.f32.f16.f16.f32 "
        "{%0,%1,%2,%3}, {%4,%5,%6,%7}, {%8,%9}, {%0,%1,%2,%3};"
        : "+f"(d[0]), "+f"(d[1]), "+f"(d[2]), "+f"(d[3])
        : "r"(a[0]), "r"(a[1]), "r"(a[2]), "r"(a[3]), "r"(b0), "r"(b1));
}

__device__ __forceinline__ void split_f16(float v, hf& hi, hf& lo) {
    hi = __float2half(v);
    lo = __float2half(v - __half2float(hi));
}
__device__ __forceinline__ uint32_t pack_f16x2(hf a, hf b) {
    __half2 t;
    t.x = a; t.y = b;
    return *(uint32_t*)&t;
}

// ---------------- mma.sync GEMM (fp16, 2-pass one-sided compensation) ----------------
// 128 threads, 4 warps in 2x2, warp tile 64x64, CTA tile 128x128, BK=64.
// C[m,n] = alpha * (Ah·Bh + (Al?Al:Ah)·(Al?Bh:Bl))  (+bias) (+resid) (silu-gate)
__global__ __launch_bounds__(128, 2) void mma_gemm(
    const hf* __restrict__ Ah, const hf* __restrict__ Al,
    int lda, long long sA1, long long sA2,
    const hf* __restrict__ Bh, const hf* __restrict__ Bl,
    int ldb, long long sB1, long long sB2,
    float* __restrict__ C, hf* __restrict__ Chi, hf* __restrict__ Clo,
    int ldc, long long sC1, long long sC2,
    const float* __restrict__ bias,
    const float* __restrict__ resid, int ldr, long long sR1, long long sR2,
    const float* __restrict__ gate,
    int K, float alpha, int batch2)
{
    extern __shared__ char smem[];
    const uint32_t sbase = smem_u32(smem);
    const uint32_t tiles = (sbase + 1023u) & ~1023u;
    constexpr int ASZ = 128 * 128;     // 16 KB (128 rows x 128 B)
    constexpr int BSZ = 128 * 128;
    constexpr int STG = ASZ + BSZ;     // 32 KB per stage

    const int tid = threadIdx.x, wid = tid >> 5, lane = tid & 31;
    const int z = blockIdx.z, z1 = z / batch2, z2 = z - z1 * batch2;
    const long long aOff = (long long)z1 * sA1 + (long long)z2 * sA2;
    const long long bOff = (long long)z1 * sB1 + (long long)z2 * sB2;
    const long long cOff = (long long)z1 * sC1 + (long long)z2 * sC2;
    Ah += aOff; Bh += bOff;
    if (Al) Al += aOff;
    if (Bl) Bl += bOff;
    const int m0 = blockIdx.y * 128, n0 = blockIdx.x * 128;
    const int m0w = (wid & 1) * 64;     // warp m offset
    const int n0w = (wid >> 1) * 64;    // warp n offset

    const int kc = K >> 6;
    const int nc = 2 * kc;

    auto load_chunk = [&](int c, int s) {
        const int seg = c / kc, kk = c - seg * kc;
        const hf* A = (seg == 1 && Al) ? Al : Ah;
        const hf* B = (seg == 1 && Bl) ? Bl : Bh;
        const int k0 = kk << 6;
        const uint32_t aB = tiles + s * STG;
        const uint32_t bB = aB + ASZ;
        #pragma unroll
        for (int u0 = 0; u0 < 2048; u0 += 128) {
            int u = u0 + tid;
            if (u < 1024) {
                int r = u >> 3, g = u & 7;
                CP_ASYNC16(aB + SWZ(r * 128 + g * 16),
                           A + (long long)(m0 + r) * lda + k0 + g * 8);
            } else {
                int u2 = u - 1024;
                int r = u2 >> 3, g = u2 & 7;
                CP_ASYNC16(bB + SWZ(r * 128 + g * 16),
                           B + (long long)(n0 + r) * ldb + k0 + g * 8);
            }
        }
        CP_COMMIT();
    };

    float acc[4][8][4];
    #pragma unroll
    for (int i = 0; i < 4; i++)
        #pragma unroll
        for (int j = 0; j < 8; j++)
            #pragma unroll
            for (int q = 0; q < 4; q++) acc[i][j][q] = 0.f;

    load_chunk(0, 0);
    if (nc > 1) load_chunk(1, 1);

    const int lrow = lane & 15;
    const int lcol = (lane >> 4) * 16;

    for (int c = 0; c < nc; c++) {
        const int s = c % 3;
        cp_wait(c + 1 < nc ? 1 : 0);
        __syncthreads();
        if (c + 2 < nc) load_chunk(c + 2, (c + 2) % 3);

        const uint32_t aSt = tiles + s * STG;
        const uint32_t bSt = aSt + ASZ;
        #pragma unroll
        for (int ks = 0; ks < 4; ks++) {
            uint32_t ra[4][4];
            #pragma unroll
            for (int mt = 0; mt < 4; mt++)
                ldmx4(ra[mt], aSt + SWZ((m0w + mt * 16 + lrow) * 128 + ks * 32 + lcol));
            #pragma unroll
            for (int ng = 0; ng < 4; ng++) {
                uint32_t rb[4];
                ldmx4(rb, bSt + SWZ((n0w + ng * 16 + lrow) * 128 + ks * 32 + lcol));
                #pragma unroll
                for (int mt = 0; mt < 4; mt++) {
                    mma_f16(acc[mt][2 * ng],     ra[mt], rb[0], rb[2]);
                    mma_f16(acc[mt][2 * ng + 1], ra[mt], rb[1], rb[3]);
                }
            }
        }
        __syncthreads();
    }

    const int rq = lane >> 2;
    const int cq = (lane & 3) * 2;
    #pragma unroll
    for (int mt = 0; mt < 4; mt++) {
        #pragma unroll
        for (int half = 0; half < 2; half++) {
            const int m = m0 + m0w + mt * 16 + rq + half * 8;
            const float bv = bias ? bias[m] : 0.f;
            const long long cBase = cOff + (long long)m * ldc + n0 + n0w;
            const long long rBase = resid ? ((long long)z1 * sR1 + (long long)z2 * sR2 +
                                             (long long)m * ldr + n0 + n0w) : 0;
            #pragma unroll
            for (int nt = 0; nt < 8; nt++) {
                float v0 = acc[mt][nt][half * 2]     * alpha + bv;
                float v1 = acc[mt][nt][half * 2 + 1] * alpha + bv;
                const int cn = nt * 8 + cq;
                if (resid) {
                    v0 += resid[rBase + cn];
                    v1 += resid[rBase + cn + 1];
                }
                if (gate) {
                    float g0 = gate[cBase + cn];
                    float g1 = gate[cBase + cn + 1];
                    v0 *= g0 / (1.f + __expf(-g0));
                    v1 *= g1 / (1.f + __expf(-g1));
                }
                if (C)
                    *(float2*)(C + cBase + cn) = make_float2(v0, v1);
                if (Chi) {
                    hf h0, l0, h1, l1;
                    split_f16(v0, h0, l0);
                    split_f16(v1, h1, l1);
                    *(uint32_t*)(Chi + cBase + cn) = pack_f16x2(h0, h1);
                    if (Clo)
                        *(uint32_t*)(Clo + cBase + cn) = pack_f16x2(l0, l1);
                }
            }
        }
    }
}

// ---------------- fused flash attention (fp16, 2-pass) ----------------
#define FA_NI (T_LEN / 128)   // 12

__global__ __launch_bounds__(256, 1) void flash_attn(
    const hf* __restrict__ gqh, const hf* __restrict__ gql,
    const hf* __restrict__ gkh,
    const hf* __restrict__ gvh,
    hf* __restrict__ goh, hf* __restrict__ gol)
{
    extern __shared__ char smem[];
    const uint32_t sb0 = smem_u32(smem);
    const uint32_t sb = (sb0 + 1023u) & ~1023u;
    const uint32_t Qh = sb, Ql = sb + 16384;
    const uint32_t ST0 = sb + 32768;
    const uint32_t STSZ = 32768;   // per stage: Kh 16K, Vh 16K

    const int tid = threadIdx.x, wid = tid >> 5, lane = tid & 31;
    const int q0 = blockIdx.x * 128;
    const int bh = blockIdx.y;
    const int b = bh >> 5, head = bh & 31;

    const hf* qhp = gqh + (long long)b * SU_H + head * HDIM;
    const hf* qlp = gql + (long long)b * SU_H + head * HDIM;
    const hf* khp = gkh + (long long)b * T_H + head * HDIM;
    const hf* vhp = gvh + (long long)b * T_H + (long long)head * HDIM * T_LEN;

    for (int u = tid; u < 2048; u += 256) {
        int comp = u >> 10, r = (u >> 3) & 127, g = u & 7;
        const hf* src = (comp ? qlp : qhp) + (long long)(q0 + r) * HID + g * 8;
        CP_ASYNC16((comp ? Ql : Qh) + SWZ(r * 128 + g * 16), src);
    }
    CP_COMMIT();

    auto loadkv = [&](int ci, int s) {
        const int t0 = ci * 128;
        const uint32_t stb = ST0 + s * STSZ;
        for (int u = tid; u < 2048; u += 256) {
            if (u < 1024) {
                int r = u >> 3, g = u & 7;
                CP_ASYNC16(stb + SWZ(r * 128 + g * 16),
                           khp + (long long)(t0 + r) * HID + g * 8);
            } else {
                int u2 = u - 1024;
                int d = u2 >> 4, gg = u2 & 15;
                CP_ASYNC16(stb + 16384 + (gg >> 3) * 8192 + SWZ(d * 128 + (gg & 7) * 16),
                           vhp + (long long)d * T_LEN + t0 + gg * 8);
            }
        }
        CP_COMMIT();
    };

    loadkv(0, 0);
    loadkv(1, 1);
    cp_wait(1);
    __syncthreads();

    const int lrow = lane & 15, lcol = (lane >> 4) * 16;
    const int mrow = wid * 16;
    uint32_t qf[2][4][4];
    #pragma unroll
    for (int ks = 0; ks < 4; ks++) {
        ldmx4(qf[0][ks], Qh + SWZ((mrow + lrow) * 128 + ks * 32 + lcol));
        ldmx4(qf[1][ks], Ql + SWZ((mrow + lrow) * 128 + ks * 32 + lcol));
    }

    float oacc[8][4];
    #pragma unroll
    for (int i = 0; i < 8; i++)
        #pragma unroll
        for (int j = 0; j < 4; j++) oacc[i][j] = 0.f;
    float M0 = -1e30f, M1 = -1e30f, L0 = 0.f, L1 = 0.f;

    for (int i = 0; i < FA_NI; i++) {
        const uint32_t stb = ST0 + (i & 1) * STSZ;
        if (i > 0) { cp_wait(i + 1 < FA_NI ? 1 : 0); __syncthreads(); }

        float sacc[16][4];
        #pragma unroll
        for (int t = 0; t < 16; t++)
            #pragma unroll
            for (int j = 0; j < 4; j++) sacc[t][j] = 0.f;

        #pragma unroll
        for (int p = 0; p < 2; p++) {
            #pragma unroll
            for (int ks = 0; ks < 4; ks++) {
                #pragma unroll
                for (int ng = 0; ng < 8; ng++) {
                    uint32_t rb[4];
                    ldmx4(rb, stb + SWZ((ng * 16 + lrow) * 128 + ks * 32 + lcol));
                    mma_f16(sacc[2 * ng],     qf[p][ks], rb[0], rb[2]);
                    mma_f16(sacc[2 * ng + 1], qf[p][ks], rb[1], rb[3]);
                }
            }
        }

        float mx0 = -1e30f, mx1 = -1e30f;
        #pragma unroll
        for (int t = 0; t < 16; t++) {
            sacc[t][0] *= 0.125f; sacc[t][1] *= 0.125f;
            sacc[t][2] *= 0.125f; sacc[t][3] *= 0.125f;
            mx0 = fmaxf(mx0, fmaxf(sacc[t][0], sacc[t][1]));
            mx1 = fmaxf(mx1, fmaxf(sacc[t][2], sacc[t][3]));
        }
        mx0 = fmaxf(mx0, __shfl_xor_sync(0xFFFFFFFFu, mx0, 1));
        mx0 = fmaxf(mx0, __shfl_xor_sync(0xFFFFFFFFu, mx0, 2));
        mx1 = fmaxf(mx1, __shfl_xor_sync(0xFFFFFFFFu, mx1, 1));
        mx1 = fmaxf(mx1, __shfl_xor_sync(0xFFFFFFFFu, mx1, 2));
        const float Mn0 = fmaxf(M0, mx0), Mn1 = fmaxf(M1, mx1);
        const float al0 = __expf(M0 - Mn0), al1 = __expf(M1 - Mn1);
        M0 = Mn0; M1 = Mn1;

        float s0 = 0.f, s1 = 0.f;
        #pragma unroll
        for (int t = 0; t < 16; t++) {
            sacc[t][0] = __expf(sacc[t][0] - M0); s0 += sacc[t][0];
            sacc[t][1] = __expf(sacc[t][1] - M0); s0 += sacc[t][1];
            sacc[t][2] = __expf(sacc[t][2] - M1); s1 += sacc[t][2];
            sacc[t][3] = __expf(sacc[t][3] - M1); s1 += sacc[t][3];
        }
        s0 += __shfl_xor_sync(0xFFFFFFFFu, s0, 1);
        s0 += __shfl_xor_sync(0xFFFFFFFFu, s0, 2);
        s1 += __shfl_xor_sync(0xFFFFFFFFu, s1, 1);
        s1 += __shfl_xor_sync(0xFFFFFFFFu, s1, 2);
        L0 = L0 * al0 + s0;
        L1 = L1 * al1 + s1;
        #pragma unroll
        for (int t = 0; t < 8; t++) {
            oacc[t][0] *= al0; oacc[t][1] *= al0;
            oacc[t][2] *= al1; oacc[t][3] *= al1;
        }

        const uint32_t vb = stb + 16384;
        #pragma unroll
        for (int ks = 0; ks < 8; ks++) {
            float p0 = sacc[2 * ks][0],     p1 = sacc[2 * ks][1];
            float p2 = sacc[2 * ks][2],     p3 = sacc[2 * ks][3];
            float p4 = sacc[2 * ks + 1][0], p5 = sacc[2 * ks + 1][1];
            float p6 = sacc[2 * ks + 1][2], p7 = sacc[2 * ks + 1][3];
            hf h0, l0, h1, l1, h2, l2, h3, l3, h4, l4, h5, l5, h6, l6, h7, l7;
            split_f16(p0, h0, l0); split_f16(p1, h1, l1);
            split_f16(p2, h2, l2); split_f16(p3, h3, l3);
            split_f16(p4, h4, l4); split_f16(p5, h5, l5);
            split_f16(p6, h6, l6); split_f16(p7, h7, l7);
            uint32_t ah[4], alr[4];
            ah[0] = pack_f16x2(h0, h1);  ah[1] = pack_f16x2(h2, h3);
            ah[2] = pack_f16x2(h4, h5);  ah[3] = pack_f16x2(h6, h7);
            alr[0] = pack_f16x2(l0, l1); alr[1] = pack_f16x2(l2, l3);
            alr[2] = pack_f16x2(l4, l5); alr[3] = pack_f16x2(l6, l7);

            const uint32_t vhb = vb + (ks >> 2) * 8192;
            const int ksl = ks & 3;
            #pragma unroll
            for (int ng = 0; ng < 4; ng++) {
                uint32_t rb[4];
                ldmx4(rb, vhb + SWZ((ng * 16 + lrow) * 128 + ksl * 32 + lcol));
                mma_f16(oacc[2 * ng],     ah,  rb[0], rb[2]);
                mma_f16(oacc[2 * ng + 1], ah,  rb[1], rb[3]);
                mma_f16(oacc[2 * ng],     alr, rb[0], rb[2]);
                mma_f16(oacc[2 * ng + 1], alr, rb[1], rb[3]);
            }
        }

        __syncthreads();
        if (i + 2 < FA_NI) loadkv(i + 2, i & 1);
    }

    const float inv0 = 1.f / L0, inv1 = 1.f / L1;
    const int rq = lane >> 2, cq = (lane & 3) * 2;
    const long long base0 = (long long)b * SU_H + (long long)(q0 + mrow + rq) * HID + head * HDIM;
    const long long base1 = base0 + 8LL * HID;
    #pragma unroll
    for (int nt = 0; nt < 8; nt++) {
        const int cn = nt * 8 + cq;
        float v0 = oacc[nt][0] * inv0, v1 = oacc[nt][1] * inv0;
        float v2 = oacc[nt][2] * inv1, v3 = oacc[nt][3] * inv1;
        hf h0, l0, h1, l1, h2, l2, h3, l3;
        split_f16(v0, h0, l0); split_f16(v1, h1, l1);
        split_f16(v2, h2, l2); split_f16(v3, h3, l3);
        *(uint32_t*)(goh + base0 + cn) = pack_f16x2(h0, h1);
        *(uint32_t*)(gol + base0 + cn) = pack_f16x2(l0, l1);
        *(uint32_t*)(goh + base1 + cn) = pack_f16x2(h2, h3);
        *(uint32_t*)(gol + base1 + cn) = pack_f16x2(l2, l3);
    }
}

// ---------------- conversions ----------------
__global__ __launch_bounds__(256) void conv_split2(const float* __restrict__ x,
                                                   hf* __restrict__ hi, hf* __restrict__ lo,
                                                   long long n4)
{
    long long i = (long long)blockIdx.x * 256 + threadIdx.x;
    if (i >= n4) return;
    float4 v = ((const float4*)x)[i];
    hf h0, l0, h1, l1, h2, l2, h3, l3;
    split_f16(v.x, h0, l0); split_f16(v.y, h1, l1);
    split_f16(v.z, h2, l2); split_f16(v.w, h3, l3);
    ((uint32_t*)hi)[i * 2]     = pack_f16x2(h0, h1);
    ((uint32_t*)hi)[i * 2 + 1] = pack_f16x2(h2, h3);
    ((uint32_t*)lo)[i * 2]     = pack_f16x2(l0, l1);
    ((uint32_t*)lo)[i * 2 + 1] = pack_f16x2(l2, l3);
}

__global__ __launch_bounds__(256) void conv_hi(const float* __restrict__ x,
                                               hf* __restrict__ hi, long long n4)
{
    long long i = (long long)blockIdx.x * 256 + threadIdx.x;
    if (i >= n4) return;
    float4 v = ((const float4*)x)[i];
    ((uint32_t*)hi)[i * 2]     = pack_f16x2(__float2half(v.x), __float2half(v.y));
    ((uint32_t*)hi)[i * 2 + 1] = pack_f16x2(__float2half(v.z), __float2half(v.w));
}

// ---------------- transpose + split ----------------
__global__ __launch_bounds__(256) void transpose_split2(
    const float* __restrict__ in, int ldi, long long sI1, long long sI2,
    hf* __restrict__ oh, hf* __restrict__ ol, int ldo, long long sO1, long long sO2,
    int batch2)
{
    __shared__ float t[32][33];
    int z = blockIdx.z, z1 = z / batch2, z2 = z - z1 * batch2;
    in += (long long)z1 * sI1 + (long long)z2 * sI2;
    long long oOff = (long long)z1 * sO1 + (long long)z2 * sO2;
    int r0 = blockIdx.y * 32, c0 = blockIdx.x * 32;
    int tx = threadIdx.x & 31, ty8 = threadIdx.x >> 5;
    #pragma unroll
    for (int i = 0; i < 4; i++) {
        int ty = ty8 + i * 8;
        t[ty][tx] = in[(long long)(r0 + ty) * ldi + c0 + tx];
    }
    __syncthreads();
    #pragma unroll
    for (int i = 0; i < 4; i++) {
        int oy = ty8 + i * 8;
        float v = t[tx][oy];
        hf h, l;
        split_f16(v, h, l);
        long long idx = oOff + (long long)(c0 + oy) * ldo + r0 + tx;
        oh[idx] = h;
        if (ol) ol[idx] = l;
    }
}

// ---------------- rmsnorm + split ----------------
__global__ __launch_bounds__(256) void rmsnorm_split(
    const float* __restrict__ x, const float* __restrict__ w,
    float* __restrict__ y, hf* __restrict__ yh, hf* __restrict__ yl)
{
    __shared__ float red[256];
    long long row = blockIdx.x;
    const float* xr = x + row * HID;
    int tid = threadIdx.x;
    float4 v0 = *(const float4*)(xr + tid * 4);
    float4 v1 = *(const float4*)(xr + 1024 + tid * 4);
    float s = v0.x * v0.x + v0.y * v0.y + v0.z * v0.z + v0.w * v0.w
            + v1.x * v1.x + v1.y * v1.y + v1.z * v1.z + v1.w * v1.w;
    red[tid] = s;
    __syncthreads();
    for (int st = 128; st > 0; st >>= 1) {
        if (tid < st) red[tid] += red[tid + st];
        __syncthreads();
    }
    float inv = rsqrtf(red[0] * (1.f / HID) + EPS_RMS);

    float4 w0 = *(const float4*)(w + tid * 4);
    float4 w1 = *(const float4*)(w + 1024 + tid * 4);
    float o[8];
    o[0] = v0.x * inv * w0.x; o[1] = v0.y * inv * w0.y;
    o[2] = v0.z * inv * w0.z; o[3] = v0.w * inv * w0.w;
    o[4] = v1.x * inv * w1.x; o[5] = v1.y * inv * w1.y;
    o[6] = v1.z * inv * w1.z; o[7] = v1.w * inv * w1.w;
    float* yr = y + row * HID;
    *(float4*)(yr + tid * 4) = make_float4(o[0], o[1], o[2], o[3]);
    *(float4*)(yr + 1024 + tid * 4) = make_float4(o[4], o[5], o[6], o[7]);
    hf* yhr = yh + row * HID;
    hf* ylr = yl + row * HID;
    #pragma unroll
    for (int g = 0; g < 2; g++) {
        hf h0, l0, h1, l1, h2, l2, h3, l3;
        split_f16(o[g * 4 + 0], h0, l0);
        split_f16(o[g * 4 + 1], h1, l1);
        split_f16(o[g * 4 + 2], h2, l2);
        split_f16(o[g * 4 + 3], h3, l3);
        int off = g * 1024 + tid * 4;
        *(uint32_t*)(yhr + off)     = pack_f16x2(h0, h1);
        *(uint32_t*)(yhr + off + 2) = pack_f16x2(h2, h3);
        *(uint32_t*)(ylr + off)     = pack_f16x2(l0, l1);
        *(uint32_t*)(ylr + off + 2) = pack_f16x2(l2, l3);
    }
}

// ---------------- host ----------------
static void* sym(const void* s) {
    void* p = nullptr;
    cudaGetSymbolAddress(&p, s);
    return p;
}

extern "C" void kernel_launch(void* const* d_in, const int* in_sizes, int n_in,
                              void* d_out, int out_size)
{
    const float* h_in = (const float*)d_in[0];
    const float* Wup  = (const float*)d_in[1];
    const float* bup  = (const float*)d_in[2];
    const float* anw  = (const float*)d_in[3];
    const float* Wq   = (const float*)d_in[4];
    const float* Wk   = (const float*)d_in[5];
    const float* Wv   = (const float*)d_in[6];
    const float* Wo   = (const float*)d_in[7];
    const float* mnw  = (const float*)d_in[8];
    const float* Wg   = (const float*)d_in[9];
    const float* Wu   = (const float*)d_in[10];
    const float* Wd   = (const float*)d_in[11];
    float* out = (float*)d_out;

    float* up_   = (float*)sym(g_up);
    float* x1_   = (float*)sym(g_x1);
    float* x2_   = (float*)sym(g_x2);
    float* x3_   = (float*)sym(g_x3);
    float* v_    = (float*)sym(g_v);
    float* gate_ = (float*)sym(g_gate);

    hf *hh = (hf*)sym(f_h_hi),  *hl = (hf*)sym(f_h_lo);
    hf *hth = (hf*)sym(f_ht_hi), *htl = (hf*)sym(f_ht_lo);
    hf *wup = (hf*)sym(f_wup);
    hf *wq = (hf*)sym(f_wq);
    hf *wk = (hf*)sym(f_wk);
    hf *wv = (hf*)sym(f_wv);
    hf *wo = (hf*)sym(f_wo);
    hf *wg = (hf*)sym(f_wg);
    hf *wu = (hf*)sym(f_wu);
    hf *wd = (hf*)sym(f_wd);
    hf *uph = (hf*)sym(f_up_hi), *upl = (hf*)sym(f_up_lo);
    hf *x1h = (hf*)sym(f_x1_hi), *x1l = (hf*)sym(f_x1_lo);
    hf *x3h = (hf*)sym(f_x3_hi), *x3l = (hf*)sym(f_x3_lo);
    hf *qh = (hf*)sym(f_q_hi),   *ql = (hf*)sym(f_q_lo);
    hf *kh = (hf*)sym(f_k_hi);
    hf *oh = (hf*)sym(f_o_hi),   *ol = (hf*)sym(f_o_lo);
    hf *vth = (hf*)sym(f_vt_hi);
    hf *ubh = (hf*)sym(f_ub_hi), *ubl = (hf*)sym(f_ub_lo);

    const int SMEMG  = 1024 + 3 * 32768;            // 99328
    const int SMEMFA = 1024 + 32768 + 2 * 32768;    // 99328
    cudaFuncSetAttribute(mma_gemm, cudaFuncAttributeMaxDynamicSharedMemorySize, SMEMG);
    cudaFuncSetAttribute(flash_attn, cudaFuncAttributeMaxDynamicSharedMemorySize, SMEMFA);

    dim3 blk(256);
    dim3 blkG(128);

    auto convW = [&](const float* x, hf* hi, long long n) {
        conv_hi<<<(unsigned)((n / 4 + 255) / 256), blk>>>(x, hi, n / 4);
    };

    // launches 1-4: minimal prerequisites for two early GEMMs
    conv_split2<<<(unsigned)(HB / 1024), blk>>>(h_in, hh, hl, HB / 4);       // 1
    convW(Wup, wup, WUPN);                                                   // 2
    transpose_split2<<<dim3(HID / 32, S_LEN / 32, BATCH), blk>>>(            // 3
        h_in, HID, S_H, 0, hth, htl, S_LEN, S_H, 0, 1);
    convW(Wk, wk, W1N);                                                      // 4

    // 5) up = Wup @ h (+bias)   <-- ncu capture targets (5th/6th launch)
    mma_gemm<<<dim3(HID / 128, SU_LEN / 128, BATCH), blkG, SMEMG>>>(
        wup, nullptr, S_LEN, 0, 0,
        hth, htl, S_LEN, S_H, 0,
        up_, uph, upl, HID, SU_H, 0,
        bup, nullptr, 0, 0, 0, nullptr,
        S_LEN, 1.f, 1);

    // 6) k (rows 0..S_LEN) = h @ Wk^T
    mma_gemm<<<dim3(HID / 128, S_LEN / 128, BATCH), blkG, SMEMG>>>(
        hh, hl, HID, S_H, 0,
        wk, nullptr, HID, 0, 0,
        nullptr, kh, nullptr, HID, T_H, 0,
        nullptr, nullptr, 0, 0, 0, nullptr,
        HID, 1.f, 1);

    convW(Wq, wq, W1N);
    convW(Wv, wv, W1N);
    convW(Wo, wo, W1N);
    convW(Wg, wg, W2N);
    convW(Wu, wu, W2N);
    convW(Wd, wd, W2N);

    // x1 = rmsnorm(up)
    rmsnorm_split<<<BATCH * SU_LEN, blk>>>(up_, anw, x1_, x1h, x1l);

    // q = x1 @ Wq^T  -> hi/lo
    mma_gemm<<<dim3(HID / 128, SU_LEN / 128, BATCH), blkG, SMEMG>>>(
        x1h, x1l, HID, SU_H, 0,
        wq, nullptr, HID, 0, 0,
        nullptr, qh, ql, HID, SU_H, 0,
        nullptr, nullptr, 0, 0, 0, nullptr,
        HID, 1.f, 1);

    // k (rows S_LEN..) = up @ Wk^T
    mma_gemm<<<dim3(HID / 128, SU_LEN / 128, BATCH), blkG, SMEMG>>>(
        uph, upl, HID, SU_H, 0,
        wk, nullptr, HID, 0, 0,
        nullptr, kh + (long long)S_LEN * HID, nullptr, HID, T_H, 0,
        nullptr, nullptr, 0, 0, 0, nullptr,
        HID, 1.f, 1);

    // v = [h; up] @ Wv^T (fp32), then transpose -> vT hi only
    mma_gemm<<<dim3(HID / 128, S_LEN / 128, BATCH), blkG, SMEMG>>>(
        hh, hl, HID, S_H, 0,
        wv, nullptr, HID, 0, 0,
        v_, nullptr, nullptr, HID, T_H, 0,
        nullptr, nullptr, 0, 0, 0, nullptr,
        HID, 1.f, 1);
    mma_gemm<<<dim3(HID / 128, SU_LEN / 128, BATCH), blkG, SMEMG>>>(
        uph, upl, HID, SU_H, 0,
        wv, nullptr, HID, 0, 0,
        v_ + (long long)S_LEN * HID, nullptr, nullptr, HID, T_H, 0,
        nullptr, nullptr, 0, 0, 0, nullptr,
        HID, 1.f, 1);
    transpose_split2<<<dim3(HDIM / 32, T_LEN / 32, BATCH * NHEAD), blk>>>(
        v_, HID, T_H, HDIM,
        vth, nullptr, T_LEN, T_H, (long long)HDIM * T_LEN, NHEAD);

    // fused flash attention -> o hi/lo
    flash_attn<<<dim3(SU_LEN / 128, BATCH * NHEAD), blk, SMEMFA>>>(
        qh, ql, kh, vth, oh, ol);

    // x2 = o @ Wo^T + x1
    mma_gemm<<<dim3(HID / 128, SU_LEN / 128, BATCH), blkG, SMEMG>>>(
        oh, ol, HID, SU_H, 0,
        wo, nullptr, HID, 0, 0,
        x2_, nullptr, nullptr, HID, SU_H, 0,
        nullptr, x1_, HID, SU_H, 0, nullptr,
        HID, 1.f, 1);

    // x3 = rmsnorm(x2)
    rmsnorm_split<<<BATCH * SU_LEN, blk>>>(x2_, mnw, x3_, x3h, x3l);

    // gate = x3 @ Wg^T (fp32)
    mma_gemm<<<dim3(INTER / 128, SU_LEN / 128, BATCH), blkG, SMEMG>>>(
        x3h, x3l, HID, SU_H, 0,
        wg, nullptr, HID, 0, 0,
        gate_, nullptr, nullptr, INTER, SU_I, 0,
        nullptr, nullptr, 0, 0, 0, nullptr,
        HID, 1.f, 1);

    // ub = silu(gate) * (x3 @ Wu^T) -> hi/lo (fused epilogue)
    mma_gemm<<<dim3(INTER / 128, SU_LEN / 128, BATCH), blkG, SMEMG>>>(
        x3h, x3l, HID, SU_H, 0,
        wu, nullptr, HID, 0, 0,
        nullptr, ubh, ubl, INTER, SU_I, 0,
        nullptr, nullptr, 0, 0, 0, gate_,
        HID, 1.f, 1);

    // out = ub @ Wd^T + x3
    mma_gemm<<<dim3(HID / 128, SU_LEN / 128, BATCH), blkG, SMEMG>>>(
        ubh, ubl, INTER, SU_I, 0,
        wd, nullptr, INTER, 0, 0,
        out, nullptr, nullptr, HID, SU_H, 0,
        nullptr, x3_, HID, SU_H, 0, nullptr,
        INTER, 1.f, 1);
}

// round 8
// speedup vs baseline: 6.4956x; 1.7131x over previous
#include <cuda_runtime.h>
#include <cuda_fp16.h>
#include <cstdint>

// ---------------- problem constants ----------------
#define BATCH 2
#define S_LEN 512
#define HID 2048
#define NHEAD 32
#define HDIM 64
#define SU_LEN 1024
#define T_LEN 1536
#define INTER 5632
#define EPS_RMS 1e-6f

#define S_H   (S_LEN * HID)
#define SU_H  (SU_LEN * HID)
#define T_H   (T_LEN * HID)
#define SU_I  ((long long)SU_LEN * INTER)

#define HB  (BATCH * S_LEN * HID)
#define XB  (BATCH * SU_LEN * HID)
#define KBN (BATCH * T_LEN * HID)
#define UBB ((long long)BATCH * SU_LEN * INTER)
#define WUPN (SU_LEN * S_LEN)
#define W1N  (HID * HID)
#define W2N  (INTER * HID)

typedef __half hf;

// ---------------- scratch (device globals; no runtime allocation) ----------------
__device__ float g_up  [XB];
__device__ float g_x1  [XB];
__device__ float g_x2  [XB];
__device__ float g_x3  [XB];
__device__ float g_v   [KBN];
__device__ float g_gate[UBB];

__device__ hf f_h  [HB];
__device__ hf f_ht [HB];
__device__ hf f_wup[WUPN];
__device__ hf f_wq[W1N];
__device__ hf f_wk[W1N];
__device__ hf f_wv[W1N];
__device__ hf f_wo[W1N];
__device__ hf f_wg[W2N];
__device__ hf f_wu[W2N];
__device__ hf f_wd[W2N];
__device__ hf f_up [XB];
__device__ hf f_x1 [XB];
__device__ hf f_x3 [XB];
__device__ hf f_q  [XB];
__device__ hf f_k  [KBN];
__device__ hf f_o  [XB];
__device__ hf f_vt [KBN];
__device__ hf f_ub [UBB];

// ---------------- PTX helpers ----------------
__device__ __forceinline__ uint32_t smem_u32(const void* p) {
    uint32_t a;
    asm("{ .reg .u64 t; cvta.to.shared.u64 t, %1; cvt.u32.u64 %0, t; }" : "=r"(a) : "l"(p));
    return a;
}
#define SWZ(off) ((off) ^ (((off) >> 3) & 0x70))

#define CP_ASYNC16(dst, src) \
    asm volatile("cp.async.cg.shared.global [%0], [%1], 16;" :: "r"(dst), "l"(src) : "memory")
#define CP_COMMIT() asm volatile("cp.async.commit_group;" ::: "memory")
__device__ __forceinline__ void cp_wait(int allow) {
    if (allow) asm volatile("cp.async.wait_group 1;" ::: "memory");
    else       asm volatile("cp.async.wait_group 0;" ::: "memory");
}

__device__ __forceinline__ void ldmx4(uint32_t* r, uint32_t addr) {
    asm volatile("ldmatrix.sync.aligned.m8n8.x4.shared.b16 {%0,%1,%2,%3}, [%4];"
        : "=r"(r[0]), "=r"(r[1]), "=r"(r[2]), "=r"(r[3]) : "r"(addr));
}

__device__ __forceinline__ void mma_f16(float* d, const uint32_t* a, uint32_t b0, uint32_t b1) {
    asm volatile("mma.sync.aligned.m16n8k16.row.col.f32.f16.f16.f32 "
        "{%0,%1,%2,%3}, {%4,%5,%6,%7}, {%8,%9}, {%0,%1,%2,%3};"
        : "+f"(d[0]), "+f"(d[1]), "+f"(d[2]), "+f"(d[3])
        : "r"(a[0]), "r"(a[1]), "r"(a[2]), "r"(a[3]), "r"(b0), "r"(b1));
}

__device__ __forceinline__ uint32_t pack_f16x2(hf a, hf b) {
    __half2 t;
    t.x = a; t.y = b;
    return *(uint32_t*)&t;
}

// ---------------- mma.sync GEMM (pure fp16, fp32 accumulate) ----------------
// 128 threads, 4 warps in 2x2, warp tile 64x64, CTA tile 128x128, BK=64.
// C[m,n] = alpha * A[m,:]·B[n,:]  (+bias) (+resid) (silu-gate)
__global__ __launch_bounds__(128, 2) void mma_gemm(
    const hf* __restrict__ A0, int lda, long long sA1, long long sA2,
    const hf* __restrict__ B0, int ldb, long long sB1, long long sB2,
    float* __restrict__ C, hf* __restrict__ Chi,
    int ldc, long long sC1, long long sC2,
    const float* __restrict__ bias,
    const float* __restrict__ resid, int ldr, long long sR1, long long sR2,
    const float* __restrict__ gate,
    int K, float alpha, int batch2)
{
    extern __shared__ char smem[];
    const uint32_t sbase = smem_u32(smem);
    const uint32_t tiles = (sbase + 1023u) & ~1023u;
    constexpr int ASZ = 128 * 128;     // 16 KB
    constexpr int BSZ = 128 * 128;
    constexpr int STG = ASZ + BSZ;     // 32 KB per stage

    const int tid = threadIdx.x, wid = tid >> 5, lane = tid & 31;
    const int z = blockIdx.z, z1 = z / batch2, z2 = z - z1 * batch2;
    const hf* A = A0 + (long long)z1 * sA1 + (long long)z2 * sA2;
    const hf* B = B0 + (long long)z1 * sB1 + (long long)z2 * sB2;
    const long long cOff = (long long)z1 * sC1 + (long long)z2 * sC2;
    const int m0 = blockIdx.y * 128, n0 = blockIdx.x * 128;
    const int m0w = (wid & 1) * 64;
    const int n0w = (wid >> 1) * 64;

    const int nc = K >> 6;

    auto load_chunk = [&](int c, int s) {
        const int k0 = c << 6;
        const uint32_t aB = tiles + s * STG;
        const uint32_t bB = aB + ASZ;
        #pragma unroll
        for (int u0 = 0; u0 < 2048; u0 += 128) {
            int u = u0 + tid;
            if (u < 1024) {
                int r = u >> 3, g = u & 7;
                CP_ASYNC16(aB + SWZ(r * 128 + g * 16),
                           A + (long long)(m0 + r) * lda + k0 + g * 8);
            } else {
                int u2 = u - 1024;
                int r = u2 >> 3, g = u2 & 7;
                CP_ASYNC16(bB + SWZ(r * 128 + g * 16),
                           B + (long long)(n0 + r) * ldb + k0 + g * 8);
            }
        }
        CP_COMMIT();
    };

    float acc[4][8][4];
    #pragma unroll
    for (int i = 0; i < 4; i++)
        #pragma unroll
        for (int j = 0; j < 8; j++)
            #pragma unroll
            for (int q = 0; q < 4; q++) acc[i][j][q] = 0.f;

    load_chunk(0, 0);
    if (nc > 1) load_chunk(1, 1);

    const int lrow = lane & 15;
    const int lcol = (lane >> 4) * 16;

    for (int c = 0; c < nc; c++) {
        const int s = c % 3;
        cp_wait(c + 1 < nc ? 1 : 0);
        __syncthreads();
        if (c + 2 < nc) load_chunk(c + 2, (c + 2) % 3);

        const uint32_t aSt = tiles + s * STG;
        const uint32_t bSt = aSt + ASZ;
        #pragma unroll
        for (int ks = 0; ks < 4; ks++) {
            uint32_t ra[4][4];
            #pragma unroll
            for (int mt = 0; mt < 4; mt++)
                ldmx4(ra[mt], aSt + SWZ((m0w + mt * 16 + lrow) * 128 + ks * 32 + lcol));
            #pragma unroll
            for (int ng = 0; ng < 4; ng++) {
                uint32_t rb[4];
                ldmx4(rb, bSt + SWZ((n0w + ng * 16 + lrow) * 128 + ks * 32 + lcol));
                #pragma unroll
                for (int mt = 0; mt < 4; mt++) {
                    mma_f16(acc[mt][2 * ng],     ra[mt], rb[0], rb[2]);
                    mma_f16(acc[mt][2 * ng + 1], ra[mt], rb[1], rb[3]);
                }
            }
        }
        __syncthreads();
    }

    const int rq = lane >> 2;
    const int cq = (lane & 3) * 2;
    #pragma unroll
    for (int mt = 0; mt < 4; mt++) {
        #pragma unroll
        for (int half = 0; half < 2; half++) {
            const int m = m0 + m0w + mt * 16 + rq + half * 8;
            const float bv = bias ? bias[m] : 0.f;
            const long long cBase = cOff + (long long)m * ldc + n0 + n0w;
            const long long rBase = resid ? ((long long)z1 * sR1 + (long long)z2 * sR2 +
                                             (long long)m * ldr + n0 + n0w) : 0;
            #pragma unroll
            for (int nt = 0; nt < 8; nt++) {
                float v0 = acc[mt][nt][half * 2]     * alpha + bv;
                float v1 = acc[mt][nt][half * 2 + 1] * alpha + bv;
                const int cn = nt * 8 + cq;
                if (resid) {
                    v0 += resid[rBase + cn];
                    v1 += resid[rBase + cn + 1];
                }
                if (gate) {
                    float g0 = gate[cBase + cn];
                    float g1 = gate[cBase + cn + 1];
                    v0 *= g0 / (1.f + __expf(-g0));
                    v1 *= g1 / (1.f + __expf(-g1));
                }
                if (C)
                    *(float2*)(C + cBase + cn) = make_float2(v0, v1);
                if (Chi)
                    *(uint32_t*)(Chi + cBase + cn) =
                        pack_f16x2(__float2half(v0), __float2half(v1));
            }
        }
    }
}

// ---------------- fused flash attention (pure fp16) ----------------
#define FA_NI (T_LEN / 128)   // 12

__global__ __launch_bounds__(256, 1) void flash_attn(
    const hf* __restrict__ gq,
    const hf* __restrict__ gk,
    const hf* __restrict__ gv,
    hf* __restrict__ go)
{
    extern __shared__ char smem[];
    const uint32_t sb0 = smem_u32(smem);
    const uint32_t sb = (sb0 + 1023u) & ~1023u;
    const uint32_t Q = sb;
    const uint32_t ST0 = sb + 16384;
    const uint32_t STSZ = 32768;   // per stage: K 16K, V 16K

    const int tid = threadIdx.x, wid = tid >> 5, lane = tid & 31;
    const int q0 = blockIdx.x * 128;
    const int bh = blockIdx.y;
    const int b = bh >> 5, head = bh & 31;

    const hf* qp = gq + (long long)b * SU_H + head * HDIM;
    const hf* kp = gk + (long long)b * T_H + head * HDIM;
    const hf* vp = gv + (long long)b * T_H + (long long)head * HDIM * T_LEN;

    for (int u = tid; u < 1024; u += 256) {
        int r = u >> 3, g = u & 7;
        CP_ASYNC16(Q + SWZ(r * 128 + g * 16), qp + (long long)(q0 + r) * HID + g * 8);
    }
    CP_COMMIT();

    auto loadkv = [&](int ci, int s) {
        const int t0 = ci * 128;
        const uint32_t stb = ST0 + s * STSZ;
        for (int u = tid; u < 2048; u += 256) {
            if (u < 1024) {
                int r = u >> 3, g = u & 7;
                CP_ASYNC16(stb + SWZ(r * 128 + g * 16),
                           kp + (long long)(t0 + r) * HID + g * 8);
            } else {
                int u2 = u - 1024;
                int d = u2 >> 4, gg = u2 & 15;
                CP_ASYNC16(stb + 16384 + (gg >> 3) * 8192 + SWZ(d * 128 + (gg & 7) * 16),
                           vp + (long long)d * T_LEN + t0 + gg * 8);
            }
        }
        CP_COMMIT();
    };

    loadkv(0, 0);
    loadkv(1, 1);
    cp_wait(1);
    __syncthreads();

    const int lrow = lane & 15, lcol = (lane >> 4) * 16;
    const int mrow = wid * 16;
    uint32_t qf[4][4];
    #pragma unroll
    for (int ks = 0; ks < 4; ks++)
        ldmx4(qf[ks], Q + SWZ((mrow + lrow) * 128 + ks * 32 + lcol));

    float oacc[8][4];
    #pragma unroll
    for (int i = 0; i < 8; i++)
        #pragma unroll
        for (int j = 0; j < 4; j++) oacc[i][j] = 0.f;
    float M0 = -1e30f, M1 = -1e30f, L0 = 0.f, L1 = 0.f;

    for (int i = 0; i < FA_NI; i++) {
        const uint32_t stb = ST0 + (i & 1) * STSZ;
        if (i > 0) { cp_wait(i + 1 < FA_NI ? 1 : 0); __syncthreads(); }

        float sacc[16][4];
        #pragma unroll
        for (int t = 0; t < 16; t++)
            #pragma unroll
            for (int j = 0; j < 4; j++) sacc[t][j] = 0.f;

        #pragma unroll
        for (int ks = 0; ks < 4; ks++) {
            #pragma unroll
            for (int ng = 0; ng < 8; ng++) {
                uint32_t rb[4];
                ldmx4(rb, stb + SWZ((ng * 16 + lrow) * 128 + ks * 32 + lcol));
                mma_f16(sacc[2 * ng],     qf[ks], rb[0], rb[2]);
                mma_f16(sacc[2 * ng + 1], qf[ks], rb[1], rb[3]);
            }
        }

        float mx0 = -1e30f, mx1 = -1e30f;
        #pragma unroll
        for (int t = 0; t < 16; t++) {
            sacc[t][0] *= 0.125f; sacc[t][1] *= 0.125f;
            sacc[t][2] *= 0.125f; sacc[t][3] *= 0.125f;
            mx0 = fmaxf(mx0, fmaxf(sacc[t][0], sacc[t][1]));
            mx1 = fmaxf(mx1, fmaxf(sacc[t][2], sacc[t][3]));
        }
        mx0 = fmaxf(mx0, __shfl_xor_sync(0xFFFFFFFFu, mx0, 1));
        mx0 = fmaxf(mx0, __shfl_xor_sync(0xFFFFFFFFu, mx0, 2));
        mx1 = fmaxf(mx1, __shfl_xor_sync(0xFFFFFFFFu, mx1, 1));
        mx1 = fmaxf(mx1, __shfl_xor_sync(0xFFFFFFFFu, mx1, 2));
        const float Mn0 = fmaxf(M0, mx0), Mn1 = fmaxf(M1, mx1);
        const float al0 = __expf(M0 - Mn0), al1 = __expf(M1 - Mn1);
        M0 = Mn0; M1 = Mn1;

        float s0 = 0.f, s1 = 0.f;
        #pragma unroll
        for (int t = 0; t < 16; t++) {
            sacc[t][0] = __expf(sacc[t][0] - M0); s0 += sacc[t][0];
            sacc[t][1] = __expf(sacc[t][1] - M0); s0 += sacc[t][1];
            sacc[t][2] = __expf(sacc[t][2] - M1); s1 += sacc[t][2];
            sacc[t][3] = __expf(sacc[t][3] - M1); s1 += sacc[t][3];
        }
        s0 += __shfl_xor_sync(0xFFFFFFFFu, s0, 1);
        s0 += __shfl_xor_sync(0xFFFFFFFFu, s0, 2);
        s1 += __shfl_xor_sync(0xFFFFFFFFu, s1, 1);
        s1 += __shfl_xor_sync(0xFFFFFFFFu, s1, 2);
        L0 = L0 * al0 + s0;
        L1 = L1 * al1 + s1;
        #pragma unroll
        for (int t = 0; t < 8; t++) {
            oacc[t][0] *= al0; oacc[t][1] *= al0;
            oacc[t][2] *= al1; oacc[t][3] *= al1;
        }

        const uint32_t vb = stb + 16384;
        #pragma unroll
        for (int ks = 0; ks < 8; ks++) {
            uint32_t ah[4];
            ah[0] = pack_f16x2(__float2half(sacc[2 * ks][0]),     __float2half(sacc[2 * ks][1]));
            ah[1] = pack_f16x2(__float2half(sacc[2 * ks][2]),     __float2half(sacc[2 * ks][3]));
            ah[2] = pack_f16x2(__float2half(sacc[2 * ks + 1][0]), __float2half(sacc[2 * ks + 1][1]));
            ah[3] = pack_f16x2(__float2half(sacc[2 * ks + 1][2]), __float2half(sacc[2 * ks + 1][3]));

            const uint32_t vhb = vb + (ks >> 2) * 8192;
            const int ksl = ks & 3;
            #pragma unroll
            for (int ng = 0; ng < 4; ng++) {
                uint32_t rb[4];
                ldmx4(rb, vhb + SWZ((ng * 16 + lrow) * 128 + ksl * 32 + lcol));
                mma_f16(oacc[2 * ng],     ah, rb[0], rb[2]);
                mma_f16(oacc[2 * ng + 1], ah, rb[1], rb[3]);
            }
        }

        __syncthreads();
        if (i + 2 < FA_NI) loadkv(i + 2, i & 1);
    }

    const float inv0 = 1.f / L0, inv1 = 1.f / L1;
    const int rq = lane >> 2, cq = (lane & 3) * 2;
    const long long base0 = (long long)b * SU_H + (long long)(q0 + mrow + rq) * HID + head * HDIM;
    const long long base1 = base0 + 8LL * HID;
    #pragma unroll
    for (int nt = 0; nt < 8; nt++) {
        const int cn = nt * 8 + cq;
        *(uint32_t*)(go + base0 + cn) =
            pack_f16x2(__float2half(oacc[nt][0] * inv0), __float2half(oacc[nt][1] * inv0));
        *(uint32_t*)(go + base1 + cn) =
            pack_f16x2(__float2half(oacc[nt][2] * inv1), __float2half(oacc[nt][3] * inv1));
    }
}

// ---------------- conversions ----------------
__global__ __launch_bounds__(256) void conv_hi(const float* __restrict__ x,
                                               hf* __restrict__ hi, long long n4)
{
    long long i = (long long)blockIdx.x * 256 + threadIdx.x;
    if (i >= n4) return;
    float4 v = ((const float4*)x)[i];
    ((uint32_t*)hi)[i * 2]     = pack_f16x2(__float2half(v.x), __float2half(v.y));
    ((uint32_t*)hi)[i * 2 + 1] = pack_f16x2(__float2half(v.z), __float2half(v.w));
}

// ---------------- transpose -> fp16 ----------------
__global__ __launch_bounds__(256) void transpose_h(
    const float* __restrict__ in, int ldi, long long sI1, long long sI2,
    hf* __restrict__ oh, int ldo, long long sO1, long long sO2,
    int batch2)
{
    __shared__ float t[32][33];
    int z = blockIdx.z, z1 = z / batch2, z2 = z - z1 * batch2;
    in += (long long)z1 * sI1 + (long long)z2 * sI2;
    long long oOff = (long long)z1 * sO1 + (long long)z2 * sO2;
    int r0 = blockIdx.y * 32, c0 = blockIdx.x * 32;
    int tx = threadIdx.x & 31, ty8 = threadIdx.x >> 5;
    #pragma unroll
    for (int i = 0; i < 4; i++) {
        int ty = ty8 + i * 8;
        t[ty][tx] = in[(long long)(r0 + ty) * ldi + c0 + tx];
    }
    __syncthreads();
    #pragma unroll
    for (int i = 0; i < 4; i++) {
        int oy = ty8 + i * 8;
        long long idx = oOff + (long long)(c0 + oy) * ldo + r0 + tx;
        oh[idx] = __float2half(t[tx][oy]);
    }
}

// ---------------- rmsnorm -> fp32 + fp16 ----------------
__global__ __launch_bounds__(256) void rmsnorm_h(
    const float* __restrict__ x, const float* __restrict__ w,
    float* __restrict__ y, hf* __restrict__ yh)
{
    __shared__ float red[256];
    long long row = blockIdx.x;
    const float* xr = x + row * HID;
    int tid = threadIdx.x;
    float4 v0 = *(const float4*)(xr + tid * 4);
    float4 v1 = *(const float4*)(xr + 1024 + tid * 4);
    float s = v0.x * v0.x + v0.y * v0.y + v0.z * v0.z + v0.w * v0.w
            + v1.x * v1.x + v1.y * v1.y + v1.z * v1.z + v1.w * v1.w;
    red[tid] = s;
    __syncthreads();
    for (int st = 128; st > 0; st >>= 1) {
        if (tid < st) red[tid] += red[tid + st];
        __syncthreads();
    }
    float inv = rsqrtf(red[0] * (1.f / HID) + EPS_RMS);

    float4 w0 = *(const float4*)(w + tid * 4);
    float4 w1 = *(const float4*)(w + 1024 + tid * 4);
    float o[8];
    o[0] = v0.x * inv * w0.x; o[1] = v0.y * inv * w0.y;
    o[2] = v0.z * inv * w0.z; o[3] = v0.w * inv * w0.w;
    o[4] = v1.x * inv * w1.x; o[5] = v1.y * inv * w1.y;
    o[6] = v1.z * inv * w1.z; o[7] = v1.w * inv * w1.w;
    float* yr = y + row * HID;
    *(float4*)(yr + tid * 4) = make_float4(o[0], o[1], o[2], o[3]);
    *(float4*)(yr + 1024 + tid * 4) = make_float4(o[4], o[5], o[6], o[7]);
    hf* yhr = yh + row * HID;
    #pragma unroll
    for (int g = 0; g < 2; g++) {
        int off = g * 1024 + tid * 4;
        *(uint32_t*)(yhr + off) =
            pack_f16x2(__float2half(o[g * 4 + 0]), __float2half(o[g * 4 + 1]));
        *(uint32_t*)(yhr + off + 2) =
            pack_f16x2(__float2half(o[g * 4 + 2]), __float2half(o[g * 4 + 3]));
    }
}

// ---------------- host ----------------
static void* sym(const void* s) {
    void* p = nullptr;
    cudaGetSymbolAddress(&p, s);
    return p;
}

extern "C" void kernel_launch(void* const* d_in, const int* in_sizes, int n_in,
                              void* d_out, int out_size)
{
    const float* h_in = (const float*)d_in[0];
    const float* Wup  = (const float*)d_in[1];
    const float* bup  = (const float*)d_in[2];
    const float* anw  = (const float*)d_in[3];
    const float* Wq   = (const float*)d_in[4];
    const float* Wk   = (const float*)d_in[5];
    const float* Wv   = (const float*)d_in[6];
    const float* Wo   = (const float*)d_in[7];
    const float* mnw  = (const float*)d_in[8];
    const float* Wg   = (const float*)d_in[9];
    const float* Wu   = (const float*)d_in[10];
    const float* Wd   = (const float*)d_in[11];
    float* out = (float*)d_out;

    float* up_   = (float*)sym(g_up);
    float* x1_   = (float*)sym(g_x1);
    float* x2_   = (float*)sym(g_x2);
    float* x3_   = (float*)sym(g_x3);
    float* v_    = (float*)sym(g_v);
    float* gate_ = (float*)sym(g_gate);

    hf *hh  = (hf*)sym(f_h);
    hf *hth = (hf*)sym(f_ht);
    hf *wup = (hf*)sym(f_wup);
    hf *wq = (hf*)sym(f_wq);
    hf *wk = (hf*)sym(f_wk);
    hf *wv = (hf*)sym(f_wv);
    hf *wo = (hf*)sym(f_wo);
    hf *wg = (hf*)sym(f_wg);
    hf *wu = (hf*)sym(f_wu);
    hf *wd = (hf*)sym(f_wd);
    hf *uph = (hf*)sym(f_up);
    hf *x1h = (hf*)sym(f_x1);
    hf *x3h = (hf*)sym(f_x3);
    hf *qh = (hf*)sym(f_q);
    hf *kh = (hf*)sym(f_k);
    hf *oh = (hf*)sym(f_o);
    hf *vth = (hf*)sym(f_vt);
    hf *ubh = (hf*)sym(f_ub);

    const int SMEMG  = 1024 + 3 * 32768;            // 99328
    const int SMEMFA = 1024 + 16384 + 2 * 32768;    // 82944
    cudaFuncSetAttribute(mma_gemm, cudaFuncAttributeMaxDynamicSharedMemorySize, SMEMG);
    cudaFuncSetAttribute(flash_attn, cudaFuncAttributeMaxDynamicSharedMemorySize, SMEMFA);

    dim3 blk(256);
    dim3 blkG(128);

    auto convW = [&](const float* x, hf* hi, long long n) {
        conv_hi<<<(unsigned)((n / 4 + 255) / 256), blk>>>(x, hi, n / 4);
    };

    convW(h_in, hh, HB);                                                     // 1
    convW(Wup, wup, WUPN);                                                   // 2
    transpose_h<<<dim3(HID / 32, S_LEN / 32, BATCH), blk>>>(                 // 3
        h_in, HID, S_H, 0, hth, S_LEN, S_H, 0, 1);
    convW(Wk, wk, W1N);                                                      // 4

    // 5) up = Wup @ h (+bias)
    mma_gemm<<<dim3(HID / 128, SU_LEN / 128, BATCH), blkG, SMEMG>>>(
        wup, S_LEN, 0, 0,
        hth, S_LEN, S_H, 0,
        up_, uph, HID, SU_H, 0,
        bup, nullptr, 0, 0, 0, nullptr,
        S_LEN, 1.f, 1);

    // 6) k (rows 0..S_LEN) = h @ Wk^T
    mma_gemm<<<dim3(HID / 128, S_LEN / 128, BATCH), blkG, SMEMG>>>(
        hh, HID, S_H, 0,
        wk, HID, 0, 0,
        nullptr, kh, HID, T_H, 0,
        nullptr, nullptr, 0, 0, 0, nullptr,
        HID, 1.f, 1);

    convW(Wq, wq, W1N);
    convW(Wv, wv, W1N);
    convW(Wo, wo, W1N);
    convW(Wg, wg, W2N);
    convW(Wu, wu, W2N);
    convW(Wd, wd, W2N);

    // x1 = rmsnorm(up)
    rmsnorm_h<<<BATCH * SU_LEN, blk>>>(up_, anw, x1_, x1h);

    // q = x1 @ Wq^T
    mma_gemm<<<dim3(HID / 128, SU_LEN / 128, BATCH), blkG, SMEMG>>>(
        x1h, HID, SU_H, 0,
        wq, HID, 0, 0,
        nullptr, qh, HID, SU_H, 0,
        nullptr, nullptr, 0, 0, 0, nullptr,
        HID, 1.f, 1);

    // k (rows S_LEN..) = up @ Wk^T
    mma_gemm<<<dim3(HID / 128, SU_LEN / 128, BATCH), blkG, SMEMG>>>(
        uph, HID, SU_H, 0,
        wk, HID, 0, 0,
        nullptr, kh + (long long)S_LEN * HID, HID, T_H, 0,
        nullptr, nullptr, 0, 0, 0, nullptr,
        HID, 1.f, 1);

    // v = [h; up] @ Wv^T (fp32), then transpose -> vT fp16
    mma_gemm<<<dim3(HID / 128, S_LEN / 128, BATCH), blkG, SMEMG>>>(
        hh, HID, S_H, 0,
        wv, HID, 0, 0,
        v_, nullptr, HID, T_H, 0,
        nullptr, nullptr, 0, 0, 0, nullptr,
        HID, 1.f, 1);
    mma_gemm<<<dim3(HID / 128, SU_LEN / 128, BATCH), blkG, SMEMG>>>(
        uph, HID, SU_H, 0,
        wv, HID, 0, 0,
        v_ + (long long)S_LEN * HID, nullptr, HID, T_H, 0,
        nullptr, nullptr, 0, 0, 0, nullptr,
        HID, 1.f, 1);
    transpose_h<<<dim3(HDIM / 32, T_LEN / 32, BATCH * NHEAD), blk>>>(
        v_, HID, T_H, HDIM,
        vth, T_LEN, T_H, (long long)HDIM * T_LEN, NHEAD);

    // fused flash attention -> o fp16
    flash_attn<<<dim3(SU_LEN / 128, BATCH * NHEAD), blk, SMEMFA>>>(
        qh, kh, vth, oh);

    // x2 = o @ Wo^T + x1
    mma_gemm<<<dim3(HID / 128, SU_LEN / 128, BATCH), blkG, SMEMG>>>(
        oh, HID, SU_H, 0,
        wo, HID, 0, 0,
        x2_, nullptr, HID, SU_H, 0,
        nullptr, x1_, HID, SU_H, 0, nullptr,
        HID, 1.f, 1);

    // x3 = rmsnorm(x2)
    rmsnorm_h<<<BATCH * SU_LEN, blk>>>(x2_, mnw, x3_, x3h);

    // gate = x3 @ Wg^T (fp32)
    mma_gemm<<<dim3(INTER / 128, SU_LEN / 128, BATCH), blkG, SMEMG>>>(
        x3h, HID, SU_H, 0,
        wg, HID, 0, 0,
        gate_, nullptr, INTER, SU_I, 0,
        nullptr, nullptr, 0, 0, 0, nullptr,
        HID, 1.f, 1);

    // ub = silu(gate) * (x3 @ Wu^T) -> fp16 (fused epilogue)
    mma_gemm<<<dim3(INTER / 128, SU_LEN / 128, BATCH), blkG, SMEMG>>>(
        x3h, HID, SU_H, 0,
        wu, HID, 0, 0,
        nullptr, ubh, INTER, SU_I, 0,
        nullptr, nullptr, 0, 0, 0, gate_,
        HID, 1.f, 1);

    // out = ub @ Wd^T + x3
    mma_gemm<<<dim3(HID / 128, SU_LEN / 128, BATCH), blkG, SMEMG>>>(
        ubh, INTER, SU_I, 0,
        wd, INTER, 0, 0,
        out, nullptr, HID, SU_H, 0,
        nullptr, x3_, HID, SU_H, 0, nullptr,
        INTER, 1.f, 1);
}

// round 9
// speedup vs baseline: 6.8793x; 1.0591x over previous
#include <cuda_runtime.h>
#include <cuda_fp16.h>
#include <cstdint>

// ---------------- problem constants ----------------
#define BATCH 2
#define S_LEN 512
#define HID 2048
#define NHEAD 32
#define HDIM 64
#define SU_LEN 1024
#define T_LEN 1536
#define INTER 5632
#define EPS_RMS 1e-6f

#define S_H   (S_LEN * HID)
#define SU_H  (SU_LEN * HID)
#define T_H   (T_LEN * HID)
#define SU_I  ((long long)SU_LEN * INTER)

#define HB  (BATCH * S_LEN * HID)
#define XB  (BATCH * SU_LEN * HID)
#define KBN (BATCH * T_LEN * HID)
#define UBB ((long long)BATCH * SU_LEN * INTER)
#define WUPN (SU_LEN * S_LEN)
#define W1N  (HID * HID)
#define W2N  (INTER * HID)

typedef __half hf;

// ---------------- scratch (device globals; no runtime allocation) ----------------
__device__ float g_up  [XB];
__device__ float g_x1  [XB];
__device__ float g_x2  [XB];
__device__ float g_x3  [XB];

__device__ hf f_h  [HB];
__device__ hf f_ht [HB];
__device__ hf f_wup[WUPN];
__device__ hf f_wq[W1N];
__device__ hf f_wk[W1N];
__device__ hf f_wv[W1N];
__device__ hf f_wo[W1N];
__device__ hf f_wg[W2N];
__device__ hf f_wu[W2N];
__device__ hf f_wd[W2N];
__device__ hf f_up [XB];
__device__ hf f_x1 [XB];
__device__ hf f_x3 [XB];
__device__ hf f_q  [XB];
__device__ hf f_k  [KBN];
__device__ hf f_v  [KBN];
__device__ hf f_o  [XB];
__device__ hf f_gate[UBB];
__device__ hf f_ub [UBB];

// ---------------- PTX helpers ----------------
__device__ __forceinline__ uint32_t smem_u32(const void* p) {
    uint32_t a;
    asm("{ .reg .u64 t; cvta.to.shared.u64 t, %1; cvt.u32.u64 %0, t; }" : "=r"(a) : "l"(p));
    return a;
}
#define SWZ(off) ((off) ^ (((off) >> 3) & 0x70))

#define CP_ASYNC16(dst, src) \
    asm volatile("cp.async.cg.shared.global [%0], [%1], 16;" :: "r"(dst), "l"(src) : "memory")
#define CP_COMMIT() asm volatile("cp.async.commit_group;" ::: "memory")
__device__ __forceinline__ void cp_wait(int allow) {
    if (allow) asm volatile("cp.async.wait_group 1;" ::: "memory");
    else       asm volatile("cp.async.wait_group 0;" ::: "memory");
}

__device__ __forceinline__ void ldmx4(uint32_t* r, uint32_t addr) {
    asm volatile("ldmatrix.sync.aligned.m8n8.x4.shared.b16 {%0,%1,%2,%3}, [%4];"
        : "=r"(r[0]), "=r"(r[1]), "=r"(r[2]), "=r"(r[3]) : "r"(addr));
}
__device__ __forceinline__ void ldmx4t(uint32_t* r, uint32_t addr) {
    asm volatile("ldmatrix.sync.aligned.m8n8.x4.trans.shared.b16 {%0,%1,%2,%3}, [%4];"
        : "=r"(r[0]), "=r"(r[1]), "=r"(r[2]), "=r"(r[3]) : "r"(addr));
}

__device__ __forceinline__ void mma_f16(float* d, const uint32_t* a, uint32_t b0, uint32_t b1) {
    asm volatile("mma.sync.aligned.m16n8k16.row.col.f32.f16.f16.f32 "
        "{%0,%1,%2,%3}, {%4,%5,%6,%7}, {%8,%9}, {%0,%1,%2,%3};"
        : "+f"(d[0]), "+f"(d[1]), "+f"(d[2]), "+f"(d[3])
        : "r"(a[0]), "r"(a[1]), "r"(a[2]), "r"(a[3]), "r"(b0), "r"(b1));
}

__device__ __forceinline__ uint32_t pack_f16x2(hf a, hf b) {
    __half2 t;
    t.x = a; t.y = b;
    return *(uint32_t*)&t;
}

// ---------------- mma.sync GEMM (pure fp16, fp32 accumulate) ----------------
// 128 threads, 4 warps in 2x2, warp tile 64x64, CTA tile 128x128, BK=64.
__global__ __launch_bounds__(128, 2) void mma_gemm(
    const hf* __restrict__ A0, int lda, long long sA1, long long sA2,
    const hf* __restrict__ B0, int ldb, long long sB1, long long sB2,
    float* __restrict__ C, hf* __restrict__ Chi,
    int ldc, long long sC1, long long sC2,
    const float* __restrict__ bias,
    const float* __restrict__ resid, int ldr, long long sR1, long long sR2,
    const hf* __restrict__ gate,
    int K, float alpha, int batch2)
{
    extern __shared__ char smem[];
    const uint32_t sbase = smem_u32(smem);
    const uint32_t tiles = (sbase + 1023u) & ~1023u;
    constexpr int ASZ = 128 * 128;
    constexpr int BSZ = 128 * 128;
    constexpr int STG = ASZ + BSZ;     // 32 KB per stage

    const int tid = threadIdx.x, wid = tid >> 5, lane = tid & 31;
    const int z = blockIdx.z, z1 = z / batch2, z2 = z - z1 * batch2;
    const hf* A = A0 + (long long)z1 * sA1 + (long long)z2 * sA2;
    const hf* B = B0 + (long long)z1 * sB1 + (long long)z2 * sB2;
    const long long cOff = (long long)z1 * sC1 + (long long)z2 * sC2;
    const int m0 = blockIdx.y * 128, n0 = blockIdx.x * 128;
    const int m0w = (wid & 1) * 64;
    const int n0w = (wid >> 1) * 64;

    const int nc = K >> 6;

    auto load_chunk = [&](int c, int s) {
        const int k0 = c << 6;
        const uint32_t aB = tiles + s * STG;
        const uint32_t bB = aB + ASZ;
        #pragma unroll
        for (int u0 = 0; u0 < 2048; u0 += 128) {
            int u = u0 + tid;
            if (u < 1024) {
                int r = u >> 3, g = u & 7;
                CP_ASYNC16(aB + SWZ(r * 128 + g * 16),
                           A + (long long)(m0 + r) * lda + k0 + g * 8);
            } else {
                int u2 = u - 1024;
                int r = u2 >> 3, g = u2 & 7;
                CP_ASYNC16(bB + SWZ(r * 128 + g * 16),
                           B + (long long)(n0 + r) * ldb + k0 + g * 8);
            }
        }
        CP_COMMIT();
    };

    float acc[4][8][4];
    #pragma unroll
    for (int i = 0; i < 4; i++)
        #pragma unroll
        for (int j = 0; j < 8; j++)
            #pragma unroll
            for (int q = 0; q < 4; q++) acc[i][j][q] = 0.f;

    load_chunk(0, 0);
    if (nc > 1) load_chunk(1, 1);

    const int lrow = lane & 15;
    const int lcol = (lane >> 4) * 16;

    for (int c = 0; c < nc; c++) {
        const int s = c % 3;
        cp_wait(c + 1 < nc ? 1 : 0);
        __syncthreads();
        if (c + 2 < nc) load_chunk(c + 2, (c + 2) % 3);

        const uint32_t aSt = tiles + s * STG;
        const uint32_t bSt = aSt + ASZ;
        #pragma unroll
        for (int ks = 0; ks < 4; ks++) {
            uint32_t ra[4][4];
            #pragma unroll
            for (int mt = 0; mt < 4; mt++)
                ldmx4(ra[mt], aSt + SWZ((m0w + mt * 16 + lrow) * 128 + ks * 32 + lcol));
            #pragma unroll
            for (int ng = 0; ng < 4; ng++) {
                uint32_t rb[4];
                ldmx4(rb, bSt + SWZ((n0w + ng * 16 + lrow) * 128 + ks * 32 + lcol));
                #pragma unroll
                for (int mt = 0; mt < 4; mt++) {
                    mma_f16(acc[mt][2 * ng],     ra[mt], rb[0], rb[2]);
                    mma_f16(acc[mt][2 * ng + 1], ra[mt], rb[1], rb[3]);
                }
            }
        }
        __syncthreads();
    }

    const int rq = lane >> 2;
    const int cq = (lane & 3) * 2;
    #pragma unroll
    for (int mt = 0; mt < 4; mt++) {
        #pragma unroll
        for (int half = 0; half < 2; half++) {
            const int m = m0 + m0w + mt * 16 + rq + half * 8;
            const float bv = bias ? bias[m] : 0.f;
            const long long cBase = cOff + (long long)m * ldc + n0 + n0w;
            const long long rBase = resid ? ((long long)z1 * sR1 + (long long)z2 * sR2 +
                                             (long long)m * ldr + n0 + n0w) : 0;
            #pragma unroll
            for (int nt = 0; nt < 8; nt++) {
                float v0 = acc[mt][nt][half * 2]     * alpha + bv;
                float v1 = acc[mt][nt][half * 2 + 1] * alpha + bv;
                const int cn = nt * 8 + cq;
                if (resid) {
                    v0 += resid[rBase + cn];
                    v1 += resid[rBase + cn + 1];
                }
                if (gate) {
                    __half2 gp = *(const __half2*)(gate + cBase + cn);
                    float g0 = __half2float(gp.x), g1 = __half2float(gp.y);
                    v0 *= g0 / (1.f + __expf(-g0));
                    v1 *= g1 / (1.f + __expf(-g1));
                }
                if (C)
                    *(float2*)(C + cBase + cn) = make_float2(v0, v1);
                if (Chi)
                    *(uint32_t*)(Chi + cBase + cn) =
                        pack_f16x2(__float2half(v0), __float2half(v1));
            }
        }
    }
}

// ---------------- fused flash attention (pure fp16, V in [t,d] layout) ----------------
#define FA_NI (T_LEN / 128)   // 12

__global__ __launch_bounds__(256, 1) void flash_attn(
    const hf* __restrict__ gq,
    const hf* __restrict__ gk,
    const hf* __restrict__ gv,
    hf* __restrict__ go)
{
    extern __shared__ char smem[];
    const uint32_t sb0 = smem_u32(smem);
    const uint32_t sb = (sb0 + 1023u) & ~1023u;
    const uint32_t Q = sb;
    const uint32_t ST0 = sb + 16384;
    const uint32_t STSZ = 32768;   // per stage: K 16K, V 16K

    const int tid = threadIdx.x, wid = tid >> 5, lane = tid & 31;
    const int q0 = blockIdx.x * 128;
    const int bh = blockIdx.y;
    const int b = bh >> 5, head = bh & 31;

    const hf* qp = gq + (long long)b * SU_H + head * HDIM;
    const hf* kp = gk + (long long)b * T_H + head * HDIM;
    const hf* vp = gv + (long long)b * T_H + head * HDIM;

    for (int u = tid; u < 1024; u += 256) {
        int r = u >> 3, g = u & 7;
        CP_ASYNC16(Q + SWZ(r * 128 + g * 16), qp + (long long)(q0 + r) * HID + g * 8);
    }
    CP_COMMIT();

    auto loadkv = [&](int ci, int s) {
        const int t0 = ci * 128;
        const uint32_t stb = ST0 + s * STSZ;
        for (int u = tid; u < 2048; u += 256) {
            if (u < 1024) {
                int r = u >> 3, g = u & 7;
                CP_ASYNC16(stb + SWZ(r * 128 + g * 16),
                           kp + (long long)(t0 + r) * HID + g * 8);
            } else {
                int u2 = u - 1024;
                int r = u2 >> 3, g = u2 & 7;
                CP_ASYNC16(stb + 16384 + SWZ(r * 128 + g * 16),
                           vp + (long long)(t0 + r) * HID + g * 8);
            }
        }
        CP_COMMIT();
    };

    loadkv(0, 0);
    loadkv(1, 1);
    cp_wait(1);
    __syncthreads();

    const int lrow = lane & 15, lcol = (lane >> 4) * 16;
    const int mrow = wid * 16;
    uint32_t qf[4][4];
    #pragma unroll
    for (int ks = 0; ks < 4; ks++)
        ldmx4(qf[ks], Q + SWZ((mrow + lrow) * 128 + ks * 32 + lcol));

    float oacc[8][4];
    #pragma unroll
    for (int i = 0; i < 8; i++)
        #pragma unroll
        for (int j = 0; j < 4; j++) oacc[i][j] = 0.f;
    float M0 = -1e30f, M1 = -1e30f, L0 = 0.f, L1 = 0.f;

    for (int i = 0; i < FA_NI; i++) {
        const uint32_t stb = ST0 + (i & 1) * STSZ;
        if (i > 0) { cp_wait(i + 1 < FA_NI ? 1 : 0); __syncthreads(); }

        float sacc[16][4];
        #pragma unroll
        for (int t = 0; t < 16; t++)
            #pragma unroll
            for (int j = 0; j < 4; j++) sacc[t][j] = 0.f;

        #pragma unroll
        for (int ks = 0; ks < 4; ks++) {
            #pragma unroll
            for (int ng = 0; ng < 8; ng++) {
                uint32_t rb[4];
                ldmx4(rb, stb + SWZ((ng * 16 + lrow) * 128 + ks * 32 + lcol));
                mma_f16(sacc[2 * ng],     qf[ks], rb[0], rb[2]);
                mma_f16(sacc[2 * ng + 1], qf[ks], rb[1], rb[3]);
            }
        }

        float mx0 = -1e30f, mx1 = -1e30f;
        #pragma unroll
        for (int t = 0; t < 16; t++) {
            sacc[t][0] *= 0.125f; sacc[t][1] *= 0.125f;
            sacc[t][2] *= 0.125f; sacc[t][3] *= 0.125f;
            mx0 = fmaxf(mx0, fmaxf(sacc[t][0], sacc[t][1]));
            mx1 = fmaxf(mx1, fmaxf(sacc[t][2], sacc[t][3]));
        }
        mx0 = fmaxf(mx0, __shfl_xor_sync(0xFFFFFFFFu, mx0, 1));
        mx0 = fmaxf(mx0, __shfl_xor_sync(0xFFFFFFFFu, mx0, 2));
        mx1 = fmaxf(mx1, __shfl_xor_sync(0xFFFFFFFFu, mx1, 1));
        mx1 = fmaxf(mx1, __shfl_xor_sync(0xFFFFFFFFu, mx1, 2));
        const float Mn0 = fmaxf(M0, mx0), Mn1 = fmaxf(M1, mx1);
        const float al0 = __expf(M0 - Mn0), al1 = __expf(M1 - Mn1);
        M0 = Mn0; M1 = Mn1;

        float s0 = 0.f, s1 = 0.f;
        #pragma unroll
        for (int t = 0; t < 16; t++) {
            sacc[t][0] = __expf(sacc[t][0] - M0); s0 += sacc[t][0];
            sacc[t][1] = __expf(sacc[t][1] - M0); s0 += sacc[t][1];
            sacc[t][2] = __expf(sacc[t][2] - M1); s1 += sacc[t][2];
            sacc[t][3] = __expf(sacc[t][3] - M1); s1 += sacc[t][3];
        }
        s0 += __shfl_xor_sync(0xFFFFFFFFu, s0, 1);
        s0 += __shfl_xor_sync(0xFFFFFFFFu, s0, 2);
        s1 += __shfl_xor_sync(0xFFFFFFFFu, s1, 1);
        s1 += __shfl_xor_sync(0xFFFFFFFFu, s1, 2);
        L0 = L0 * al0 + s0;
        L1 = L1 * al1 + s1;
        #pragma unroll
        for (int t = 0; t < 8; t++) {
            oacc[t][0] *= al0; oacc[t][1] *= al0;
            oacc[t][2] *= al1; oacc[t][3] *= al1;
        }

        // ---- O += P V  (V in [t,d]; B-fragments via ldmatrix.trans) ----
        const uint32_t vb = stb + 16384;
        #pragma unroll
        for (int ks = 0; ks < 8; ks++) {
            uint32_t ah[4];
            ah[0] = pack_f16x2(__float2half(sacc[2 * ks][0]),     __float2half(sacc[2 * ks][1]));
            ah[1] = pack_f16x2(__float2half(sacc[2 * ks][2]),     __float2half(sacc[2 * ks][3]));
            ah[2] = pack_f16x2(__float2half(sacc[2 * ks + 1][0]), __float2half(sacc[2 * ks + 1][1]));
            ah[3] = pack_f16x2(__float2half(sacc[2 * ks + 1][2]), __float2half(sacc[2 * ks + 1][3]));

            #pragma unroll
            for (int ng = 0; ng < 4; ng++) {
                uint32_t rb[4];
                ldmx4t(rb, vb + SWZ((ks * 16 + lrow) * 128 + ng * 32 + lcol));
                mma_f16(oacc[2 * ng],     ah, rb[0], rb[1]);
                mma_f16(oacc[2 * ng + 1], ah, rb[2], rb[3]);
            }
        }

        __syncthreads();
        if (i + 2 < FA_NI) loadkv(i + 2, i & 1);
    }

    const float inv0 = 1.f / L0, inv1 = 1.f / L1;
    const int rq = lane >> 2, cq = (lane & 3) * 2;
    const long long base0 = (long long)b * SU_H + (long long)(q0 + mrow + rq) * HID + head * HDIM;
    const long long base1 = base0 + 8LL * HID;
    #pragma unroll
    for (int nt = 0; nt < 8; nt++) {
        const int cn = nt * 8 + cq;
        *(uint32_t*)(go + base0 + cn) =
            pack_f16x2(__float2half(oacc[nt][0] * inv0), __float2half(oacc[nt][1] * inv0));
        *(uint32_t*)(go + base1 + cn) =
            pack_f16x2(__float2half(oacc[nt][2] * inv1), __float2half(oacc[nt][3] * inv1));
    }
}

// ---------------- fused multi-buffer fp32->fp16 conversion ----------------
struct ConvJobs {
    const float* src[10];
    hf* dst[10];
    long long n4[10];
    int bstart[11];
};

__global__ __launch_bounds__(256) void conv_multi(ConvJobs J)
{
    int b = blockIdx.x;
    int j = 0;
    #pragma unroll
    for (int t = 0; t < 9; t++)
        if (b >= J.bstart[t + 1]) j = t + 1;
    long long i = (long long)(b - J.bstart[j]) * 256 + threadIdx.x;
    if (i >= J.n4[j]) return;
    float4 v = ((const float4*)J.src[j])[i];
    uint32_t* d = (uint32_t*)J.dst[j];
    d[i * 2]     = pack_f16x2(__float2half(v.x), __float2half(v.y));
    d[i * 2 + 1] = pack_f16x2(__float2half(v.z), __float2half(v.w));
}

// ---------------- transpose -> fp16 ----------------
__global__ __launch_bounds__(256) void transpose_h(
    const float* __restrict__ in, int ldi, long long sI1,
    hf* __restrict__ oh, int ldo, long long sO1)
{
    __shared__ float t[32][33];
    int z = blockIdx.z;
    in += (long long)z * sI1;
    long long oOff = (long long)z * sO1;
    int r0 = blockIdx.y * 32, c0 = blockIdx.x * 32;
    int tx = threadIdx.x & 31, ty8 = threadIdx.x >> 5;
    #pragma unroll
    for (int i = 0; i < 4; i++) {
        int ty = ty8 + i * 8;
        t[ty][tx] = in[(long long)(r0 + ty) * ldi + c0 + tx];
    }
    __syncthreads();
    #pragma unroll
    for (int i = 0; i < 4; i++) {
        int oy = ty8 + i * 8;
        long long idx = oOff + (long long)(c0 + oy) * ldo + r0 + tx;
        oh[idx] = __float2half(t[tx][oy]);
    }
}

// ---------------- rmsnorm -> fp32 + fp16 ----------------
__global__ __launch_bounds__(256) void rmsnorm_h(
    const float* __restrict__ x, const float* __restrict__ w,
    float* __restrict__ y, hf* __restrict__ yh)
{
    __shared__ float red[256];
    long long row = blockIdx.x;
    const float* xr = x + row * HID;
    int tid = threadIdx.x;
    float4 v0 = *(const float4*)(xr + tid * 4);
    float4 v1 = *(const float4*)(xr + 1024 + tid * 4);
    float s = v0.x * v0.x + v0.y * v0.y + v0.z * v0.z + v0.w * v0.w
            + v1.x * v1.x + v1.y * v1.y + v1.z * v1.z + v1.w * v1.w;
    red[tid] = s;
    __syncthreads();
    for (int st = 128; st > 0; st >>= 1) {
        if (tid < st) red[tid] += red[tid + st];
        __syncthreads();
    }
    float inv = rsqrtf(red[0] * (1.f / HID) + EPS_RMS);

    float4 w0 = *(const float4*)(w + tid * 4);
    float4 w1 = *(const float4*)(w + 1024 + tid * 4);
    float o[8];
    o[0] = v0.x * inv * w0.x; o[1] = v0.y * inv * w0.y;
    o[2] = v0.z * inv * w0.z; o[3] = v0.w * inv * w0.w;
    o[4] = v1.x * inv * w1.x; o[5] = v1.y * inv * w1.y;
    o[6] = v1.z * inv * w1.z; o[7] = v1.w * inv * w1.w;
    float* yr = y + row * HID;
    *(float4*)(yr + tid * 4) = make_float4(o[0], o[1], o[2], o[3]);
    *(float4*)(yr + 1024 + tid * 4) = make_float4(o[4], o[5], o[6], o[7]);
    hf* yhr = yh + row * HID;
    #pragma unroll
    for (int g = 0; g < 2; g++) {
        int off = g * 1024 + tid * 4;
        *(uint32_t*)(yhr + off) =
            pack_f16x2(__float2half(o[g * 4 + 0]), __float2half(o[g * 4 + 1]));
        *(uint32_t*)(yhr + off + 2) =
            pack_f16x2(__float2half(o[g * 4 + 2]), __float2half(o[g * 4 + 3]));
    }
}

// ---------------- host ----------------
static void* sym(const void* s) {
    void* p = nullptr;
    cudaGetSymbolAddress(&p, s);
    return p;
}

extern "C" void kernel_launch(void* const* d_in, const int* in_sizes, int n_in,
                              void* d_out, int out_size)
{
    const float* h_in = (const float*)d_in[0];
    const float* Wup  = (const float*)d_in[1];
    const float* bup  = (const float*)d_in[2];
    const float* anw  = (const float*)d_in[3];
    const float* Wq   = (const float*)d_in[4];
    const float* Wk   = (const float*)d_in[5];
    const float* Wv   = (const float*)d_in[6];
    const float* Wo   = (const float*)d_in[7];
    const float* mnw  = (const float*)d_in[8];
    const float* Wg   = (const float*)d_in[9];
    const float* Wu   = (const float*)d_in[10];
    const float* Wd   = (const float*)d_in[11];
    float* out = (float*)d_out;

    float* up_ = (float*)sym(g_up);
    float* x1_ = (float*)sym(g_x1);
    float* x2_ = (float*)sym(g_x2);
    float* x3_ = (float*)sym(g_x3);

    hf *hh  = (hf*)sym(f_h);
    hf *hth = (hf*)sym(f_ht);
    hf *wup = (hf*)sym(f_wup);
    hf *wq = (hf*)sym(f_wq);
    hf *wk = (hf*)sym(f_wk);
    hf *wv = (hf*)sym(f_wv);
    hf *wo = (hf*)sym(f_wo);
    hf *wg = (hf*)sym(f_wg);
    hf *wu = (hf*)sym(f_wu);
    hf *wd = (hf*)sym(f_wd);
    hf *uph = (hf*)sym(f_up);
    hf *x1h = (hf*)sym(f_x1);
    hf *x3h = (hf*)sym(f_x3);
    hf *qh = (hf*)sym(f_q);
    hf *kh = (hf*)sym(f_k);
    hf *vh = (hf*)sym(f_v);
    hf *oh = (hf*)sym(f_o);
    hf *gate16 = (hf*)sym(f_gate);
    hf *ubh = (hf*)sym(f_ub);

    const int SMEMG  = 1024 + 3 * 32768;            // 99328
    const int SMEMFA = 1024 + 16384 + 2 * 32768;    // 82944
    cudaFuncSetAttribute(mma_gemm, cudaFuncAttributeMaxDynamicSharedMemorySize, SMEMG);
    cudaFuncSetAttribute(flash_attn, cudaFuncAttributeMaxDynamicSharedMemorySize, SMEMFA);

    dim3 blk(256);
    dim3 blkG(128);

    // 1) all fp32->fp16 conversions in one launch
    {
        ConvJobs J;
        const float* srcs[10] = { h_in, Wup, Wq, Wk, Wv, Wo, Wg, Wu, Wd, nullptr };
        hf* dsts[10] = { hh, wup, wq, wk, wv, wo, wg, wu, wd, nullptr };
        long long ns[10] = { HB, WUPN, W1N, W1N, W1N, W1N, W2N, W2N, W2N, 0 };
        int cum = 0;
        for (int j = 0; j < 10; j++) {
            J.src[j] = srcs[j];
            J.dst[j] = dsts[j];
            J.n4[j] = ns[j] / 4;
            J.bstart[j] = cum;
            cum += (int)((J.n4[j] + 255) / 256);
        }
        J.bstart[10] = cum;
        conv_multi<<<cum, blk>>>(J);
    }

    // 2) h [S,H] -> hT [H,S] per batch
    transpose_h<<<dim3(HID / 32, S_LEN / 32, BATCH), blk>>>(
        h_in, HID, S_H, hth, S_LEN, S_H);

    // 3) up = Wup @ hT (+bias)
    mma_gemm<<<dim3(HID / 128, SU_LEN / 128, BATCH), blkG, SMEMG>>>(
        wup, S_LEN, 0, 0,
        hth, S_LEN, S_H, 0,
        up_, uph, HID, SU_H, 0,
        bup, nullptr, 0, 0, 0, nullptr,
        S_LEN, 1.f, 1);

    // 4) k (rows 0..S) = h @ Wk^T
    mma_gemm<<<dim3(HID / 128, S_LEN / 128, BATCH), blkG, SMEMG>>>(
        hh, HID, S_H, 0,
        wk, HID, 0, 0,
        nullptr, kh, HID, T_H, 0,
        nullptr, nullptr, 0, 0, 0, nullptr,
        HID, 1.f, 1);

    // 5) v (rows 0..S) = h @ Wv^T -> fp16 [t,d]
    mma_gemm<<<dim3(HID / 128, S_LEN / 128, BATCH), blkG, SMEMG>>>(
        hh, HID, S_H, 0,
        wv, HID, 0, 0,
        nullptr, vh, HID, T_H, 0,
        nullptr, nullptr, 0, 0, 0, nullptr,
        HID, 1.f, 1);

    // 6) x1 = rmsnorm(up)
    rmsnorm_h<<<BATCH * SU_LEN, blk>>>(up_, anw, x1_, x1h);

    // 7) q = x1 @ Wq^T
    mma_gemm<<<dim3(HID / 128, SU_LEN / 128, BATCH), blkG, SMEMG>>>(
        x1h, HID, SU_H, 0,
        wq, HID, 0, 0,
        nullptr, qh, HID, SU_H, 0,
        nullptr, nullptr, 0, 0, 0, nullptr,
        HID, 1.f, 1);

    // 8) k (rows S..) = up @ Wk^T
    mma_gemm<<<dim3(HID / 128, SU_LEN / 128, BATCH), blkG, SMEMG>>>(
        uph, HID, SU_H, 0,
        wk, HID, 0, 0,
        nullptr, kh + (long long)S_LEN * HID, HID, T_H, 0,
        nullptr, nullptr, 0, 0, 0, nullptr,
        HID, 1.f, 1);

    // 9) v (rows S..) = up @ Wv^T
    mma_gemm<<<dim3(HID / 128, SU_LEN / 128, BATCH), blkG, SMEMG>>>(
        uph, HID, SU_H, 0,
        wv, HID, 0, 0,
        nullptr, vh + (long long)S_LEN * HID, HID, T_H, 0,
        nullptr, nullptr, 0, 0, 0, nullptr,
        HID, 1.f, 1);

    // 10) fused flash attention -> o fp16
    flash_attn<<<dim3(SU_LEN / 128, BATCH * NHEAD), blk, SMEMFA>>>(
        qh, kh, vh, oh);

    // 11) x2 = o @ Wo^T + x1
    mma_gemm<<<dim3(HID / 128, SU_LEN / 128, BATCH), blkG, SMEMG>>>(
        oh, HID, SU_H, 0,
        wo, HID, 0, 0,
        x2_, nullptr, HID, SU_H, 0,
        nullptr, x1_, HID, SU_H, 0, nullptr,
        HID, 1.f, 1);

    // 12) x3 = rmsnorm(x2)
    rmsnorm_h<<<BATCH * SU_LEN, blk>>>(x2_, mnw, x3_, x3h);

    // 13) gate = x3 @ Wg^T -> fp16
    mma_gemm<<<dim3(INTER / 128, SU_LEN / 128, BATCH), blkG, SMEMG>>>(
        x3h, HID, SU_H, 0,
        wg, HID, 0, 0,
        nullptr, gate16, INTER, SU_I, 0,
        nullptr, nullptr, 0, 0, 0, nullptr,
        HID, 1.f, 1);

    // 14) ub = silu(gate) * (x3 @ Wu^T) -> fp16
    mma_gemm<<<dim3(INTER / 128, SU_LEN / 128, BATCH), blkG, SMEMG>>>(
        x3h, HID, SU_H, 0,
        wu, HID, 0, 0,
        nullptr, ubh, INTER, SU_I, 0,
        nullptr, nullptr, 0, 0, 0, gate16,
        HID, 1.f, 1);

    // 15) out = ub @ Wd^T + x3
    mma_gemm<<<dim3(HID / 128, SU_LEN / 128, BATCH), blkG, SMEMG>>>(
        ubh, INTER, SU_I, 0,
        wd, INTER, 0, 0,
        out, nullptr, HID, SU_H, 0,
        nullptr, x3_, HID, SU_H, 0, nullptr,
        INTER, 1.f, 1);
}

// round 10
// speedup vs baseline: 7.1293x; 1.0363x over previous
#include <cuda_runtime.h>
#include <cuda_fp16.h>
#include <cstdint>

// ---------------- problem constants ----------------
#define BATCH 2
#define S_LEN 512
#define HID 2048
#define NHEAD 32
#define HDIM 64
#define SU_LEN 1024
#define T_LEN 1536
#define INTER 5632
#define EPS_RMS 1e-6f

#define S_H   (S_LEN * HID)
#define SU_H  (SU_LEN * HID)
#define T_H   (T_LEN * HID)
#define SU_I  ((long long)SU_LEN * INTER)

#define HB  (BATCH * S_LEN * HID)
#define XB  (BATCH * SU_LEN * HID)
#define KBN (BATCH * T_LEN * HID)
#define UBB ((long long)BATCH * SU_LEN * INTER)
#define WUPN (SU_LEN * S_LEN)
#define W1N  (HID * HID)
#define W2N  (INTER * HID)

typedef __half hf;

// ---------------- scratch (device globals; no runtime allocation) ----------------
__device__ float g_up  [XB];
__device__ float g_x1  [XB];
__device__ float g_x2  [XB];
__device__ float g_x3  [XB];

__device__ hf f_h  [HB];
__device__ hf f_ht [HB];
__device__ hf f_wup[WUPN];
__device__ hf f_wqkv[3 * W1N];   // [Wq; Wk; Wv] rows
__device__ hf f_wo[W1N];
__device__ hf f_wg[W2N];
__device__ hf f_wu[W2N];
__device__ hf f_wd[W2N];
__device__ hf f_up [XB];
__device__ hf f_x1 [XB];
__device__ hf f_x3 [XB];
__device__ hf f_q  [XB];
__device__ hf f_k  [KBN];
__device__ hf f_v  [KBN];
__device__ hf f_o  [XB];
__device__ hf f_gate[UBB];
__device__ hf f_ub [UBB];

// ---------------- PTX helpers ----------------
__device__ __forceinline__ uint32_t smem_u32(const void* p) {
    uint32_t a;
    asm("{ .reg .u64 t; cvta.to.shared.u64 t, %1; cvt.u32.u64 %0, t; }" : "=r"(a) : "l"(p));
    return a;
}
#define SWZ(off) ((off) ^ (((off) >> 3) & 0x70))

#define CP_ASYNC16(dst, src) \
    asm volatile("cp.async.cg.shared.global [%0], [%1], 16;" :: "r"(dst), "l"(src) : "memory")
#define CP_COMMIT() asm volatile("cp.async.commit_group;" ::: "memory")
__device__ __forceinline__ void cp_wait(int allow) {
    if (allow) asm volatile("cp.async.wait_group 1;" ::: "memory");
    else       asm volatile("cp.async.wait_group 0;" ::: "memory");
}

__device__ __forceinline__ void ldmx4(uint32_t* r, uint32_t addr) {
    asm volatile("ldmatrix.sync.aligned.m8n8.x4.shared.b16 {%0,%1,%2,%3}, [%4];"
        : "=r"(r[0]), "=r"(r[1]), "=r"(r[2]), "=r"(r[3]) : "r"(addr));
}
__device__ __forceinline__ void ldmx4t(uint32_t* r, uint32_t addr) {
    asm volatile("ldmatrix.sync.aligned.m8n8.x4.trans.shared.b16 {%0,%1,%2,%3}, [%4];"
        : "=r"(r[0]), "=r"(r[1]), "=r"(r[2]), "=r"(r[3]) : "r"(addr));
}

__device__ __forceinline__ void mma_f16(float* d, const uint32_t* a, uint32_t b0, uint32_t b1) {
    asm volatile("mma.sync.aligned.m16n8k16.row.col.f32.f16.f16.f32 "
        "{%0,%1,%2,%3}, {%4,%5,%6,%7}, {%8,%9}, {%0,%1,%2,%3};"
        : "+f"(d[0]), "+f"(d[1]), "+f"(d[2]), "+f"(d[3])
        : "r"(a[0]), "r"(a[1]), "r"(a[2]), "r"(a[3]), "r"(b0), "r"(b1));
}

__device__ __forceinline__ uint32_t pack_f16x2(hf a, hf b) {
    __half2 t;
    t.x = a; t.y = b;
    return *(uint32_t*)&t;
}

// ---------------- mma.sync GEMM (pure fp16, fp32 accumulate) ----------------
// 128 threads, 4 warps in 2x2, warp tile 64x64, CTA tile 128x128, BK=64.
// Batched over grid.z (stride sA1/sB1/sC1 or per-segment strides).
// If s0 != null: segmented fp16 output — columns [0,2048) -> s0, [2048,4096) -> s1.
__global__ __launch_bounds__(128, 2) void mma_gemm(
    const hf* __restrict__ A0, int lda, long long sA1,
    const hf* __restrict__ B0, int ldb, long long sB1,
    float* __restrict__ C, hf* __restrict__ Chi, int ldc, long long sC1,
    const float* __restrict__ bias,
    const float* __restrict__ resid, int ldr, long long sR1,
    const hf* __restrict__ gate,
    hf* __restrict__ s0, long long ss0,
    hf* __restrict__ s1, long long ss1,
    int K, float alpha)
{
    extern __shared__ char smem[];
    const uint32_t sbase = smem_u32(smem);
    const uint32_t tiles = (sbase + 1023u) & ~1023u;
    constexpr int ASZ = 128 * 128;
    constexpr int STG = 2 * ASZ;       // 32 KB per stage

    const int tid = threadIdx.x, wid = tid >> 5, lane = tid & 31;
    const int z = blockIdx.z;
    const hf* A = A0 + (long long)z * sA1;
    const hf* B = B0 + (long long)z * sB1;
    const int m0 = blockIdx.y * 128, n0 = blockIdx.x * 128;
    const int m0w = (wid & 1) * 64;
    const int n0w = (wid >> 1) * 64;

    const int nc = K >> 6;

    auto load_chunk = [&](int c, int s) {
        const int k0 = c << 6;
        const uint32_t aB = tiles + s * STG;
        const uint32_t bB = aB + ASZ;
        #pragma unroll
        for (int u0 = 0; u0 < 2048; u0 += 128) {
            int u = u0 + tid;
            if (u < 1024) {
                int r = u >> 3, g = u & 7;
                CP_ASYNC16(aB + SWZ(r * 128 + g * 16),
                           A + (long long)(m0 + r) * lda + k0 + g * 8);
            } else {
                int u2 = u - 1024;
                int r = u2 >> 3, g = u2 & 7;
                CP_ASYNC16(bB + SWZ(r * 128 + g * 16),
                           B + (long long)(n0 + r) * ldb + k0 + g * 8);
            }
        }
        CP_COMMIT();
    };

    float acc[4][8][4];
    #pragma unroll
    for (int i = 0; i < 4; i++)
        #pragma unroll
        for (int j = 0; j < 8; j++)
            #pragma unroll
            for (int q = 0; q < 4; q++) acc[i][j][q] = 0.f;

    load_chunk(0, 0);
    if (nc > 1) load_chunk(1, 1);

    const int lrow = lane & 15;
    const int lcol = (lane >> 4) * 16;

    for (int c = 0; c < nc; c++) {
        const int s = c % 3;
        cp_wait(c + 1 < nc ? 1 : 0);
        __syncthreads();
        if (c + 2 < nc) load_chunk(c + 2, (c + 2) % 3);

        const uint32_t aSt = tiles + s * STG;
        const uint32_t bSt = aSt + ASZ;
        #pragma unroll
        for (int ks = 0; ks < 4; ks++) {
            uint32_t ra[4][4];
            #pragma unroll
            for (int mt = 0; mt < 4; mt++)
                ldmx4(ra[mt], aSt + SWZ((m0w + mt * 16 + lrow) * 128 + ks * 32 + lcol));
            uint32_t rb[2][4];
            ldmx4(rb[0], bSt + SWZ((n0w + lrow) * 128 + ks * 32 + lcol));
            #pragma unroll
            for (int ng = 0; ng < 4; ng++) {
                if (ng < 3)
                    ldmx4(rb[(ng + 1) & 1],
                          bSt + SWZ((n0w + (ng + 1) * 16 + lrow) * 128 + ks * 32 + lcol));
                const uint32_t* rbc = rb[ng & 1];
                #pragma unroll
                for (int mt = 0; mt < 4; mt++) {
                    mma_f16(acc[mt][2 * ng],     ra[mt], rbc[0], rbc[2]);
                    mma_f16(acc[mt][2 * ng + 1], ra[mt], rbc[1], rbc[3]);
                }
            }
        }
        __syncthreads();
    }

    // ---- epilogue ----
    hf* hOut;
    float* fOut;
    long long cAdj;
    if (s0) {
        const int seg = n0 >> 11;               // 2048-column segments
        hf* sp = seg ? s1 : s0;
        const long long st = seg ? ss1 : ss0;
        hOut = sp;
        fOut = nullptr;
        cAdj = (long long)z * st - ((long long)seg << 11);
    } else {
        hOut = Chi;
        fOut = C;
        cAdj = (long long)z * sC1;
    }

    const int rq = lane >> 2;
    const int cq = (lane & 3) * 2;
    #pragma unroll
    for (int mt = 0; mt < 4; mt++) {
        #pragma unroll
        for (int half = 0; half < 2; half++) {
            const int m = m0 + m0w + mt * 16 + rq + half * 8;
            const float bv = bias ? bias[m] : 0.f;
            const long long cBase = cAdj + (long long)m * ldc + n0 + n0w;
            const long long rBase = resid ? ((long long)z * sR1 +
                                             (long long)m * ldr + n0 + n0w) : 0;
            #pragma unroll
            for (int nt = 0; nt < 8; nt++) {
                float v0 = acc[mt][nt][half * 2]     * alpha + bv;
                float v1 = acc[mt][nt][half * 2 + 1] * alpha + bv;
                const int cn = nt * 8 + cq;
                if (resid) {
                    v0 += resid[rBase + cn];
                    v1 += resid[rBase + cn + 1];
                }
                if (gate) {
                    __half2 gp = *(const __half2*)(gate + cBase + cn);
                    float g0 = __half2float(gp.x), g1 = __half2float(gp.y);
                    v0 *= g0 / (1.f + __expf(-g0));
                    v1 *= g1 / (1.f + __expf(-g1));
                }
                if (fOut)
                    *(float2*)(fOut + cBase + cn) = make_float2(v0, v1);
                if (hOut)
                    *(uint32_t*)(hOut + cBase + cn) =
                        pack_f16x2(__float2half(v0), __float2half(v1));
            }
        }
    }
}

// ---------------- fused flash attention (pure fp16, V in [t,d] layout) ----------------
#define FA_NI (T_LEN / 128)   // 12

__global__ __launch_bounds__(256, 1) void flash_attn(
    const hf* __restrict__ gq,
    const hf* __restrict__ gk,
    const hf* __restrict__ gv,
    hf* __restrict__ go)
{
    extern __shared__ char smem[];
    const uint32_t sb0 = smem_u32(smem);
    const uint32_t sb = (sb0 + 1023u) & ~1023u;
    const uint32_t Q = sb;
    const uint32_t ST0 = sb + 16384;
    const uint32_t STSZ = 32768;   // per stage: K 16K, V 16K

    const int tid = threadIdx.x, wid = tid >> 5, lane = tid & 31;
    const int q0 = blockIdx.x * 128;
    const int bh = blockIdx.y;
    const int b = bh >> 5, head = bh & 31;

    const hf* qp = gq + (long long)b * SU_H + head * HDIM;
    const hf* kp = gk + (long long)b * T_H + head * HDIM;
    const hf* vp = gv + (long long)b * T_H + head * HDIM;

    for (int u = tid; u < 1024; u += 256) {
        int r = u >> 3, g = u & 7;
        CP_ASYNC16(Q + SWZ(r * 128 + g * 16), qp + (long long)(q0 + r) * HID + g * 8);
    }
    CP_COMMIT();

    auto loadkv = [&](int ci, int s) {
        const int t0 = ci * 128;
        const uint32_t stb = ST0 + s * STSZ;
        for (int u = tid; u < 2048; u += 256) {
            if (u < 1024) {
                int r = u >> 3, g = u & 7;
                CP_ASYNC16(stb + SWZ(r * 128 + g * 16),
                           kp + (long long)(t0 + r) * HID + g * 8);
            } else {
                int u2 = u - 1024;
                int r = u2 >> 3, g = u2 & 7;
                CP_ASYNC16(stb + 16384 + SWZ(r * 128 + g * 16),
                           vp + (long long)(t0 + r) * HID + g * 8);
            }
        }
        CP_COMMIT();
    };

    loadkv(0, 0);
    loadkv(1, 1);
    cp_wait(1);
    __syncthreads();

    const int lrow = lane & 15, lcol = (lane >> 4) * 16;
    const int mrow = wid * 16;
    uint32_t qf[4][4];
    #pragma unroll
    for (int ks = 0; ks < 4; ks++)
        ldmx4(qf[ks], Q + SWZ((mrow + lrow) * 128 + ks * 32 + lcol));

    float oacc[8][4];
    #pragma unroll
    for (int i = 0; i < 8; i++)
        #pragma unroll
        for (int j = 0; j < 4; j++) oacc[i][j] = 0.f;
    float M0 = -1e30f, M1 = -1e30f, L0 = 0.f, L1 = 0.f;

    for (int i = 0; i < FA_NI; i++) {
        const uint32_t stb = ST0 + (i & 1) * STSZ;
        if (i > 0) { cp_wait(i + 1 < FA_NI ? 1 : 0); __syncthreads(); }

        float sacc[16][4];
        #pragma unroll
        for (int t = 0; t < 16; t++)
            #pragma unroll
            for (int j = 0; j < 4; j++) sacc[t][j] = 0.f;

        #pragma unroll
        for (int ks = 0; ks < 4; ks++) {
            #pragma unroll
            for (int ng = 0; ng < 8; ng++) {
                uint32_t rb[4];
                ldmx4(rb, stb + SWZ((ng * 16 + lrow) * 128 + ks * 32 + lcol));
                mma_f16(sacc[2 * ng],     qf[ks], rb[0], rb[2]);
                mma_f16(sacc[2 * ng + 1], qf[ks], rb[1], rb[3]);
            }
        }

        float mx0 = -1e30f, mx1 = -1e30f;
        #pragma unroll
        for (int t = 0; t < 16; t++) {
            sacc[t][0] *= 0.125f; sacc[t][1] *= 0.125f;
            sacc[t][2] *= 0.125f; sacc[t][3] *= 0.125f;
            mx0 = fmaxf(mx0, fmaxf(sacc[t][0], sacc[t][1]));
            mx1 = fmaxf(mx1, fmaxf(sacc[t][2], sacc[t][3]));
        }
        mx0 = fmaxf(mx0, __shfl_xor_sync(0xFFFFFFFFu, mx0, 1));
        mx0 = fmaxf(mx0, __shfl_xor_sync(0xFFFFFFFFu, mx0, 2));
        mx1 = fmaxf(mx1, __shfl_xor_sync(0xFFFFFFFFu, mx1, 1));
        mx1 = fmaxf(mx1, __shfl_xor_sync(0xFFFFFFFFu, mx1, 2));
        const float Mn0 = fmaxf(M0, mx0), Mn1 = fmaxf(M1, mx1);
        const float al0 = __expf(M0 - Mn0), al1 = __expf(M1 - Mn1);
        M0 = Mn0; M1 = Mn1;

        float s0 = 0.f, s1 = 0.f;
        #pragma unroll
        for (int t = 0; t < 16; t++) {
            sacc[t][0] = __expf(sacc[t][0] - M0); s0 += sacc[t][0];
            sacc[t][1] = __expf(sacc[t][1] - M0); s0 += sacc[t][1];
            sacc[t][2] = __expf(sacc[t][2] - M1); s1 += sacc[t][2];
            sacc[t][3] = __expf(sacc[t][3] - M1); s1 += sacc[t][3];
        }
        s0 += __shfl_xor_sync(0xFFFFFFFFu, s0, 1);
        s0 += __shfl_xor_sync(0xFFFFFFFFu, s0, 2);
        s1 += __shfl_xor_sync(0xFFFFFFFFu, s1, 1);
        s1 += __shfl_xor_sync(0xFFFFFFFFu, s1, 2);
        L0 = L0 * al0 + s0;
        L1 = L1 * al1 + s1;
        #pragma unroll
        for (int t = 0; t < 8; t++) {
            oacc[t][0] *= al0; oacc[t][1] *= al0;
            oacc[t][2] *= al1; oacc[t][3] *= al1;
        }

        const uint32_t vb = stb + 16384;
        #pragma unroll
        for (int ks = 0; ks < 8; ks++) {
            uint32_t ah[4];
            ah[0] = pack_f16x2(__float2half(sacc[2 * ks][0]),     __float2half(sacc[2 * ks][1]));
            ah[1] = pack_f16x2(__float2half(sacc[2 * ks][2]),     __float2half(sacc[2 * ks][3]));
            ah[2] = pack_f16x2(__float2half(sacc[2 * ks + 1][0]), __float2half(sacc[2 * ks + 1][1]));
            ah[3] = pack_f16x2(__float2half(sacc[2 * ks + 1][2]), __float2half(sacc[2 * ks + 1][3]));

            #pragma unroll
            for (int ng = 0; ng < 4; ng++) {
                uint32_t rb[4];
                ldmx4t(rb, vb + SWZ((ks * 16 + lrow) * 128 + ng * 32 + lcol));
                mma_f16(oacc[2 * ng],     ah, rb[0], rb[1]);
                mma_f16(oacc[2 * ng + 1], ah, rb[2], rb[3]);
            }
        }

        __syncthreads();
        if (i + 2 < FA_NI) loadkv(i + 2, i & 1);
    }

    const float inv0 = 1.f / L0, inv1 = 1.f / L1;
    const int rq = lane >> 2, cq = (lane & 3) * 2;
    const long long base0 = (long long)b * SU_H + (long long)(q0 + mrow + rq) * HID + head * HDIM;
    const long long base1 = base0 + 8LL * HID;
    #pragma unroll
    for (int nt = 0; nt < 8; nt++) {
        const int cn = nt * 8 + cq;
        *(uint32_t*)(go + base0 + cn) =
            pack_f16x2(__float2half(oacc[nt][0] * inv0), __float2half(oacc[nt][1] * inv0));
        *(uint32_t*)(go + base1 + cn) =
            pack_f16x2(__float2half(oacc[nt][2] * inv1), __float2half(oacc[nt][3] * inv1));
    }
}

// ---------------- fused multi-buffer fp32->fp16 conversion ----------------
struct ConvJobs {
    const float* src[10];
    hf* dst[10];
    long long n4[10];
    int bstart[11];
};

__global__ __launch_bounds__(256) void conv_multi(ConvJobs J)
{
    int b = blockIdx.x;
    int j = 0;
    #pragma unroll
    for (int t = 0; t < 9; t++)
        if (b >= J.bstart[t + 1]) j = t + 1;
    long long i = (long long)(b - J.bstart[j]) * 256 + threadIdx.x;
    if (i >= J.n4[j]) return;
    float4 v = ((const float4*)J.src[j])[i];
    uint32_t* d = (uint32_t*)J.dst[j];
    d[i * 2]     = pack_f16x2(__float2half(v.x), __float2half(v.y));
    d[i * 2 + 1] = pack_f16x2(__float2half(v.z), __float2half(v.w));
}

// ---------------- transpose -> fp16 ----------------
__global__ __launch_bounds__(256) void transpose_h(
    const float* __restrict__ in, int ldi, long long sI1,
    hf* __restrict__ oh, int ldo, long long sO1)
{
    __shared__ float t[32][33];
    int z = blockIdx.z;
    in += (long long)z * sI1;
    long long oOff = (long long)z * sO1;
    int r0 = blockIdx.y * 32, c0 = blockIdx.x * 32;
    int tx = threadIdx.x & 31, ty8 = threadIdx.x >> 5;
    #pragma unroll
    for (int i = 0; i < 4; i++) {
        int ty = ty8 + i * 8;
        t[ty][tx] = in[(long long)(r0 + ty) * ldi + c0 + tx];
    }
    __syncthreads();
    #pragma unroll
    for (int i = 0; i < 4; i++) {
        int oy = ty8 + i * 8;
        long long idx = oOff + (long long)(c0 + oy) * ldo + r0 + tx;
        oh[idx] = __float2half(t[tx][oy]);
    }
}

// ---------------- rmsnorm -> fp32 + fp16 ----------------
__global__ __launch_bounds__(256) void rmsnorm_h(
    const float* __restrict__ x, const float* __restrict__ w,
    float* __restrict__ y, hf* __restrict__ yh)
{
    __shared__ float red[256];
    long long row = blockIdx.x;
    const float* xr = x + row * HID;
    int tid = threadIdx.x;
    float4 v0 = *(const float4*)(xr + tid * 4);
    float4 v1 = *(const float4*)(xr + 1024 + tid * 4);
    float s = v0.x * v0.x + v0.y * v0.y + v0.z * v0.z + v0.w * v0.w
            + v1.x * v1.x + v1.y * v1.y + v1.z * v1.z + v1.w * v1.w;
    red[tid] = s;
    __syncthreads();
    for (int st = 128; st > 0; st >>= 1) {
        if (tid < st) red[tid] += red[tid + st];
        __syncthreads();
    }
    float inv = rsqrtf(red[0] * (1.f / HID) + EPS_RMS);

    float4 w0 = *(const float4*)(w + tid * 4);
    float4 w1 = *(const float4*)(w + 1024 + tid * 4);
    float o[8];
    o[0] = v0.x * inv * w0.x; o[1] = v0.y * inv * w0.y;
    o[2] = v0.z * inv * w0.z; o[3] = v0.w * inv * w0.w;
    o[4] = v1.x * inv * w1.x; o[5] = v1.y * inv * w1.y;
    o[6] = v1.z * inv * w1.z; o[7] = v1.w * inv * w1.w;
    float* yr = y + row * HID;
    *(float4*)(yr + tid * 4) = make_float4(o[0], o[1], o[2], o[3]);
    *(float4*)(yr + 1024 + tid * 4) = make_float4(o[4], o[5], o[6], o[7]);
    hf* yhr = yh + row * HID;
    #pragma unroll
    for (int g = 0; g < 2; g++) {
        int off = g * 1024 + tid * 4;
        *(uint32_t*)(yhr + off) =
            pack_f16x2(__float2half(o[g * 4 + 0]), __float2half(o[g * 4 + 1]));
        *(uint32_t*)(yhr + off + 2) =
            pack_f16x2(__float2half(o[g * 4 + 2]), __float2half(o[g * 4 + 3]));
    }
}

// ---------------- host ----------------
static void* sym(const void* s) {
    void* p = nullptr;
    cudaGetSymbolAddress(&p, s);
    return p;
}

extern "C" void kernel_launch(void* const* d_in, const int* in_sizes, int n_in,
                              void* d_out, int out_size)
{
    const float* h_in = (const float*)d_in[0];
    const float* Wup  = (const float*)d_in[1];
    const float* bup  = (const float*)d_in[2];
    const float* anw  = (const float*)d_in[3];
    const float* Wq   = (const float*)d_in[4];
    const float* Wk   = (const float*)d_in[5];
    const float* Wv   = (const float*)d_in[6];
    const float* Wo   = (const float*)d_in[7];
    const float* mnw  = (const float*)d_in[8];
    const float* Wg   = (const float*)d_in[9];
    const float* Wu   = (const float*)d_in[10];
    const float* Wd   = (const float*)d_in[11];
    float* out = (float*)d_out;

    float* up_ = (float*)sym(g_up);
    float* x1_ = (float*)sym(g_x1);
    float* x2_ = (float*)sym(g_x2);
    float* x3_ = (float*)sym(g_x3);

    hf *hh  = (hf*)sym(f_h);
    hf *hth = (hf*)sym(f_ht);
    hf *wup = (hf*)sym(f_wup);
    hf *wqkv = (hf*)sym(f_wqkv);
    hf *wo = (hf*)sym(f_wo);
    hf *wg = (hf*)sym(f_wg);
    hf *wu = (hf*)sym(f_wu);
    hf *wd = (hf*)sym(f_wd);
    hf *uph = (hf*)sym(f_up);
    hf *x1h = (hf*)sym(f_x1);
    hf *x3h = (hf*)sym(f_x3);
    hf *qh = (hf*)sym(f_q);
    hf *kh = (hf*)sym(f_k);
    hf *vh = (hf*)sym(f_v);
    hf *oh = (hf*)sym(f_o);
    hf *gate16 = (hf*)sym(f_gate);
    hf *ubh = (hf*)sym(f_ub);

    const int SMEMG  = 1024 + 3 * 32768;            // 99328
    const int SMEMFA = 1024 + 16384 + 2 * 32768;    // 82944
    cudaFuncSetAttribute(mma_gemm, cudaFuncAttributeMaxDynamicSharedMemorySize, SMEMG);
    cudaFuncSetAttribute(flash_attn, cudaFuncAttributeMaxDynamicSharedMemorySize, SMEMFA);

    dim3 blk(256);
    dim3 blkG(128);

    const hf* nullh = nullptr;

    // 1) all fp32->fp16 conversions in one launch (Wq/Wk/Wv packed contiguously)
    {
        ConvJobs J;
        const float* srcs[10] = { h_in, Wup, Wq, Wk, Wv, Wo, Wg, Wu, Wd, nullptr };
        hf* dsts[10] = { hh, wup, wqkv, wqkv + W1N, wqkv + 2 * W1N, wo, wg, wu, wd, nullptr };
        long long ns[10] = { HB, WUPN, W1N, W1N, W1N, W1N, W2N, W2N, W2N, 0 };
        int cum = 0;
        for (int j = 0; j < 10; j++) {
            J.src[j] = srcs[j];
            J.dst[j] = dsts[j];
            J.n4[j] = ns[j] / 4;
            J.bstart[j] = cum;
            cum += (int)((J.n4[j] + 255) / 256);
        }
        J.bstart[10] = cum;
        conv_multi<<<cum, blk>>>(J);
    }

    // 2) h [S,H] -> hT [H,S] per batch
    transpose_h<<<dim3(HID / 32, S_LEN / 32, BATCH), blk>>>(
        h_in, HID, S_H, hth, S_LEN, S_H);

    // 3) up = Wup @ hT (+bias) -> fp32 + fp16
    mma_gemm<<<dim3(HID / 128, SU_LEN / 128, BATCH), blkG, SMEMG>>>(
        wup, S_LEN, 0,
        hth, S_LEN, S_H,
        up_, uph, HID, SU_H,
        bup, nullptr, 0, 0, nullh,
        nullptr, 0, nullptr, 0,
        S_LEN, 1.f);

    // 4) (k,v) rows 0..S = h @ [Wk;Wv]^T  (segmented output, grid 256)
    mma_gemm<<<dim3(2 * HID / 128, S_LEN / 128, BATCH), blkG, SMEMG>>>(
        hh, HID, S_H,
        wqkv + W1N, HID, 0,
        nullptr, nullptr, HID, 0,
        nullptr, nullptr, 0, 0, nullh,
        kh, T_H, vh, T_H,
        HID, 1.f);

    // 5) x1 = rmsnorm(up)
    rmsnorm_h<<<BATCH * SU_LEN, blk>>>(up_, anw, x1_, x1h);

    // 6) q = x1 @ Wq^T
    mma_gemm<<<dim3(HID / 128, SU_LEN / 128, BATCH), blkG, SMEMG>>>(
        x1h, HID, SU_H,
        wqkv, HID, 0,
        nullptr, qh, HID, SU_H,
        nullptr, nullptr, 0, 0, nullh,
        nullptr, 0, nullptr, 0,
        HID, 1.f);

    // 7) (k,v) rows S.. = up @ [Wk;Wv]^T  (segmented output, grid 512)
    mma_gemm<<<dim3(2 * HID / 128, SU_LEN / 128, BATCH), blkG, SMEMG>>>(
        uph, HID, SU_H,
        wqkv + W1N, HID, 0,
        nullptr, nullptr, HID, 0,
        nullptr, nullptr, 0, 0, nullh,
        kh + (long long)S_LEN * HID, T_H, vh + (long long)S_LEN * HID, T_H,
        HID, 1.f);

    // 8) fused flash attention -> o fp16
    flash_attn<<<dim3(SU_LEN / 128, BATCH * NHEAD), blk, SMEMFA>>>(
        qh, kh, vh, oh);

    // 9) x2 = o @ Wo^T + x1
    mma_gemm<<<dim3(HID / 128, SU_LEN / 128, BATCH), blkG, SMEMG>>>(
        oh, HID, SU_H,
        wo, HID, 0,
        x2_, nullptr, HID, SU_H,
        nullptr, x1_, HID, SU_H, nullh,
        nullptr, 0, nullptr, 0,
        HID, 1.f);

    // 10) x3 = rmsnorm(x2)
    rmsnorm_h<<<BATCH * SU_LEN, blk>>>(x2_, mnw, x3_, x3h);

    // 11) gate = x3 @ Wg^T -> fp16
    mma_gemm<<<dim3(INTER / 128, SU_LEN / 128, BATCH), blkG, SMEMG>>>(
        x3h, HID, SU_H,
        wg, HID, 0,
        nullptr, gate16, INTER, SU_I,
        nullptr, nullptr, 0, 0, nullh,
        nullptr, 0, nullptr, 0,
        HID, 1.f);

    // 12) ub = silu(gate) * (x3 @ Wu^T) -> fp16
    mma_gemm<<<dim3(INTER / 128, SU_LEN / 128, BATCH), blkG, SMEMG>>>(
        x3h, HID, SU_H,
        wu, HID, 0,
        nullptr, ubh, INTER, SU_I,
        nullptr, nullptr, 0, 0, gate16,
        nullptr, 0, nullptr, 0,
        HID, 1.f);

    // 13) out = ub @ Wd^T + x3
    mma_gemm<<<dim3(HID / 128, SU_LEN / 128, BATCH), blkG, SMEMG>>>(
        ubh, INTER, SU_I,
        wd, INTER, 0,
        out, nullptr, HID, SU_H,
        nullptr, x3_, HID, SU_H, nullh,
        nullptr, 0, nullptr, 0,
        INTER, 1.f);
}

// round 11
// speedup vs baseline: 7.1323x; 1.0004x over previous
#include <cuda_runtime.h>
#include <cuda_fp16.h>
#include <cstdint>

// ---------------- problem constants ----------------
#define BATCH 2
#define S_LEN 512
#define HID 2048
#define NHEAD 32
#define HDIM 64
#define SU_LEN 1024
#define T_LEN 1536
#define INTER 5632
#define EPS_RMS 1e-6f

#define S_H   (S_LEN * HID)
#define SU_H  (SU_LEN * HID)
#define T_H   (T_LEN * HID)
#define SU_I  ((long long)SU_LEN * INTER)

#define HB  (BATCH * S_LEN * HID)
#define XB  (BATCH * SU_LEN * HID)
#define KBN (BATCH * T_LEN * HID)
#define UBB ((long long)BATCH * SU_LEN * INTER)
#define WUPN (SU_LEN * S_LEN)
#define W1N  (HID * HID)
#define W2N  (INTER * HID)

typedef __half hf;

// ---------------- scratch (device globals; no runtime allocation) ----------------
__device__ float g_up  [XB];
__device__ float g_x1  [XB];
__device__ float g_x2  [XB];
__device__ float g_x3  [XB];

__device__ hf f_h  [HB];
__device__ hf f_ht [HB];
__device__ hf f_wup[WUPN];
__device__ hf f_wqkv[3 * W1N];   // [Wq; Wk; Wv] rows
__device__ hf f_wo[W1N];
__device__ hf f_wg[W2N];
__device__ hf f_wu[W2N];
__device__ hf f_wd[W2N];
__device__ hf f_up [XB];
__device__ hf f_x1 [XB];
__device__ hf f_x3 [XB];
__device__ hf f_q  [XB];
__device__ hf f_k  [KBN];
__device__ hf f_v  [KBN];
__device__ hf f_o  [XB];
__device__ hf f_gate[UBB];
__device__ hf f_ub [UBB];

// ---------------- PTX helpers ----------------
__device__ __forceinline__ uint32_t smem_u32(const void* p) {
    uint32_t a;
    asm("{ .reg .u64 t; cvta.to.shared.u64 t, %1; cvt.u32.u64 %0, t; }" : "=r"(a) : "l"(p));
    return a;
}
#define SWZ(off) ((off) ^ (((off) >> 3) & 0x70))

#define CP_ASYNC16(dst, src) \
    asm volatile("cp.async.cg.shared.global [%0], [%1], 16;" :: "r"(dst), "l"(src) : "memory")
#define CP_COMMIT() asm volatile("cp.async.commit_group;" ::: "memory")
__device__ __forceinline__ void cp_wait(int allow) {
    if (allow) asm volatile("cp.async.wait_group 1;" ::: "memory");
    else       asm volatile("cp.async.wait_group 0;" ::: "memory");
}

__device__ __forceinline__ void ldmx4(uint32_t* r, uint32_t addr) {
    asm volatile("ldmatrix.sync.aligned.m8n8.x4.shared.b16 {%0,%1,%2,%3}, [%4];"
        : "=r"(r[0]), "=r"(r[1]), "=r"(r[2]), "=r"(r[3]) : "r"(addr));
}
__device__ __forceinline__ void ldmx4t(uint32_t* r, uint32_t addr) {
    asm volatile("ldmatrix.sync.aligned.m8n8.x4.trans.shared.b16 {%0,%1,%2,%3}, [%4];"
        : "=r"(r[0]), "=r"(r[1]), "=r"(r[2]), "=r"(r[3]) : "r"(addr));
}

__device__ __forceinline__ void mma_f16(float* d, const uint32_t* a, uint32_t b0, uint32_t b1) {
    asm volatile("mma.sync.aligned.m16n8k16.row.col.f32.f16.f16.f32 "
        "{%0,%1,%2,%3}, {%4,%5,%6,%7}, {%8,%9}, {%0,%1,%2,%3};"
        : "+f"(d[0]), "+f"(d[1]), "+f"(d[2]), "+f"(d[3])
        : "r"(a[0]), "r"(a[1]), "r"(a[2]), "r"(a[3]), "r"(b0), "r"(b1));
}

__device__ __forceinline__ uint32_t pack_f16x2(hf a, hf b) {
    __half2 t;
    t.x = a; t.y = b;
    return *(uint32_t*)&t;
}

// ---------------- mma.sync GEMM (pure fp16, fp32 accumulate) ----------------
// 128 threads, 4 warps in 2x2, warp tile 64x64, CTA tile 128x128, BK=64.
// Batched over grid.z (stride sA1/sB1/sC1 or per-segment strides).
// If s0 != null: segmented fp16 output — columns [0,2048) -> s0, [2048,4096) -> s1.
__global__ __launch_bounds__(128, 2) void mma_gemm(
    const hf* __restrict__ A0, int lda, long long sA1,
    const hf* __restrict__ B0, int ldb, long long sB1,
    float* __restrict__ C, hf* __restrict__ Chi, int ldc, long long sC1,
    const float* __restrict__ bias,
    const float* __restrict__ resid, int ldr, long long sR1,
    const hf* __restrict__ gate,
    hf* __restrict__ s0, long long ss0,
    hf* __restrict__ s1, long long ss1,
    int K, float alpha)
{
    extern __shared__ char smem[];
    const uint32_t sbase = smem_u32(smem);
    const uint32_t tiles = (sbase + 1023u) & ~1023u;
    constexpr int ASZ = 128 * 128;
    constexpr int STG = 2 * ASZ;       // 32 KB per stage

    const int tid = threadIdx.x, wid = tid >> 5, lane = tid & 31;
    const int z = blockIdx.z;
    const hf* A = A0 + (long long)z * sA1;
    const hf* B = B0 + (long long)z * sB1;
    const int m0 = blockIdx.y * 128, n0 = blockIdx.x * 128;
    const int m0w = (wid & 1) * 64;
    const int n0w = (wid >> 1) * 64;

    const int nc = K >> 6;

    auto load_chunk = [&](int c, int s) {
        const int k0 = c << 6;
        const uint32_t aB = tiles + s * STG;
        const uint32_t bB = aB + ASZ;
        #pragma unroll
        for (int u0 = 0; u0 < 2048; u0 += 128) {
            int u = u0 + tid;
            if (u < 1024) {
                int r = u >> 3, g = u & 7;
                CP_ASYNC16(aB + SWZ(r * 128 + g * 16),
                           A + (long long)(m0 + r) * lda + k0 + g * 8);
            } else {
                int u2 = u - 1024;
                int r = u2 >> 3, g = u2 & 7;
                CP_ASYNC16(bB + SWZ(r * 128 + g * 16),
                           B + (long long)(n0 + r) * ldb + k0 + g * 8);
            }
        }
        CP_COMMIT();
    };

    float acc[4][8][4];
    #pragma unroll
    for (int i = 0; i < 4; i++)
        #pragma unroll
        for (int j = 0; j < 8; j++)
            #pragma unroll
            for (int q = 0; q < 4; q++) acc[i][j][q] = 0.f;

    load_chunk(0, 0);
    if (nc > 1) load_chunk(1, 1);

    const int lrow = lane & 15;
    const int lcol = (lane >> 4) * 16;

    for (int c = 0; c < nc; c++) {
        const int s = c % 3;
        cp_wait(c + 1 < nc ? 1 : 0);
        __syncthreads();
        if (c + 2 < nc) load_chunk(c + 2, (c + 2) % 3);

        const uint32_t aSt = tiles + s * STG;
        const uint32_t bSt = aSt + ASZ;
        #pragma unroll
        for (int ks = 0; ks < 4; ks++) {
            uint32_t ra[4][4];
            #pragma unroll
            for (int mt = 0; mt < 4; mt++)
                ldmx4(ra[mt], aSt + SWZ((m0w + mt * 16 + lrow) * 128 + ks * 32 + lcol));
            uint32_t rb[2][4];
            ldmx4(rb[0], bSt + SWZ((n0w + lrow) * 128 + ks * 32 + lcol));
            #pragma unroll
            for (int ng = 0; ng < 4; ng++) {
                if (ng < 3)
                    ldmx4(rb[(ng + 1) & 1],
                          bSt + SWZ((n0w + (ng + 1) * 16 + lrow) * 128 + ks * 32 + lcol));
                const uint32_t* rbc = rb[ng & 1];
                #pragma unroll
                for (int mt = 0; mt < 4; mt++) {
                    mma_f16(acc[mt][2 * ng],     ra[mt], rbc[0], rbc[2]);
                    mma_f16(acc[mt][2 * ng + 1], ra[mt], rbc[1], rbc[3]);
                }
            }
        }
        __syncthreads();
    }

    // ---- epilogue ----
    hf* hOut;
    float* fOut;
    long long cAdj;
    if (s0) {
        const int seg = n0 >> 11;               // 2048-column segments
        hf* sp = seg ? s1 : s0;
        const long long st = seg ? ss1 : ss0;
        hOut = sp;
        fOut = nullptr;
        cAdj = (long long)z * st - ((long long)seg << 11);
    } else {
        hOut = Chi;
        fOut = C;
        cAdj = (long long)z * sC1;
    }

    const int rq = lane >> 2;
    const int cq = (lane & 3) * 2;
    #pragma unroll
    for (int mt = 0; mt < 4; mt++) {
        #pragma unroll
        for (int half = 0; half < 2; half++) {
            const int m = m0 + m0w + mt * 16 + rq + half * 8;
            const float bv = bias ? bias[m] : 0.f;
            const long long cBase = cAdj + (long long)m * ldc + n0 + n0w;
            const long long rBase = resid ? ((long long)z * sR1 +
                                             (long long)m * ldr + n0 + n0w) : 0;
            #pragma unroll
            for (int nt = 0; nt < 8; nt++) {
                float v0 = acc[mt][nt][half * 2]     * alpha + bv;
                float v1 = acc[mt][nt][half * 2 + 1] * alpha + bv;
                const int cn = nt * 8 + cq;
                if (resid) {
                    v0 += resid[rBase + cn];
                    v1 += resid[rBase + cn + 1];
                }
                if (gate) {
                    __half2 gp = *(const __half2*)(gate + cBase + cn);
                    float g0 = __half2float(gp.x), g1 = __half2float(gp.y);
                    v0 *= g0 / (1.f + __expf(-g0));
                    v1 *= g1 / (1.f + __expf(-g1));
                }
                if (fOut)
                    *(float2*)(fOut + cBase + cn) = make_float2(v0, v1);
                if (hOut)
                    *(uint32_t*)(hOut + cBase + cn) =
                        pack_f16x2(__float2half(v0), __float2half(v1));
            }
        }
    }
}

// ---------------- fused flash attention (pure fp16, V in [t,d] layout) ----------------
#define FA_NI (T_LEN / 128)   // 12

__global__ __launch_bounds__(256, 1) void flash_attn(
    const hf* __restrict__ gq,
    const hf* __restrict__ gk,
    const hf* __restrict__ gv,
    hf* __restrict__ go)
{
    extern __shared__ char smem[];
    const uint32_t sb0 = smem_u32(smem);
    const uint32_t sb = (sb0 + 1023u) & ~1023u;
    const uint32_t Q = sb;
    const uint32_t ST0 = sb + 16384;
    const uint32_t STSZ = 32768;   // per stage: K 16K, V 16K

    const int tid = threadIdx.x, wid = tid >> 5, lane = tid & 31;
    const int q0 = blockIdx.x * 128;
    const int bh = blockIdx.y;
    const int b = bh >> 5, head = bh & 31;

    const hf* qp = gq + (long long)b * SU_H + head * HDIM;
    const hf* kp = gk + (long long)b * T_H + head * HDIM;
    const hf* vp = gv + (long long)b * T_H + head * HDIM;

    for (int u = tid; u < 1024; u += 256) {
        int r = u >> 3, g = u & 7;
        CP_ASYNC16(Q + SWZ(r * 128 + g * 16), qp + (long long)(q0 + r) * HID + g * 8);
    }
    CP_COMMIT();

    auto loadkv = [&](int ci, int s) {
        const int t0 = ci * 128;
        const uint32_t stb = ST0 + s * STSZ;
        for (int u = tid; u < 2048; u += 256) {
            if (u < 1024) {
                int r = u >> 3, g = u & 7;
                CP_ASYNC16(stb + SWZ(r * 128 + g * 16),
                           kp + (long long)(t0 + r) * HID + g * 8);
            } else {
                int u2 = u - 1024;
                int r = u2 >> 3, g = u2 & 7;
                CP_ASYNC16(stb + 16384 + SWZ(r * 128 + g * 16),
                           vp + (long long)(t0 + r) * HID + g * 8);
            }
        }
        CP_COMMIT();
    };

    loadkv(0, 0);
    loadkv(1, 1);
    cp_wait(1);
    __syncthreads();

    const int lrow = lane & 15, lcol = (lane >> 4) * 16;
    const int mrow = wid * 16;
    uint32_t qf[4][4];
    #pragma unroll
    for (int ks = 0; ks < 4; ks++)
        ldmx4(qf[ks], Q + SWZ((mrow + lrow) * 128 + ks * 32 + lcol));

    float oacc[8][4];
    #pragma unroll
    for (int i = 0; i < 8; i++)
        #pragma unroll
        for (int j = 0; j < 4; j++) oacc[i][j] = 0.f;
    float M0 = -1e30f, M1 = -1e30f, L0 = 0.f, L1 = 0.f;

    for (int i = 0; i < FA_NI; i++) {
        const uint32_t stb = ST0 + (i & 1) * STSZ;
        if (i > 0) { cp_wait(i + 1 < FA_NI ? 1 : 0); __syncthreads(); }

        float sacc[16][4];
        #pragma unroll
        for (int t = 0; t < 16; t++)
            #pragma unroll
            for (int j = 0; j < 4; j++) sacc[t][j] = 0.f;

        #pragma unroll
        for (int ks = 0; ks < 4; ks++) {
            #pragma unroll
            for (int ng = 0; ng < 8; ng++) {
                uint32_t rb[4];
                ldmx4(rb, stb + SWZ((ng * 16 + lrow) * 128 + ks * 32 + lcol));
                mma_f16(sacc[2 * ng],     qf[ks], rb[0], rb[2]);
                mma_f16(sacc[2 * ng + 1], qf[ks], rb[1], rb[3]);
            }
        }

        float mx0 = -1e30f, mx1 = -1e30f;
        #pragma unroll
        for (int t = 0; t < 16; t++) {
            sacc[t][0] *= 0.125f; sacc[t][1] *= 0.125f;
            sacc[t][2] *= 0.125f; sacc[t][3] *= 0.125f;
            mx0 = fmaxf(mx0, fmaxf(sacc[t][0], sacc[t][1]));
            mx1 = fmaxf(mx1, fmaxf(sacc[t][2], sacc[t][3]));
        }
        mx0 = fmaxf(mx0, __shfl_xor_sync(0xFFFFFFFFu, mx0, 1));
        mx0 = fmaxf(mx0, __shfl_xor_sync(0xFFFFFFFFu, mx0, 2));
        mx1 = fmaxf(mx1, __shfl_xor_sync(0xFFFFFFFFu, mx1, 1));
        mx1 = fmaxf(mx1, __shfl_xor_sync(0xFFFFFFFFu, mx1, 2));
        const float Mn0 = fmaxf(M0, mx0), Mn1 = fmaxf(M1, mx1);
        const float al0 = __expf(M0 - Mn0), al1 = __expf(M1 - Mn1);
        M0 = Mn0; M1 = Mn1;

        float s0 = 0.f, s1 = 0.f;
        #pragma unroll
        for (int t = 0; t < 16; t++) {
            sacc[t][0] = __expf(sacc[t][0] - M0); s0 += sacc[t][0];
            sacc[t][1] = __expf(sacc[t][1] - M0); s0 += sacc[t][1];
            sacc[t][2] = __expf(sacc[t][2] - M1); s1 += sacc[t][2];
            sacc[t][3] = __expf(sacc[t][3] - M1); s1 += sacc[t][3];
        }
        s0 += __shfl_xor_sync(0xFFFFFFFFu, s0, 1);
        s0 += __shfl_xor_sync(0xFFFFFFFFu, s0, 2);
        s1 += __shfl_xor_sync(0xFFFFFFFFu, s1, 1);
        s1 += __shfl_xor_sync(0xFFFFFFFFu, s1, 2);
        L0 = L0 * al0 + s0;
        L1 = L1 * al1 + s1;
        #pragma unroll
        for (int t = 0; t < 8; t++) {
            oacc[t][0] *= al0; oacc[t][1] *= al0;
            oacc[t][2] *= al1; oacc[t][3] *= al1;
        }

        const uint32_t vb = stb + 16384;
        #pragma unroll
        for (int ks = 0; ks < 8; ks++) {
            uint32_t ah[4];
            ah[0] = pack_f16x2(__float2half(sacc[2 * ks][0]),     __float2half(sacc[2 * ks][1]));
            ah[1] = pack_f16x2(__float2half(sacc[2 * ks][2]),     __float2half(sacc[2 * ks][3]));
            ah[2] = pack_f16x2(__float2half(sacc[2 * ks + 1][0]), __float2half(sacc[2 * ks + 1][1]));
            ah[3] = pack_f16x2(__float2half(sacc[2 * ks + 1][2]), __float2half(sacc[2 * ks + 1][3]));

            #pragma unroll
            for (int ng = 0; ng < 4; ng++) {
                uint32_t rb[4];
                ldmx4t(rb, vb + SWZ((ks * 16 + lrow) * 128 + ng * 32 + lcol));
                mma_f16(oacc[2 * ng],     ah, rb[0], rb[1]);
                mma_f16(oacc[2 * ng + 1], ah, rb[2], rb[3]);
            }
        }

        __syncthreads();
        if (i + 2 < FA_NI) loadkv(i + 2, i & 1);
    }

    const float inv0 = 1.f / L0, inv1 = 1.f / L1;
    const int rq = lane >> 2, cq = (lane & 3) * 2;
    const long long base0 = (long long)b * SU_H + (long long)(q0 + mrow + rq) * HID + head * HDIM;
    const long long base1 = base0 + 8LL * HID;
    #pragma unroll
    for (int nt = 0; nt < 8; nt++) {
        const int cn = nt * 8 + cq;
        *(uint32_t*)(go + base0 + cn) =
            pack_f16x2(__float2half(oacc[nt][0] * inv0), __float2half(oacc[nt][1] * inv0));
        *(uint32_t*)(go + base1 + cn) =
            pack_f16x2(__float2half(oacc[nt][2] * inv1), __float2half(oacc[nt][3] * inv1));
    }
}

// ---------------- fused multi-buffer fp32->fp16 conversion ----------------
struct ConvJobs {
    const float* src[10];
    hf* dst[10];
    long long n4[10];
    int bstart[11];
};

__global__ __launch_bounds__(256) void conv_multi(ConvJobs J)
{
    int b = blockIdx.x;
    int j = 0;
    #pragma unroll
    for (int t = 0; t < 9; t++)
        if (b >= J.bstart[t + 1]) j = t + 1;
    long long i = (long long)(b - J.bstart[j]) * 256 + threadIdx.x;
    if (i >= J.n4[j]) return;
    float4 v = ((const float4*)J.src[j])[i];
    uint32_t* d = (uint32_t*)J.dst[j];
    d[i * 2]     = pack_f16x2(__float2half(v.x), __float2half(v.y));
    d[i * 2 + 1] = pack_f16x2(__float2half(v.z), __float2half(v.w));
}

// ---------------- transpose -> fp16 ----------------
__global__ __launch_bounds__(256) void transpose_h(
    const float* __restrict__ in, int ldi, long long sI1,
    hf* __restrict__ oh, int ldo, long long sO1)
{
    __shared__ float t[32][33];
    int z = blockIdx.z;
    in += (long long)z * sI1;
    long long oOff = (long long)z * sO1;
    int r0 = blockIdx.y * 32, c0 = blockIdx.x * 32;
    int tx = threadIdx.x & 31, ty8 = threadIdx.x >> 5;
    #pragma unroll
    for (int i = 0; i < 4; i++) {
        int ty = ty8 + i * 8;
        t[ty][tx] = in[(long long)(r0 + ty) * ldi + c0 + tx];
    }
    __syncthreads();
    #pragma unroll
    for (int i = 0; i < 4; i++) {
        int oy = ty8 + i * 8;
        long long idx = oOff + (long long)(c0 + oy) * ldo + r0 + tx;
        oh[idx] = __float2half(t[tx][oy]);
    }
}

// ---------------- rmsnorm -> fp32 + fp16 ----------------
__global__ __launch_bounds__(256) void rmsnorm_h(
    const float* __restrict__ x, const float* __restrict__ w,
    float* __restrict__ y, hf* __restrict__ yh)
{
    __shared__ float red[256];
    long long row = blockIdx.x;
    const float* xr = x + row * HID;
    int tid = threadIdx.x;
    float4 v0 = *(const float4*)(xr + tid * 4);
    float4 v1 = *(const float4*)(xr + 1024 + tid * 4);
    float s = v0.x * v0.x + v0.y * v0.y + v0.z * v0.z + v0.w * v0.w
            + v1.x * v1.x + v1.y * v1.y + v1.z * v1.z + v1.w * v1.w;
    red[tid] = s;
    __syncthreads();
    for (int st = 128; st > 0; st >>= 1) {
        if (tid < st) red[tid] += red[tid + st];
        __syncthreads();
    }
    float inv = rsqrtf(red[0] * (1.f / HID) + EPS_RMS);

    float4 w0 = *(const float4*)(w + tid * 4);
    float4 w1 = *(const float4*)(w + 1024 + tid * 4);
    float o[8];
    o[0] = v0.x * inv * w0.x; o[1] = v0.y * inv * w0.y;
    o[2] = v0.z * inv * w0.z; o[3] = v0.w * inv * w0.w;
    o[4] = v1.x * inv * w1.x; o[5] = v1.y * inv * w1.y;
    o[6] = v1.z * inv * w1.z; o[7] = v1.w * inv * w1.w;
    float* yr = y + row * HID;
    *(float4*)(yr + tid * 4) = make_float4(o[0], o[1], o[2], o[3]);
    *(float4*)(yr + 1024 + tid * 4) = make_float4(o[4], o[5], o[6], o[7]);
    hf* yhr = yh + row * HID;
    #pragma unroll
    for (int g = 0; g < 2; g++) {
        int off = g * 1024 + tid * 4;
        *(uint32_t*)(yhr + off) =
            pack_f16x2(__float2half(o[g * 4 + 0]), __float2half(o[g * 4 + 1]));
        *(uint32_t*)(yhr + off + 2) =
            pack_f16x2(__float2half(o[g * 4 + 2]), __float2half(o[g * 4 + 3]));
    }
}

// ---------------- host ----------------
static void* sym(const void* s) {
    void* p = nullptr;
    cudaGetSymbolAddress(&p, s);
    return p;
}

extern "C" void kernel_launch(void* const* d_in, const int* in_sizes, int n_in,
                              void* d_out, int out_size)
{
    const float* h_in = (const float*)d_in[0];
    const float* Wup  = (const float*)d_in[1];
    const float* bup  = (const float*)d_in[2];
    const float* anw  = (const float*)d_in[3];
    const float* Wq   = (const float*)d_in[4];
    const float* Wk   = (const float*)d_in[5];
    const float* Wv   = (const float*)d_in[6];
    const float* Wo   = (const float*)d_in[7];
    const float* mnw  = (const float*)d_in[8];
    const float* Wg   = (const float*)d_in[9];
    const float* Wu   = (const float*)d_in[10];
    const float* Wd   = (const float*)d_in[11];
    float* out = (float*)d_out;

    float* up_ = (float*)sym(g_up);
    float* x1_ = (float*)sym(g_x1);
    float* x2_ = (float*)sym(g_x2);
    float* x3_ = (float*)sym(g_x3);

    hf *hh  = (hf*)sym(f_h);
    hf *hth = (hf*)sym(f_ht);
    hf *wup = (hf*)sym(f_wup);
    hf *wqkv = (hf*)sym(f_wqkv);
    hf *wo = (hf*)sym(f_wo);
    hf *wg = (hf*)sym(f_wg);
    hf *wu = (hf*)sym(f_wu);
    hf *wd = (hf*)sym(f_wd);
    hf *uph = (hf*)sym(f_up);
    hf *x1h = (hf*)sym(f_x1);
    hf *x3h = (hf*)sym(f_x3);
    hf *qh = (hf*)sym(f_q);
    hf *kh = (hf*)sym(f_k);
    hf *vh = (hf*)sym(f_v);
    hf *oh = (hf*)sym(f_o);
    hf *gate16 = (hf*)sym(f_gate);
    hf *ubh = (hf*)sym(f_ub);

    const int SMEMG  = 1024 + 3 * 32768;            // 99328
    const int SMEMFA = 1024 + 16384 + 2 * 32768;    // 82944
    cudaFuncSetAttribute(mma_gemm, cudaFuncAttributeMaxDynamicSharedMemorySize, SMEMG);
    cudaFuncSetAttribute(flash_attn, cudaFuncAttributeMaxDynamicSharedMemorySize, SMEMFA);

    dim3 blk(256);
    dim3 blkG(128);

    const hf* nullh = nullptr;

    // 1) all fp32->fp16 conversions in one launch (Wq/Wk/Wv packed contiguously)
    {
        ConvJobs J;
        const float* srcs[10] = { h_in, Wup, Wq, Wk, Wv, Wo, Wg, Wu, Wd, nullptr };
        hf* dsts[10] = { hh, wup, wqkv, wqkv + W1N, wqkv + 2 * W1N, wo, wg, wu, wd, nullptr };
        long long ns[10] = { HB, WUPN, W1N, W1N, W1N, W1N, W2N, W2N, W2N, 0 };
        int cum = 0;
        for (int j = 0; j < 10; j++) {
            J.src[j] = srcs[j];
            J.dst[j] = dsts[j];
            J.n4[j] = ns[j] / 4;
            J.bstart[j] = cum;
            cum += (int)((J.n4[j] + 255) / 256);
        }
        J.bstart[10] = cum;
        conv_multi<<<cum, blk>>>(J);
    }

    // 2) h [S,H] -> hT [H,S] per batch
    transpose_h<<<dim3(HID / 32, S_LEN / 32, BATCH), blk>>>(
        h_in, HID, S_H, hth, S_LEN, S_H);

    // 3) up = Wup @ hT (+bias) -> fp32 + fp16
    mma_gemm<<<dim3(HID / 128, SU_LEN / 128, BATCH), blkG, SMEMG>>>(
        wup, S_LEN, 0,
        hth, S_LEN, S_H,
        up_, uph, HID, SU_H,
        bup, nullptr, 0, 0, nullh,
        nullptr, 0, nullptr, 0,
        S_LEN, 1.f);

    // 4) (k,v) rows 0..S = h @ [Wk;Wv]^T  (segmented output, grid 256)
    mma_gemm<<<dim3(2 * HID / 128, S_LEN / 128, BATCH), blkG, SMEMG>>>(
        hh, HID, S_H,
        wqkv + W1N, HID, 0,
        nullptr, nullptr, HID, 0,
        nullptr, nullptr, 0, 0, nullh,
        kh, T_H, vh, T_H,
        HID, 1.f);

    // 5) x1 = rmsnorm(up)
    rmsnorm_h<<<BATCH * SU_LEN, blk>>>(up_, anw, x1_, x1h);

    // 6) q = x1 @ Wq^T
    mma_gemm<<<dim3(HID / 128, SU_LEN / 128, BATCH), blkG, SMEMG>>>(
        x1h, HID, SU_H,
        wqkv, HID, 0,
        nullptr, qh, HID, SU_H,
        nullptr, nullptr, 0, 0, nullh,
        nullptr, 0, nullptr, 0,
        HID, 1.f);

    // 7) (k,v) rows S.. = up @ [Wk;Wv]^T  (segmented output, grid 512)
    mma_gemm<<<dim3(2 * HID / 128, SU_LEN / 128, BATCH), blkG, SMEMG>>>(
        uph, HID, SU_H,
        wqkv + W1N, HID, 0,
        nullptr, nullptr, HID, 0,
        nullptr, nullptr, 0, 0, nullh,
        kh + (long long)S_LEN * HID, T_H, vh + (long long)S_LEN * HID, T_H,
        HID, 1.f);

    // 8) fused flash attention -> o fp16
    flash_attn<<<dim3(SU_LEN / 128, BATCH * NHEAD), blk, SMEMFA>>>(
        qh, kh, vh, oh);

    // 9) x2 = o @ Wo^T + x1
    mma_gemm<<<dim3(HID / 128, SU_LEN / 128, BATCH), blkG, SMEMG>>>(
        oh, HID, SU_H,
        wo, HID, 0,
        x2_, nullptr, HID, SU_H,
        nullptr, x1_, HID, SU_H, nullh,
        nullptr, 0, nullptr, 0,
        HID, 1.f);

    // 10) x3 = rmsnorm(x2)
    rmsnorm_h<<<BATCH * SU_LEN, blk>>>(x2_, mnw, x3_, x3h);

    // 11) gate = x3 @ Wg^T -> fp16
    mma_gemm<<<dim3(INTER / 128, SU_LEN / 128, BATCH), blkG, SMEMG>>>(
        x3h, HID, SU_H,
        wg, HID, 0,
        nullptr, gate16, INTER, SU_I,
        nullptr, nullptr, 0, 0, nullh,
        nullptr, 0, nullptr, 0,
        HID, 1.f);

    // 12) ub = silu(gate) * (x3 @ Wu^T) -> fp16
    mma_gemm<<<dim3(INTER / 128, SU_LEN / 128, BATCH), blkG, SMEMG>>>(
        x3h, HID, SU_H,
        wu, HID, 0,
        nullptr, ubh, INTER, SU_I,
        nullptr, nullptr, 0, 0, gate16,
        nullptr, 0, nullptr, 0,
        HID, 1.f);

    // 13) out = ub @ Wd^T + x3
    mma_gemm<<<dim3(HID / 128, SU_LEN / 128, BATCH), blkG, SMEMG>>>(
        ubh, INTER, SU_I,
        wd, INTER, 0,
        out, nullptr, HID, SU_H,
        nullptr, x3_, HID, SU_H, nullh,
        nullptr, 0, nullptr, 0,
        INTER, 1.f);
}